// round 2
// baseline (speedup 1.0000x reference)
#include <cuda_runtime.h>
#include <math.h>

#define Bn 64
#define Tn 256
#define In 512
#define Hn 800
#define FH 3200   // 4*H

// Scratch: proj[dir][(b*T + t)*4H + g*H + h]
__device__ float g_proj[2][Bn * Tn * FH];
// Recurrent state: h double-buffered per direction, c single
__device__ float g_h[2][2][Bn * Hn];
__device__ float g_c[2][Bn * Hn];

__global__ void init_state() {
    int i = blockIdx.x * blockDim.x + threadIdx.x;
    if (i < Bn * Hn) {
        g_h[0][0][i] = 0.f; g_h[0][1][i] = 0.f;
        g_h[1][0][i] = 0.f; g_h[1][1][i] = 0.f;
        g_c[0][i] = 0.f;    g_c[1][i] = 0.f;
    }
}

// ---------------------------------------------------------------------------
// proj[dir][(b*T+t)*4H + g*H + n] = sum_i x[b,t,i]*mask[b,g,i]*W[i, g*H+n] + bias[g*H+n]
// GEMM: M = B*T = 16384, N = H = 800 (per gate), K = I = 512
// Tile: BM=64, BN=80 (800 = 10*80, no bounds checks), BK=16.
// 128 threads, each computes 8x5 outputs.
// grid = (10 n-tiles, 256 m-tiles, 8 = dir*4+g)
// ---------------------------------------------------------------------------
__global__ void proj_kernel(const float* __restrict__ x,
                            const float* __restrict__ mask_f,
                            const float* __restrict__ mask_b,
                            const float* __restrict__ W_f,
                            const float* __restrict__ W_b,
                            const float* __restrict__ bias_f,
                            const float* __restrict__ bias_b)
{
    constexpr int BM = 64, BN = 80, BK = 16;
    const int z   = blockIdx.z;
    const int dir = z >> 2;
    const int g   = z & 3;
    const int m0  = blockIdx.y * BM;
    const int n0  = blockIdx.x * BN;
    const float* __restrict__ W    = dir ? W_b    : W_f;
    const float* __restrict__ mask = dir ? mask_b : mask_f;
    const float* __restrict__ bias = dir ? bias_b : bias_f;

    __shared__ float As[BK][BM];
    __shared__ float Bs[BK][BN];

    const int tid = threadIdx.x;   // 128
    const int mt  = tid & 7;       // 8 row groups (TM=8, rows mt + r*8)
    const int nt  = tid >> 3;      // 16 col groups (TN=5, cols nt*5 + c)

    float acc[8][5];
#pragma unroll
    for (int r = 0; r < 8; r++)
#pragma unroll
        for (int c = 0; c < 5; c++) acc[r][c] = 0.f;

    for (int k0 = 0; k0 < In; k0 += BK) {
        // A tile: 64 rows x 16 k = 256 float4, 2 per thread, mask applied
#pragma unroll
        for (int r = 0; r < 2; r++) {
            int idx = tid + r * 128;
            int k4  = idx & 3;
            int m   = idx >> 2;          // 0..63
            int bt  = m0 + m;
            int b   = bt >> 8;           // bt / T
            const float4 xv = *(const float4*)(x    + (size_t)bt * In + k0 + k4 * 4);
            const float4 mv = *(const float4*)(mask + (size_t)b * (4 * In) + (size_t)g * In + k0 + k4 * 4);
            As[k4 * 4 + 0][m] = xv.x * mv.x;
            As[k4 * 4 + 1][m] = xv.y * mv.y;
            As[k4 * 4 + 2][m] = xv.z * mv.z;
            As[k4 * 4 + 3][m] = xv.w * mv.w;
        }
        // B tile: 16 x 80 = 1280 elems, 10 per thread
#pragma unroll
        for (int r = 0; r < 10; r++) {
            int idx = tid + r * 128;
            int n   = idx % 80;
            int k   = idx / 80;
            Bs[k][n] = W[(size_t)(k0 + k) * FH + (size_t)g * Hn + n0 + n];
        }
        __syncthreads();
#pragma unroll
        for (int k = 0; k < BK; k++) {
            float af[8], bf[5];
#pragma unroll
            for (int r = 0; r < 8; r++) af[r] = As[k][mt + r * 8];
#pragma unroll
            for (int c = 0; c < 5; c++) bf[c] = Bs[k][nt * 5 + c];
#pragma unroll
            for (int r = 0; r < 8; r++)
#pragma unroll
                for (int c = 0; c < 5; c++)
                    acc[r][c] = fmaf(af[r], bf[c], acc[r][c]);
        }
        __syncthreads();
    }

    float* __restrict__ outp = g_proj[dir];
#pragma unroll
    for (int r = 0; r < 8; r++) {
        int bt = m0 + mt + r * 8;
#pragma unroll
        for (int c = 0; c < 5; c++) {
            int n = n0 + nt * 5 + c;
            outp[(size_t)bt * FH + (size_t)g * Hn + n] = acc[r][c] + bias[g * Hn + n];
        }
    }
}

// ---------------------------------------------------------------------------
// One timestep, both directions (blockIdx.y = dir).
// z(64, 4H) = h_prev(64,800) @ U(800, 4H);  each block owns 8 h-columns x 4 gates
// so the gate nonlinearity + c/h update is thread-local.
// Tile: BM=64 (all batch), 8 h-cols * 4 gates = 32 N cols, BK=16, K=800.
// 128 threads: jt = tid&7 (h col), mt = tid>>3 (batch group, TM=4: b = mt + r*16).
// grid = (100, 2)
// ---------------------------------------------------------------------------
__global__ void step_kernel(const float* __restrict__ U_f,
                            const float* __restrict__ U_b,
                            float* __restrict__ out,
                            int t)
{
    constexpr int BK = 16;
    const int dir = blockIdx.y;
    const int n0  = blockIdx.x * 8;
    const float* __restrict__ U = dir ? U_b : U_f;
    const int cur = t & 1;
    const int nxt = 1 - cur;
    const float* __restrict__ hprev = g_h[dir][cur];
    const int t_eff = dir ? (Tn - 1 - t) : t;    // proj time index (backward reads reversed)

    __shared__ float As[BK][64];
    __shared__ float Bs[BK][32];

    const int tid = threadIdx.x;  // 128
    const int jt  = tid & 7;      // h column within tile
    const int mt  = tid >> 3;     // 0..15 batch group

    float acc[4][4];              // [batch r][gate]
#pragma unroll
    for (int r = 0; r < 4; r++)
#pragma unroll
        for (int g = 0; g < 4; g++) acc[r][g] = 0.f;

    for (int k0 = 0; k0 < Hn; k0 += BK) {
        // A: h_prev tile 64x16 = 256 float4, 2 per thread
#pragma unroll
        for (int r = 0; r < 2; r++) {
            int idx = tid + r * 128;
            int k4  = idx & 3;
            int m   = idx >> 2;
            const float4 hv = *(const float4*)(hprev + (size_t)m * Hn + k0 + k4 * 4);
            As[k4 * 4 + 0][m] = hv.x;
            As[k4 * 4 + 1][m] = hv.y;
            As[k4 * 4 + 2][m] = hv.z;
            As[k4 * 4 + 3][m] = hv.w;
        }
        // B: U tile 16 x (4 gates x 8 cols) = 512 elems, 4 per thread
#pragma unroll
        for (int r = 0; r < 4; r++) {
            int idx = tid + r * 128;
            int col = idx & 31;          // g*8 + j
            int k   = idx >> 5;
            int gg  = col >> 3;
            int j   = col & 7;
            Bs[k][col] = U[(size_t)(k0 + k) * FH + (size_t)gg * Hn + n0 + j];
        }
        __syncthreads();
#pragma unroll
        for (int k = 0; k < BK; k++) {
            float af[4], bf[4];
#pragma unroll
            for (int r = 0; r < 4; r++) af[r] = As[k][mt + r * 16];
#pragma unroll
            for (int g = 0; g < 4; g++) bf[g] = Bs[k][g * 8 + jt];
#pragma unroll
            for (int r = 0; r < 4; r++)
#pragma unroll
                for (int g = 0; g < 4; g++)
                    acc[r][g] = fmaf(af[r], bf[g], acc[r][g]);
        }
        __syncthreads();
    }

    // Gate math + state update + output write
    const int hh = n0 + jt;
    const float* __restrict__ proj = g_proj[dir];
#pragma unroll
    for (int r = 0; r < 4; r++) {
        int b = mt + r * 16;
        size_t pbase = ((size_t)b * Tn + t_eff) * FH;
        float zi = acc[r][0] + proj[pbase + 0 * Hn + hh];
        float zf = acc[r][1] + proj[pbase + 1 * Hn + hh];
        float zg = acc[r][2] + proj[pbase + 2 * Hn + hh];
        float zo = acc[r][3] + proj[pbase + 3 * Hn + hh];

        float ig = 1.f / (1.f + expf(-zi));
        float fg = 1.f / (1.f + expf(-zf));
        float gg = tanhf(zg);
        float og = 1.f / (1.f + expf(-zo));

        size_t ci = (size_t)b * Hn + hh;
        float cv = fg * g_c[dir][ci] + ig * gg;
        float hv = og * tanhf(cv);
        g_c[dir][ci] = cv;
        g_h[dir][nxt][ci] = hv;

        // Hcat[b, t, dir*H + hh]  (backward outputs are in processing order)
        out[((size_t)b * Tn + t) * (2 * Hn) + (size_t)dir * Hn + hh] = hv;
        if (t == Tn - 1) {
            size_t hcat0 = (size_t)Bn * Tn * (2 * Hn);
            size_t ccat0 = hcat0 + (size_t)Bn * (2 * Hn);
            out[hcat0 + (size_t)b * (2 * Hn) + (size_t)dir * Hn + hh] = hv;
            out[ccat0 + (size_t)b * (2 * Hn) + (size_t)dir * Hn + hh] = cv;
        }
    }
}

extern "C" void kernel_launch(void* const* d_in, const int* in_sizes, int n_in,
                              void* d_out, int out_size)
{
    const float* x      = (const float*)d_in[0];
    const float* mask_f = (const float*)d_in[1];
    const float* mask_b = (const float*)d_in[2];
    const float* W_f    = (const float*)d_in[3];
    const float* U_f    = (const float*)d_in[4];
    const float* b_f    = (const float*)d_in[5];
    const float* W_b    = (const float*)d_in[6];
    const float* U_b    = (const float*)d_in[7];
    const float* b_b    = (const float*)d_in[8];
    float* out = (float*)d_out;

    init_state<<<(Bn * Hn + 255) / 256, 256>>>();
    proj_kernel<<<dim3(10, 256, 8), 128>>>(x, mask_f, mask_b, W_f, W_b, b_f, b_b);
    for (int t = 0; t < Tn; t++)
        step_kernel<<<dim3(100, 2), 128>>>(U_f, U_b, out, t);
}

// round 3
// speedup vs baseline: 1.3338x; 1.3338x over previous
#include <cuda_runtime.h>
#include <math.h>

#define Bn 64
#define Tn 256
#define In 512
#define Hn 800
#define FH 3200   // 4*H

// Scratch: proj[dir][(b*T + t)*4H + g*H + h]
__device__ float g_proj[2][Bn * Tn * FH];
// Recurrent state: h double-buffered per direction, c single
__device__ float g_h[2][2][Bn * Hn];
__device__ float g_c[2][Bn * Hn];

__global__ void init_state() {
    int i = blockIdx.x * blockDim.x + threadIdx.x;
    if (i < Bn * Hn) {
        g_h[0][0][i] = 0.f; g_h[0][1][i] = 0.f;
        g_h[1][0][i] = 0.f; g_h[1][1][i] = 0.f;
        g_c[0][i] = 0.f;    g_c[1][i] = 0.f;
    }
}

// ---------------------------------------------------------------------------
// Input projection GEMM (unchanged): M=16384, N=800/gate, K=512
// ---------------------------------------------------------------------------
__global__ void proj_kernel(const float* __restrict__ x,
                            const float* __restrict__ mask_f,
                            const float* __restrict__ mask_b,
                            const float* __restrict__ W_f,
                            const float* __restrict__ W_b,
                            const float* __restrict__ bias_f,
                            const float* __restrict__ bias_b)
{
    constexpr int BM = 64, BN = 80, BK = 16;
    const int z   = blockIdx.z;
    const int dir = z >> 2;
    const int g   = z & 3;
    const int m0  = blockIdx.y * BM;
    const int n0  = blockIdx.x * BN;
    const float* __restrict__ W    = dir ? W_b    : W_f;
    const float* __restrict__ mask = dir ? mask_b : mask_f;
    const float* __restrict__ bias = dir ? bias_b : bias_f;

    __shared__ float As[BK][BM];
    __shared__ float Bs[BK][BN];

    const int tid = threadIdx.x;   // 128
    const int mt  = tid & 7;
    const int nt  = tid >> 3;

    float acc[8][5];
#pragma unroll
    for (int r = 0; r < 8; r++)
#pragma unroll
        for (int c = 0; c < 5; c++) acc[r][c] = 0.f;

    for (int k0 = 0; k0 < In; k0 += BK) {
#pragma unroll
        for (int r = 0; r < 2; r++) {
            int idx = tid + r * 128;
            int k4  = idx & 3;
            int m   = idx >> 2;
            int bt  = m0 + m;
            int b   = bt >> 8;
            const float4 xv = *(const float4*)(x    + (size_t)bt * In + k0 + k4 * 4);
            const float4 mv = *(const float4*)(mask + (size_t)b * (4 * In) + (size_t)g * In + k0 + k4 * 4);
            As[k4 * 4 + 0][m] = xv.x * mv.x;
            As[k4 * 4 + 1][m] = xv.y * mv.y;
            As[k4 * 4 + 2][m] = xv.z * mv.z;
            As[k4 * 4 + 3][m] = xv.w * mv.w;
        }
#pragma unroll
        for (int r = 0; r < 10; r++) {
            int idx = tid + r * 128;
            int n   = idx % 80;
            int k   = idx / 80;
            Bs[k][n] = W[(size_t)(k0 + k) * FH + (size_t)g * Hn + n0 + n];
        }
        __syncthreads();
#pragma unroll
        for (int k = 0; k < BK; k++) {
            float af[8], bf[5];
#pragma unroll
            for (int r = 0; r < 8; r++) af[r] = As[k][mt + r * 8];
#pragma unroll
            for (int c = 0; c < 5; c++) bf[c] = Bs[k][nt * 5 + c];
#pragma unroll
            for (int r = 0; r < 8; r++)
#pragma unroll
                for (int c = 0; c < 5; c++)
                    acc[r][c] = fmaf(af[r], bf[c], acc[r][c]);
        }
        __syncthreads();
    }

    float* __restrict__ outp = g_proj[dir];
#pragma unroll
    for (int r = 0; r < 8; r++) {
        int bt = m0 + mt + r * 8;
#pragma unroll
        for (int c = 0; c < 5; c++) {
            int n = n0 + nt * 5 + c;
            outp[(size_t)bt * FH + (size_t)g * Hn + n] = acc[r][c] + bias[g * Hn + n];
        }
    }
}

// ---------------------------------------------------------------------------
// Fast gate nonlinearities (MUFU-based, ~1e-6 rel err)
// ---------------------------------------------------------------------------
__device__ __forceinline__ float fast_sigmoid(float x) {
    return __fdividef(1.f, 1.f + __expf(-x));
}
__device__ __forceinline__ float fast_tanh(float x) {
    // 1 - 2/(e^{2x}+1): exact limits at +-inf via __expf saturation
    float e = __expf(2.f * x);
    return 1.f - __fdividef(2.f, e + 1.f);
}

// ---------------------------------------------------------------------------
// One timestep, both directions.
// z(16b x 64c tile) = h_prev(16,800) @ U(800, cols) ; cols = 4 gates x 16 h.
// Grid: (50 h-tiles, 4 batch-quarters, 2 dirs) = 400 CTAs, 128 threads.
// A tile stored batch-major (k contiguous) -> warp-uniform LDS.128 for af.
// B tile [k][g*16+h] -> contiguous LDS.64 for bf.
// Double-buffered SMEM, 1 syncthreads per 32-k block.
// ---------------------------------------------------------------------------
__global__ void __launch_bounds__(128)
step_kernel(const float* __restrict__ U_f,
            const float* __restrict__ U_b,
            float* __restrict__ out,
            int t)
{
    const int dir = blockIdx.z;
    const int n0h = blockIdx.x * 16;    // h tile base
    const int b0  = blockIdx.y * 16;    // batch tile base
    const float* __restrict__ U = dir ? U_b : U_f;
    const int cur = t & 1;
    const int nxt = cur ^ 1;
    const float* __restrict__ hprev = g_h[dir][cur];
    const int t_eff = dir ? (Tn - 1 - t) : t;

    __shared__ float As[2][16][32];     // [buf][b][k]
    __shared__ float Bs[2][32][64];     // [buf][k][g*16+h]
    __shared__ float zs[16][64];        // [b][g*16+h]

    const int tid = threadIdx.x;        // 128
    const int jt  = tid & 31;           // col pair index (2 cols each)
    const int mb  = tid >> 5;           // batch group (4 batches each)

    // fill decode
    const int a_k4 = tid & 7;           // which float4 along k (8*4=32)
    const int a_b  = tid >> 3;          // batch row 0..15

    float acc[4][2];
#pragma unroll
    for (int r = 0; r < 4; r++) { acc[r][0] = 0.f; acc[r][1] = 0.f; }

    // preload block 0
    {
        const float4 hv = *(const float4*)(hprev + (size_t)(b0 + a_b) * Hn + a_k4 * 4);
        *(float4*)&As[0][a_b][a_k4 * 4] = hv;
#pragma unroll
        for (int i = 0; i < 4; i++) {
            int q  = tid + i * 128;
            int bk = q >> 4;
            int rr = q & 15;
            const float4 uv = *(const float4*)(U + (size_t)bk * FH + (size_t)(rr >> 2) * Hn + n0h + ((rr & 3) << 2));
            *(float4*)&Bs[0][bk][rr * 4] = uv;
        }
    }
    __syncthreads();

    for (int blk = 0; blk < 25; blk++) {
        const int buf = blk & 1;
        float4 pa;
        float4 pb[4];
        if (blk < 24) {
            const int k0 = (blk + 1) * 32;
            pa = *(const float4*)(hprev + (size_t)(b0 + a_b) * Hn + k0 + a_k4 * 4);
#pragma unroll
            for (int i = 0; i < 4; i++) {
                int q  = tid + i * 128;
                int bk = q >> 4;
                int rr = q & 15;
                pb[i] = *(const float4*)(U + (size_t)(k0 + bk) * FH + (size_t)(rr >> 2) * Hn + n0h + ((rr & 3) << 2));
            }
        }
        // compute over current buffer
#pragma unroll
        for (int kk = 0; kk < 32; kk += 4) {
            float ar[4][4];
#pragma unroll
            for (int r = 0; r < 4; r++)
                *(float4*)&ar[r][0] = *(const float4*)&As[buf][mb * 4 + r][kk];
#pragma unroll
            for (int j = 0; j < 4; j++) {
                float2 bv = *(const float2*)&Bs[buf][kk + j][jt * 2];
#pragma unroll
                for (int r = 0; r < 4; r++) {
                    acc[r][0] = fmaf(ar[r][j], bv.x, acc[r][0]);
                    acc[r][1] = fmaf(ar[r][j], bv.y, acc[r][1]);
                }
            }
        }
        if (blk < 24) {
            *(float4*)&As[buf ^ 1][a_b][a_k4 * 4] = pa;
#pragma unroll
            for (int i = 0; i < 4; i++) {
                int q  = tid + i * 128;
                int bk = q >> 4;
                int rr = q & 15;
                *(float4*)&Bs[buf ^ 1][bk][rr * 4] = pb[i];
            }
            __syncthreads();
        }
    }

    // exchange z through shared memory (float2 stores, conflict-free)
#pragma unroll
    for (int r = 0; r < 4; r++)
        *(float2*)&zs[mb * 4 + r][jt * 2] = make_float2(acc[r][0], acc[r][1]);
    __syncthreads();

    // gate phase: 256 (b,h) pairs / 128 threads = 2 each
    const float* __restrict__ proj = g_proj[dir];
#pragma unroll
    for (int i = 0; i < 2; i++) {
        int p = tid + i * 128;
        int b = p >> 4;
        int h = p & 15;
        int bg = b0 + b;
        int hg = n0h + h;
        size_t pbase = ((size_t)bg * Tn + t_eff) * FH;

        float zi = zs[b][ 0 + h] + proj[pbase + 0 * Hn + hg];
        float zf = zs[b][16 + h] + proj[pbase + 1 * Hn + hg];
        float zg = zs[b][32 + h] + proj[pbase + 2 * Hn + hg];
        float zo = zs[b][48 + h] + proj[pbase + 3 * Hn + hg];

        float ig = fast_sigmoid(zi);
        float fg = fast_sigmoid(zf);
        float gg = fast_tanh(zg);
        float og = fast_sigmoid(zo);

        size_t ci = (size_t)bg * Hn + hg;
        float cv = fg * g_c[dir][ci] + ig * gg;
        float hv = og * fast_tanh(cv);
        g_c[dir][ci] = cv;
        g_h[dir][nxt][ci] = hv;

        out[((size_t)bg * Tn + t) * (2 * Hn) + (size_t)dir * Hn + hg] = hv;
        if (t == Tn - 1) {
            size_t hcat0 = (size_t)Bn * Tn * (2 * Hn);
            size_t ccat0 = hcat0 + (size_t)Bn * (2 * Hn);
            out[hcat0 + (size_t)bg * (2 * Hn) + (size_t)dir * Hn + hg] = hv;
            out[ccat0 + (size_t)bg * (2 * Hn) + (size_t)dir * Hn + hg] = cv;
        }
    }
}

extern "C" void kernel_launch(void* const* d_in, const int* in_sizes, int n_in,
                              void* d_out, int out_size)
{
    const float* x      = (const float*)d_in[0];
    const float* mask_f = (const float*)d_in[1];
    const float* mask_b = (const float*)d_in[2];
    const float* W_f    = (const float*)d_in[3];
    const float* U_f    = (const float*)d_in[4];
    const float* b_f    = (const float*)d_in[5];
    const float* W_b    = (const float*)d_in[6];
    const float* U_b    = (const float*)d_in[7];
    const float* b_b    = (const float*)d_in[8];
    float* out = (float*)d_out;

    init_state<<<(Bn * Hn + 255) / 256, 256>>>();
    proj_kernel<<<dim3(10, 256, 8), 128>>>(x, mask_f, mask_b, W_f, W_b, b_f, b_b);
    for (int t = 0; t < Tn; t++)
        step_kernel<<<dim3(50, 4, 2), 128>>>(U_f, U_b, out, t);
}

// round 4
// speedup vs baseline: 1.7331x; 1.2994x over previous
#include <cuda_runtime.h>
#include <math.h>

#define Bn 64
#define Tn 256
#define In 512
#define Hn 800
#define FH 3200   // 4*H

#define NCTA_DIR 67          // CTAs per direction (66*12 + 8 = 800 h-cols)
#define NH 12                // h columns per CTA (padded; last CTA has 8)
#define WCOLS 48             // 4 gates * NH
#define ASTR 36              // padded k-stride of As (bank-friendly, 16B aligned)

// Scratch: proj[dir][(b*T + t)*4H + g*H + h]
__device__ float g_proj[2][Bn * Tn * FH];
// Recurrent state: h double-buffered per direction, c single
__device__ float g_h[2][2][Bn * Hn];
__device__ float g_c[2][Bn * Hn];
// Grid barrier state (per direction)
__device__ volatile unsigned g_bar_count[2];
__device__ volatile unsigned g_bar_sense[2];

__global__ void init_state() {
    int i = blockIdx.x * blockDim.x + threadIdx.x;
    if (i < Bn * Hn) {
        g_h[0][0][i] = 0.f; g_h[0][1][i] = 0.f;
        g_h[1][0][i] = 0.f; g_h[1][1][i] = 0.f;
        g_c[0][i] = 0.f;    g_c[1][i] = 0.f;
    }
    if (i < 2) { g_bar_count[i] = 0u; g_bar_sense[i] = 0u; }
}

// ---------------------------------------------------------------------------
// Input projection GEMM (unchanged): M=16384, N=800/gate, K=512
// ---------------------------------------------------------------------------
__global__ void proj_kernel(const float* __restrict__ x,
                            const float* __restrict__ mask_f,
                            const float* __restrict__ mask_b,
                            const float* __restrict__ W_f,
                            const float* __restrict__ W_b,
                            const float* __restrict__ bias_f,
                            const float* __restrict__ bias_b)
{
    constexpr int BK = 16;
    const int z   = blockIdx.z;
    const int dir = z >> 2;
    const int g   = z & 3;
    const int m0  = blockIdx.y * 64;
    const int n0  = blockIdx.x * 80;
    const float* __restrict__ W    = dir ? W_b    : W_f;
    const float* __restrict__ mask = dir ? mask_b : mask_f;
    const float* __restrict__ bias = dir ? bias_b : bias_f;

    __shared__ float As[BK][64];
    __shared__ float Bs[BK][80];

    const int tid = threadIdx.x;   // 128
    const int mt  = tid & 7;
    const int nt  = tid >> 3;

    float acc[8][5];
#pragma unroll
    for (int r = 0; r < 8; r++)
#pragma unroll
        for (int c = 0; c < 5; c++) acc[r][c] = 0.f;

    for (int k0 = 0; k0 < In; k0 += BK) {
#pragma unroll
        for (int r = 0; r < 2; r++) {
            int idx = tid + r * 128;
            int k4  = idx & 3;
            int m   = idx >> 2;
            int bt  = m0 + m;
            int b   = bt >> 8;
            const float4 xv = *(const float4*)(x    + (size_t)bt * In + k0 + k4 * 4);
            const float4 mv = *(const float4*)(mask + (size_t)b * (4 * In) + (size_t)g * In + k0 + k4 * 4);
            As[k4 * 4 + 0][m] = xv.x * mv.x;
            As[k4 * 4 + 1][m] = xv.y * mv.y;
            As[k4 * 4 + 2][m] = xv.z * mv.z;
            As[k4 * 4 + 3][m] = xv.w * mv.w;
        }
#pragma unroll
        for (int r = 0; r < 10; r++) {
            int idx = tid + r * 128;
            int n   = idx % 80;
            int k   = idx / 80;
            Bs[k][n] = W[(size_t)(k0 + k) * FH + (size_t)g * Hn + n0 + n];
        }
        __syncthreads();
#pragma unroll
        for (int k = 0; k < BK; k++) {
            float af[8], bf[5];
#pragma unroll
            for (int r = 0; r < 8; r++) af[r] = As[k][mt + r * 8];
#pragma unroll
            for (int c = 0; c < 5; c++) bf[c] = Bs[k][nt * 5 + c];
#pragma unroll
            for (int r = 0; r < 8; r++)
#pragma unroll
                for (int c = 0; c < 5; c++)
                    acc[r][c] = fmaf(af[r], bf[c], acc[r][c]);
        }
        __syncthreads();
    }

    float* __restrict__ outp = g_proj[dir];
#pragma unroll
    for (int r = 0; r < 8; r++) {
        int bt = m0 + mt + r * 8;
#pragma unroll
        for (int c = 0; c < 5; c++) {
            int n = n0 + nt * 5 + c;
            outp[(size_t)bt * FH + (size_t)g * Hn + n] = acc[r][c] + bias[g * Hn + n];
        }
    }
}

// ---------------------------------------------------------------------------
// Fast gate nonlinearities (MUFU-based, ~1e-6 rel err)
// ---------------------------------------------------------------------------
__device__ __forceinline__ float fast_sigmoid(float x) {
    return __fdividef(1.f, 1.f + __expf(-x));
}
__device__ __forceinline__ float fast_tanh(float x) {
    float e = __expf(2.f * x);
    return 1.f - __fdividef(2.f, e + 1.f);
}

// ---------------------------------------------------------------------------
// Persistent bidirectional LSTM recurrence.
// Grid = 134 CTAs (67 per dir), 256 threads, 1 CTA/SM (all co-resident).
// Each CTA owns 12 h-columns (48 U columns incl. all 4 gates); its U slice
// (800 x 48 fp32 = 153.6 KB) lives in SMEM for the whole kernel.
// Per step: z(64 x 48) = h_prev(64,800) @ Uslice, gate update, h/c write,
// then a per-direction sense-reversing grid barrier.
// ---------------------------------------------------------------------------
__global__ void __launch_bounds__(256, 1)
lstm_persistent(const float* __restrict__ U_f,
                const float* __restrict__ U_b,
                float* __restrict__ out)
{
    extern __shared__ float smem[];
    float* Bs = smem;                          // [800][48]      153600 B
    float* As = Bs + Hn * WCOLS;               // [2][64][36]     18432 B
    float* zs = As + 2 * 64 * ASTR;            // [64][48]        12288 B

    const int bid = blockIdx.x;
    const int dir = bid / NCTA_DIR;
    const int j   = bid - dir * NCTA_DIR;
    const int h0  = j * NH;
    const int tid = threadIdx.x;               // 256
    const int mt  = tid >> 4;                  // 16 groups x 4 batches
    const int jt  = tid & 15;                  // 16 groups x 3 cols (w = jt + 16*cc)
    const float* __restrict__ U = dir ? U_b : U_f;

    // One-time: load this CTA's U slice into SMEM. Column w -> gate w/12, h = h0 + w%12.
    for (int idx = tid; idx < Hn * WCOLS; idx += 256) {
        int k = idx / WCOLS;
        int w = idx - k * WCOLS;
        int g = w / NH;
        int c = w - g * NH;
        int hh = h0 + c;
        Bs[idx] = (hh < Hn) ? U[(size_t)k * FH + (size_t)g * Hn + hh] : 0.f;
    }
    __syncthreads();

    unsigned sense = 0;
    const float* __restrict__ proj = g_proj[dir];

    for (int t = 0; t < Tn; t++) {
        const int cur = t & 1;
        const float* __restrict__ hprev = g_h[dir][cur];
        float* __restrict__ hnext = g_h[dir][cur ^ 1];

        // Preload h k-block 0 into As[0]
        {
#pragma unroll
            for (int r = 0; r < 2; r++) {
                int idx = tid + r * 256;           // 0..511
                int b   = idx >> 3;
                int kk  = (idx & 7) * 4;
                float4 hv = *(const float4*)(hprev + (size_t)b * Hn + kk);
                *(float4*)&As[b * ASTR + kk] = hv;
            }
        }
        __syncthreads();

        float acc[4][3];
#pragma unroll
        for (int r = 0; r < 4; r++) { acc[r][0] = 0.f; acc[r][1] = 0.f; acc[r][2] = 0.f; }

        for (int blk = 0; blk < 25; blk++) {
            const int buf = blk & 1;
            float4 pf0, pf1;
            if (blk < 24) {
                const int kn = (blk + 1) * 32;
                int i0 = tid, i1 = tid + 256;
                pf0 = *(const float4*)(hprev + (size_t)(i0 >> 3) * Hn + kn + (i0 & 7) * 4);
                pf1 = *(const float4*)(hprev + (size_t)(i1 >> 3) * Hn + kn + (i1 & 7) * 4);
            }
            const float* Ab = As + buf * (64 * ASTR);
            const int kbase = blk * 32;
#pragma unroll
            for (int kk = 0; kk < 32; kk += 4) {
                float4 ar[4];
#pragma unroll
                for (int r = 0; r < 4; r++)
                    ar[r] = *(const float4*)&Ab[(mt * 4 + r) * ASTR + kk];
#pragma unroll
                for (int q = 0; q < 4; q++) {
                    const float* Bk = Bs + (size_t)(kbase + kk + q) * WCOLS;
                    float b0 = Bk[jt];
                    float b1 = Bk[jt + 16];
                    float b2 = Bk[jt + 32];
                    float a0 = (q == 0) ? ar[0].x : (q == 1) ? ar[0].y : (q == 2) ? ar[0].z : ar[0].w;
                    float a1 = (q == 0) ? ar[1].x : (q == 1) ? ar[1].y : (q == 2) ? ar[1].z : ar[1].w;
                    float a2 = (q == 0) ? ar[2].x : (q == 1) ? ar[2].y : (q == 2) ? ar[2].z : ar[2].w;
                    float a3 = (q == 0) ? ar[3].x : (q == 1) ? ar[3].y : (q == 2) ? ar[3].z : ar[3].w;
                    acc[0][0] = fmaf(a0, b0, acc[0][0]); acc[0][1] = fmaf(a0, b1, acc[0][1]); acc[0][2] = fmaf(a0, b2, acc[0][2]);
                    acc[1][0] = fmaf(a1, b0, acc[1][0]); acc[1][1] = fmaf(a1, b1, acc[1][1]); acc[1][2] = fmaf(a1, b2, acc[1][2]);
                    acc[2][0] = fmaf(a2, b0, acc[2][0]); acc[2][1] = fmaf(a2, b1, acc[2][1]); acc[2][2] = fmaf(a2, b2, acc[2][2]);
                    acc[3][0] = fmaf(a3, b0, acc[3][0]); acc[3][1] = fmaf(a3, b1, acc[3][1]); acc[3][2] = fmaf(a3, b2, acc[3][2]);
                }
            }
            if (blk < 24) {
                float* An = As + (buf ^ 1) * (64 * ASTR);
                int i0 = tid, i1 = tid + 256;
                *(float4*)&An[(i0 >> 3) * ASTR + (i0 & 7) * 4] = pf0;
                *(float4*)&An[(i1 >> 3) * ASTR + (i1 & 7) * 4] = pf1;
                __syncthreads();
            }
        }

        // Exchange z through shared memory
        __syncthreads();   // all reads of As done; zs free to write
#pragma unroll
        for (int r = 0; r < 4; r++) {
            int b = mt * 4 + r;
            zs[b * WCOLS + jt]      = acc[r][0];
            zs[b * WCOLS + jt + 16] = acc[r][1];
            zs[b * WCOLS + jt + 32] = acc[r][2];
        }
        __syncthreads();

        // Gate update: 64 batches x NH h-cols (guarded), 3 per thread
        const int t_eff = dir ? (Tn - 1 - t) : t;
#pragma unroll
        for (int it = 0; it < 3; it++) {
            int idx = it * 256 + tid;           // 0..767
            int b = idx / NH;
            int c = idx - b * NH;
            int hh = h0 + c;
            if (hh < Hn) {
                size_t pbase = ((size_t)b * Tn + t_eff) * FH;
                float zi = zs[b * WCOLS + 0 * NH + c] + proj[pbase + 0 * Hn + hh];
                float zf = zs[b * WCOLS + 1 * NH + c] + proj[pbase + 1 * Hn + hh];
                float zg = zs[b * WCOLS + 2 * NH + c] + proj[pbase + 2 * Hn + hh];
                float zo = zs[b * WCOLS + 3 * NH + c] + proj[pbase + 3 * Hn + hh];

                float ig = fast_sigmoid(zi);
                float fg = fast_sigmoid(zf);
                float gg = fast_tanh(zg);
                float og = fast_sigmoid(zo);

                size_t ci = (size_t)b * Hn + hh;
                float cv = fg * g_c[dir][ci] + ig * gg;
                float hv = og * fast_tanh(cv);
                g_c[dir][ci] = cv;
                hnext[ci] = hv;

                out[((size_t)b * Tn + t) * (2 * Hn) + (size_t)dir * Hn + hh] = hv;
                if (t == Tn - 1) {
                    size_t hcat0 = (size_t)Bn * Tn * (2 * Hn);
                    size_t ccat0 = hcat0 + (size_t)Bn * (2 * Hn);
                    out[hcat0 + (size_t)b * (2 * Hn) + (size_t)dir * Hn + hh] = hv;
                    out[ccat0 + (size_t)b * (2 * Hn) + (size_t)dir * Hn + hh] = cv;
                }
            }
        }

        // Per-direction grid barrier (sense-reversing).
        // __threadfence: release (h/c/out globally visible) + L1 invalidate so
        // next step's h loads observe other CTAs' writes.
        __threadfence();
        __syncthreads();
        if (tid == 0) {
            unsigned ns = sense ^ 1u;
            unsigned arrived = atomicAdd((unsigned*)&g_bar_count[dir], 1u);
            if (arrived == NCTA_DIR - 1) {
                g_bar_count[dir] = 0u;
                __threadfence();
                g_bar_sense[dir] = ns;
            } else {
                while (g_bar_sense[dir] != ns) __nanosleep(64);
            }
            __threadfence();
        }
        __syncthreads();
        sense ^= 1u;
    }
}

extern "C" void kernel_launch(void* const* d_in, const int* in_sizes, int n_in,
                              void* d_out, int out_size)
{
    const float* x      = (const float*)d_in[0];
    const float* mask_f = (const float*)d_in[1];
    const float* mask_b = (const float*)d_in[2];
    const float* W_f    = (const float*)d_in[3];
    const float* U_f    = (const float*)d_in[4];
    const float* b_f    = (const float*)d_in[5];
    const float* W_b    = (const float*)d_in[6];
    const float* U_b    = (const float*)d_in[7];
    const float* b_b    = (const float*)d_in[8];
    float* out = (float*)d_out;

    const int smem_bytes = (Hn * WCOLS + 2 * 64 * ASTR + 64 * WCOLS) * sizeof(float); // 184320
    static int configured = 0;
    if (!configured) {
        cudaFuncSetAttribute(lstm_persistent,
                             cudaFuncAttributeMaxDynamicSharedMemorySize, smem_bytes);
        configured = 1;
    }

    init_state<<<(Bn * Hn + 255) / 256, 256>>>();
    proj_kernel<<<dim3(10, 256, 8), 128>>>(x, mask_f, mask_b, W_f, W_b, b_f, b_b);
    lstm_persistent<<<2 * NCTA_DIR, 256, smem_bytes>>>(U_f, U_b, out);
}

// round 6
// speedup vs baseline: 2.0985x; 1.2109x over previous
#include <cuda_runtime.h>
#include <cuda_bf16.h>
#include <math.h>
#include <stdint.h>

#define Bn 64
#define Tn 256
#define In 512
#define Hn 800
#define FH 3200   // 4*H

#define NCTA_DIR 67
#define NH 12
#define WCOLS 48
#define ASTR 36

// ---------------- device globals (no runtime allocation allowed) ------------
__device__ float g_proj[2][Bn * Tn * FH];                 // 419 MB
__device__ __nv_bfloat16 g_ahi[8][Bn * Tn * In];          // masked x hi, z=dir*4+g
__device__ __nv_bfloat16 g_alo[8][Bn * Tn * In];          // masked x lo
__device__ __nv_bfloat16 g_wcat[8][Hn * 1024];            // [n][k]: k<512 = W_hi, k>=512 = W_lo
__device__ float g_h[2][2][Bn * Hn];
__device__ float g_c[2][Bn * Hn];
__device__ volatile unsigned g_bar_count[2];
__device__ volatile unsigned g_bar_sense[2];

__global__ void init_state() {
    int i = blockIdx.x * blockDim.x + threadIdx.x;
    if (i < Bn * Hn) {
        g_h[0][0][i] = 0.f; g_h[0][1][i] = 0.f;
        g_h[1][0][i] = 0.f; g_h[1][1][i] = 0.f;
        g_c[0][i] = 0.f;    g_c[1][i] = 0.f;
    }
    if (i < 2) { g_bar_count[i] = 0u; g_bar_sense[i] = 0u; }
}

// ---------------- helpers ----------------------------------------------------
__device__ __forceinline__ uint32_t smem_u32(const void* p) {
    uint32_t a;
    asm("{ .reg .u64 t; cvta.to.shared.u64 t, %1; cvt.u32.u64 %0, t; }" : "=r"(a) : "l"(p));
    return a;
}
__device__ __forceinline__ void ldmatrix_x4(uint32_t& a0, uint32_t& a1, uint32_t& a2, uint32_t& a3,
                                            uint32_t addr) {
    asm volatile("ldmatrix.sync.aligned.m8n8.x4.shared.b16 {%0,%1,%2,%3}, [%4];"
                 : "=r"(a0), "=r"(a1), "=r"(a2), "=r"(a3) : "r"(addr));
}
__device__ __forceinline__ void ldmatrix_x2(uint32_t& b0, uint32_t& b1, uint32_t addr) {
    asm volatile("ldmatrix.sync.aligned.m8n8.x2.shared.b16 {%0,%1}, [%2];"
                 : "=r"(b0), "=r"(b1) : "r"(addr));
}
__device__ __forceinline__ void mma_bf16(float& c0, float& c1, float& c2, float& c3,
                                         uint32_t a0, uint32_t a1, uint32_t a2, uint32_t a3,
                                         uint32_t b0, uint32_t b1) {
    asm volatile("mma.sync.aligned.m16n8k16.row.col.f32.bf16.bf16.f32 "
                 "{%0,%1,%2,%3}, {%4,%5,%6,%7}, {%8,%9}, {%0,%1,%2,%3};"
                 : "+f"(c0), "+f"(c1), "+f"(c2), "+f"(c3)
                 : "r"(a0), "r"(a1), "r"(a2), "r"(a3), "r"(b0), "r"(b1));
}

// ---------------- conversion kernels ----------------------------------------
__global__ void convert_x(const float* __restrict__ x,
                          const float* __restrict__ mask_f,
                          const float* __restrict__ mask_b)
{
    int idx = blockIdx.x * blockDim.x + threadIdx.x;      // (bt, i/4)
    if (idx >= Bn * Tn * (In / 4)) return;
    int bt = idx >> 7;
    int i4 = idx & 127;
    int b  = bt >> 8;
    float4 xv = *(const float4*)(x + (size_t)bt * In + i4 * 4);
#pragma unroll
    for (int dir = 0; dir < 2; dir++) {
        const float* mask = dir ? mask_b : mask_f;
#pragma unroll
        for (int g = 0; g < 4; g++) {
            float4 mv = *(const float4*)(mask + (size_t)b * (4 * In) + (size_t)g * In + i4 * 4);
            float v[4] = {xv.x * mv.x, xv.y * mv.y, xv.z * mv.z, xv.w * mv.w};
            __nv_bfloat16 h[4], l[4];
#pragma unroll
            for (int q = 0; q < 4; q++) {
                h[q] = __float2bfloat16(v[q]);
                l[q] = __float2bfloat16(v[q] - __bfloat162float(h[q]));
            }
            int z = dir * 4 + g;
            size_t o = (size_t)bt * In + i4 * 4;
            __nv_bfloat162 h0; h0.x = h[0]; h0.y = h[1];
            __nv_bfloat162 h1; h1.x = h[2]; h1.y = h[3];
            __nv_bfloat162 l0; l0.x = l[0]; l0.y = l[1];
            __nv_bfloat162 l1; l1.x = l[2]; l1.y = l[3];
            *(__nv_bfloat162*)&g_ahi[z][o]     = h0;
            *(__nv_bfloat162*)&g_ahi[z][o + 2] = h1;
            *(__nv_bfloat162*)&g_alo[z][o]     = l0;
            *(__nv_bfloat162*)&g_alo[z][o + 2] = l1;
        }
    }
}

__global__ void convert_w(const float* __restrict__ W_f,
                          const float* __restrict__ W_b)
{
    int idx = blockIdx.x * blockDim.x + threadIdx.x;      // (z, ksrc, n)
    if (idx >= 8 * In * Hn) return;
    int n    = idx % Hn;
    int rest = idx / Hn;
    int ks   = rest & 511;
    int z    = rest >> 9;
    int dir  = z >> 2, g = z & 3;
    const float* W = dir ? W_b : W_f;
    float v = W[(size_t)ks * FH + (size_t)g * Hn + n];
    __nv_bfloat16 h = __float2bfloat16(v);
    __nv_bfloat16 l = __float2bfloat16(v - __bfloat162float(h));
    g_wcat[z][(size_t)n * 1024 + ks]       = h;
    g_wcat[z][(size_t)n * 1024 + 512 + ks] = l;
}

// ---------------- proj GEMM via mma.sync (HMMA bf16) --------------------------
// C[16384, 800] per z: split-bf16, K_eff = 1536 = [hi,hi,lo]x[Whi,Wlo,Whi]
// CTA tile M=128 x N=80, BK=32, double-buffered SMEM, 8 warps (4M x 2N),
// warp tile 32x40 = 2 m16-tiles x 5 n8-tiles.
#define PBK 32
#define PCHUNK 48
#define A_STRIDE 80          // bytes per SMEM row (conflict-free for ldmatrix)
#define A_BYTES (128 * A_STRIDE)
#define B_BYTES (80  * A_STRIDE)

__global__ void __launch_bounds__(256)
proj_mma(const float* __restrict__ bias_f, const float* __restrict__ bias_b)
{
    __shared__ char sA[2][A_BYTES];
    __shared__ char sB[2][B_BYTES];

    const int z   = blockIdx.z;
    const int dir = z >> 2, g = z & 3;
    const int m0  = blockIdx.y * 128;
    const int n0  = blockIdx.x * 80;
    const __nv_bfloat16* __restrict__ ahi = g_ahi[z];
    const __nv_bfloat16* __restrict__ alo = g_alo[z];
    const __nv_bfloat16* __restrict__ wc  = g_wcat[z];
    const float* __restrict__ bias = dir ? bias_b : bias_f;

    const int tid  = threadIdx.x;
    const int wid  = tid >> 5;
    const int lane = tid & 31;
    const int wm   = wid & 3;        // M warp (4 x 32)
    const int wn   = wid >> 2;       // N warp (2 x 40)

    const uint32_t sAu = smem_u32(&sA[0][0]);
    const uint32_t sBu = smem_u32(&sB[0][0]);

    // ldmatrix base addresses (within buffer 0); add buf*bytes + kk*2 later.
    uint32_t aAddr[2], bAddr[5];
#pragma unroll
    for (int mt = 0; mt < 2; mt++) {
        int row = wm * 32 + mt * 16 + (lane & 15);
        aAddr[mt] = sAu + row * A_STRIDE + ((lane >> 4) << 3) * 2;
    }
#pragma unroll
    for (int nt = 0; nt < 5; nt++) {
        int row = wn * 40 + nt * 8 + (lane & 7);
        bAddr[nt] = sBu + row * A_STRIDE + (((lane >> 3) & 1) << 3) * 2;
    }

    // global->smem decode (uint4 granularity)
    // A: 512 uint4: r = idx>>2 (0..127), c = idx&3 ; B: 320 uint4: r = idx>>2 (0..79)
    float acc[2][5][4];
#pragma unroll
    for (int mt = 0; mt < 2; mt++)
#pragma unroll
        for (int nt = 0; nt < 5; nt++)
#pragma unroll
            for (int q = 0; q < 4; q++) acc[mt][nt][q] = 0.f;

    // chunk 0 load
    {
#pragma unroll
        for (int it = 0; it < 2; it++) {
            int idx = tid + it * 256;
            int r = idx >> 2, c = idx & 3;
            uint4 v = *(const uint4*)(ahi + (size_t)(m0 + r) * In + c * 8);
            *(uint4*)(&sA[0][r * A_STRIDE + c * 16]) = v;
        }
#pragma unroll
        for (int it = 0; it < 2; it++) {
            int idx = tid + it * 256;
            if (idx < 320) {
                int r = idx >> 2, c = idx & 3;
                uint4 v = *(const uint4*)(wc + (size_t)(n0 + r) * 1024 + c * 8);
                *(uint4*)(&sB[0][r * A_STRIDE + c * 16]) = v;
            }
        }
    }
    __syncthreads();

    for (int c = 0; c < PCHUNK; c++) {
        const int buf = c & 1;
        uint4 pa[2], pb[2];
        if (c + 1 < PCHUNK) {
            const int cn = c + 1;
            int ka, kb;
            const __nv_bfloat16* asrc;
            if (cn < 16)      { asrc = ahi; ka = cn * PBK;        kb = cn * PBK; }
            else if (cn < 32) { asrc = ahi; ka = (cn - 16) * PBK; kb = cn * PBK; }
            else              { asrc = alo; ka = (cn - 32) * PBK; kb = (cn - 32) * PBK; }
#pragma unroll
            for (int it = 0; it < 2; it++) {
                int idx = tid + it * 256;
                int r = idx >> 2, cc = idx & 3;
                pa[it] = *(const uint4*)(asrc + (size_t)(m0 + r) * In + ka + cc * 8);
            }
#pragma unroll
            for (int it = 0; it < 2; it++) {
                int idx = tid + it * 256;
                if (idx < 320) {
                    int r = idx >> 2, cc = idx & 3;
                    pb[it] = *(const uint4*)(wc + (size_t)(n0 + r) * 1024 + kb + cc * 8);
                }
            }
        }

        const uint32_t aOff = buf * A_BYTES;
        const uint32_t bOff = buf * B_BYTES;
#pragma unroll
        for (int kk = 0; kk < 2; kk++) {       // two k16 steps
            uint32_t a[2][4], b[5][2];
#pragma unroll
            for (int mt = 0; mt < 2; mt++)
                ldmatrix_x4(a[mt][0], a[mt][1], a[mt][2], a[mt][3],
                            aAddr[mt] + aOff + kk * 32);
#pragma unroll
            for (int nt = 0; nt < 5; nt++)
                ldmatrix_x2(b[nt][0], b[nt][1], bAddr[nt] + bOff + kk * 32);
#pragma unroll
            for (int mt = 0; mt < 2; mt++)
#pragma unroll
                for (int nt = 0; nt < 5; nt++)
                    mma_bf16(acc[mt][nt][0], acc[mt][nt][1], acc[mt][nt][2], acc[mt][nt][3],
                             a[mt][0], a[mt][1], a[mt][2], a[mt][3],
                             b[nt][0], b[nt][1]);
        }

        if (c + 1 < PCHUNK) {
            const int nb = buf ^ 1;
#pragma unroll
            for (int it = 0; it < 2; it++) {
                int idx = tid + it * 256;
                int r = idx >> 2, cc = idx & 3;
                *(uint4*)(&sA[nb][r * A_STRIDE + cc * 16]) = pa[it];
            }
#pragma unroll
            for (int it = 0; it < 2; it++) {
                int idx = tid + it * 256;
                if (idx < 320) {
                    int r = idx >> 2, cc = idx & 3;
                    *(uint4*)(&sB[nb][r * A_STRIDE + cc * 16]) = pb[it];
                }
            }
            __syncthreads();
        }
    }

    // epilogue: acc[mt][nt] -> rows m0+wm*32+mt*16+{lane/4, lane/4+8},
    //                          cols n0+wn*40+nt*8+2*(lane%4)+{0,1}
    float* __restrict__ outp = g_proj[dir];
#pragma unroll
    for (int mt = 0; mt < 2; mt++) {
        int mrow0 = m0 + wm * 32 + mt * 16 + (lane >> 2);
#pragma unroll
        for (int nt = 0; nt < 5; nt++) {
            int n = n0 + wn * 40 + nt * 8 + ((lane & 3) << 1);
            float2 bv = *(const float2*)(bias + g * Hn + n);
            float2 v0 = make_float2(acc[mt][nt][0] + bv.x, acc[mt][nt][1] + bv.y);
            float2 v1 = make_float2(acc[mt][nt][2] + bv.x, acc[mt][nt][3] + bv.y);
            *(float2*)(outp + (size_t)mrow0 * FH + (size_t)g * Hn + n) = v0;
            *(float2*)(outp + (size_t)(mrow0 + 8) * FH + (size_t)g * Hn + n) = v1;
        }
    }
}

// ---------------- fast gate nonlinearities ----------------------------------
__device__ __forceinline__ float fast_sigmoid(float x) {
    return __fdividef(1.f, 1.f + __expf(-x));
}
__device__ __forceinline__ float fast_tanh(float x) {
    float e = __expf(2.f * x);
    return 1.f - __fdividef(2.f, e + 1.f);
}

// ---------------- persistent recurrence (unchanged, known-good) --------------
__global__ void __launch_bounds__(256, 1)
lstm_persistent(const float* __restrict__ U_f,
                const float* __restrict__ U_b,
                float* __restrict__ out)
{
    extern __shared__ float smem[];
    float* Bs = smem;
    float* As = Bs + Hn * WCOLS;
    float* zs = As + 2 * 64 * ASTR;

    const int bid = blockIdx.x;
    const int dir = bid / NCTA_DIR;
    const int j   = bid - dir * NCTA_DIR;
    const int h0  = j * NH;
    const int tid = threadIdx.x;
    const int mt  = tid >> 4;
    const int jt  = tid & 15;
    const float* __restrict__ U = dir ? U_b : U_f;

    for (int idx = tid; idx < Hn * WCOLS; idx += 256) {
        int k = idx / WCOLS;
        int w = idx - k * WCOLS;
        int g = w / NH;
        int c = w - g * NH;
        int hh = h0 + c;
        Bs[idx] = (hh < Hn) ? U[(size_t)k * FH + (size_t)g * Hn + hh] : 0.f;
    }
    __syncthreads();

    unsigned sense = 0;
    const float* __restrict__ proj = g_proj[dir];

    for (int t = 0; t < Tn; t++) {
        const int cur = t & 1;
        const float* __restrict__ hprev = g_h[dir][cur];
        float* __restrict__ hnext = g_h[dir][cur ^ 1];

#pragma unroll
        for (int r = 0; r < 2; r++) {
            int idx = tid + r * 256;
            int b   = idx >> 3;
            int kk  = (idx & 7) * 4;
            float4 hv = *(const float4*)(hprev + (size_t)b * Hn + kk);
            *(float4*)&As[b * ASTR + kk] = hv;
        }
        __syncthreads();

        float acc[4][3];
#pragma unroll
        for (int r = 0; r < 4; r++) { acc[r][0] = 0.f; acc[r][1] = 0.f; acc[r][2] = 0.f; }

        for (int blk = 0; blk < 25; blk++) {
            const int buf = blk & 1;
            float4 pf0, pf1;
            if (blk < 24) {
                const int kn = (blk + 1) * 32;
                int i0 = tid, i1 = tid + 256;
                pf0 = *(const float4*)(hprev + (size_t)(i0 >> 3) * Hn + kn + (i0 & 7) * 4);
                pf1 = *(const float4*)(hprev + (size_t)(i1 >> 3) * Hn + kn + (i1 & 7) * 4);
            }
            const float* Ab = As + buf * (64 * ASTR);
            const int kbase = blk * 32;
#pragma unroll
            for (int kk = 0; kk < 32; kk += 4) {
                float4 ar[4];
#pragma unroll
                for (int r = 0; r < 4; r++)
                    ar[r] = *(const float4*)&Ab[(mt * 4 + r) * ASTR + kk];
#pragma unroll
                for (int q = 0; q < 4; q++) {
                    const float* Bk = Bs + (size_t)(kbase + kk + q) * WCOLS;
                    float b0 = Bk[jt];
                    float b1 = Bk[jt + 16];
                    float b2 = Bk[jt + 32];
                    float a0 = (q == 0) ? ar[0].x : (q == 1) ? ar[0].y : (q == 2) ? ar[0].z : ar[0].w;
                    float a1 = (q == 0) ? ar[1].x : (q == 1) ? ar[1].y : (q == 2) ? ar[1].z : ar[1].w;
                    float a2 = (q == 0) ? ar[2].x : (q == 1) ? ar[2].y : (q == 2) ? ar[2].z : ar[2].w;
                    float a3 = (q == 0) ? ar[3].x : (q == 1) ? ar[3].y : (q == 2) ? ar[3].z : ar[3].w;
                    acc[0][0] = fmaf(a0, b0, acc[0][0]); acc[0][1] = fmaf(a0, b1, acc[0][1]); acc[0][2] = fmaf(a0, b2, acc[0][2]);
                    acc[1][0] = fmaf(a1, b0, acc[1][0]); acc[1][1] = fmaf(a1, b1, acc[1][1]); acc[1][2] = fmaf(a1, b2, acc[1][2]);
                    acc[2][0] = fmaf(a2, b0, acc[2][0]); acc[2][1] = fmaf(a2, b1, acc[2][1]); acc[2][2] = fmaf(a2, b2, acc[2][2]);
                    acc[3][0] = fmaf(a3, b0, acc[3][0]); acc[3][1] = fmaf(a3, b1, acc[3][1]); acc[3][2] = fmaf(a3, b2, acc[3][2]);
                }
            }
            if (blk < 24) {
                float* An = As + (buf ^ 1) * (64 * ASTR);
                int i0 = tid, i1 = tid + 256;
                *(float4*)&An[(i0 >> 3) * ASTR + (i0 & 7) * 4] = pf0;
                *(float4*)&An[(i1 >> 3) * ASTR + (i1 & 7) * 4] = pf1;
                __syncthreads();
            }
        }

        __syncthreads();
#pragma unroll
        for (int r = 0; r < 4; r++) {
            int b = mt * 4 + r;
            zs[b * WCOLS + jt]      = acc[r][0];
            zs[b * WCOLS + jt + 16] = acc[r][1];
            zs[b * WCOLS + jt + 32] = acc[r][2];
        }
        __syncthreads();

        const int t_eff = dir ? (Tn - 1 - t) : t;
#pragma unroll
        for (int it = 0; it < 3; it++) {
            int idx = it * 256 + tid;
            int b = idx / NH;
            int c = idx - b * NH;
            int hh = h0 + c;
            if (hh < Hn) {
                size_t pbase = ((size_t)b * Tn + t_eff) * FH;
                float zi = zs[b * WCOLS + 0 * NH + c] + proj[pbase + 0 * Hn + hh];
                float zf = zs[b * WCOLS + 1 * NH + c] + proj[pbase + 1 * Hn + hh];
                float zg = zs[b * WCOLS + 2 * NH + c] + proj[pbase + 2 * Hn + hh];
                float zo = zs[b * WCOLS + 3 * NH + c] + proj[pbase + 3 * Hn + hh];

                float ig = fast_sigmoid(zi);
                float fg = fast_sigmoid(zf);
                float gg = fast_tanh(zg);
                float og = fast_sigmoid(zo);

                size_t ci = (size_t)b * Hn + hh;
                float cv = fg * g_c[dir][ci] + ig * gg;
                float hv = og * fast_tanh(cv);
                g_c[dir][ci] = cv;
                hnext[ci] = hv;

                out[((size_t)b * Tn + t) * (2 * Hn) + (size_t)dir * Hn + hh] = hv;
                if (t == Tn - 1) {
                    size_t hcat0 = (size_t)Bn * Tn * (2 * Hn);
                    size_t ccat0 = hcat0 + (size_t)Bn * (2 * Hn);
                    out[hcat0 + (size_t)b * (2 * Hn) + (size_t)dir * Hn + hh] = hv;
                    out[ccat0 + (size_t)b * (2 * Hn) + (size_t)dir * Hn + hh] = cv;
                }
            }
        }

        __threadfence();
        __syncthreads();
        if (tid == 0) {
            unsigned ns = sense ^ 1u;
            unsigned arrived = atomicAdd((unsigned*)&g_bar_count[dir], 1u);
            if (arrived == NCTA_DIR - 1) {
                g_bar_count[dir] = 0u;
                __threadfence();
                g_bar_sense[dir] = ns;
            } else {
                while (g_bar_sense[dir] != ns) __nanosleep(64);
            }
            __threadfence();
        }
        __syncthreads();
        sense ^= 1u;
    }
}

// ---------------- launch ------------------------------------------------------
extern "C" void kernel_launch(void* const* d_in, const int* in_sizes, int n_in,
                              void* d_out, int out_size)
{
    const float* x      = (const float*)d_in[0];
    const float* mask_f = (const float*)d_in[1];
    const float* mask_b = (const float*)d_in[2];
    const float* W_f    = (const float*)d_in[3];
    const float* U_f    = (const float*)d_in[4];
    const float* b_f    = (const float*)d_in[5];
    const float* W_b    = (const float*)d_in[6];
    const float* U_b    = (const float*)d_in[7];
    const float* b_b    = (const float*)d_in[8];
    float* out = (float*)d_out;

    const int lstm_smem = (Hn * WCOLS + 2 * 64 * ASTR + 64 * WCOLS) * sizeof(float); // 184320
    static int configured = 0;
    if (!configured) {
        cudaFuncSetAttribute(lstm_persistent,
                             cudaFuncAttributeMaxDynamicSharedMemorySize, lstm_smem);
        configured = 1;
    }

    init_state<<<(Bn * Hn + 255) / 256, 256>>>();
    convert_x<<<(Bn * Tn * (In / 4) + 255) / 256, 256>>>(x, mask_f, mask_b);
    convert_w<<<(8 * In * Hn + 255) / 256, 256>>>(W_f, W_b);
    proj_mma<<<dim3(10, 128, 8), 256>>>(b_f, b_b);
    lstm_persistent<<<2 * NCTA_DIR, 256, lstm_smem>>>(U_f, U_b, out);
}

// round 7
// speedup vs baseline: 3.2587x; 1.5529x over previous
#include <cuda_runtime.h>
#include <cuda_bf16.h>
#include <math.h>
#include <stdint.h>

#define Bn 64
#define Tn 256
#define In 512
#define Hn 800
#define FH 3200   // 4*H

#define NCTA_DIR 67
#define NH 12
#define WCOLS 48

// SMEM geometry for persistent kernel
#define USTR_B 1616            // bytes per U row (808 bf16), conflict-free
#define U_BYTES (96 * USTR_B)  // 155136
#define ASTR_B 176             // bytes per A row (88 bf16), conflict-free
#define A_HALF (64 * ASTR_B)   // 11264 (hi or lo)
#define A_BUF  (2 * A_HALF)    // 22528 per buffer
#define A_OFF  U_BYTES
#define ZS_OFF (U_BYTES + 2 * A_BUF)   // 200192
#define ZSTR 52
#define LSTM_SMEM (ZS_OFF + 64 * ZSTR * 4)  // 213504

// ---------------- device globals ------------------------------------------
__device__ float g_proj[2][Bn * Tn * FH];
__device__ __nv_bfloat16 g_ahi[8][Bn * Tn * In];
__device__ __nv_bfloat16 g_alo[8][Bn * Tn * In];
__device__ __nv_bfloat16 g_wcat[8][Hn * 1024];
__device__ __nv_bfloat16 g_hbf[2][2][2][Bn * Hn];   // [dir][buf][hi=0/lo=1]
__device__ float g_c[2][Bn * Hn];
__device__ volatile unsigned g_bar_count[2];
__device__ volatile unsigned g_bar_sense[2];

__global__ void init_state() {
    int i = blockIdx.x * blockDim.x + threadIdx.x;
    if (i < Bn * Hn) {
        __nv_bfloat16 z = __float2bfloat16(0.f);
#pragma unroll
        for (int d = 0; d < 2; d++)
#pragma unroll
            for (int bu = 0; bu < 2; bu++)
#pragma unroll
                for (int p = 0; p < 2; p++)
                    g_hbf[d][bu][p][i] = z;
        g_c[0][i] = 0.f; g_c[1][i] = 0.f;
    }
    if (i < 2) { g_bar_count[i] = 0u; g_bar_sense[i] = 0u; }
}

// ---------------- helpers ---------------------------------------------------
__device__ __forceinline__ uint32_t smem_u32(const void* p) {
    uint32_t a;
    asm("{ .reg .u64 t; cvta.to.shared.u64 t, %1; cvt.u32.u64 %0, t; }" : "=r"(a) : "l"(p));
    return a;
}
__device__ __forceinline__ void ldmatrix_x4(uint32_t& a0, uint32_t& a1, uint32_t& a2, uint32_t& a3,
                                            uint32_t addr) {
    asm volatile("ldmatrix.sync.aligned.m8n8.x4.shared.b16 {%0,%1,%2,%3}, [%4];"
                 : "=r"(a0), "=r"(a1), "=r"(a2), "=r"(a3) : "r"(addr));
}
__device__ __forceinline__ void ldmatrix_x2(uint32_t& b0, uint32_t& b1, uint32_t addr) {
    asm volatile("ldmatrix.sync.aligned.m8n8.x2.shared.b16 {%0,%1}, [%2];"
                 : "=r"(b0), "=r"(b1) : "r"(addr));
}
__device__ __forceinline__ void mma_bf16(float& c0, float& c1, float& c2, float& c3,
                                         uint32_t a0, uint32_t a1, uint32_t a2, uint32_t a3,
                                         uint32_t b0, uint32_t b1) {
    asm volatile("mma.sync.aligned.m16n8k16.row.col.f32.bf16.bf16.f32 "
                 "{%0,%1,%2,%3}, {%4,%5,%6,%7}, {%8,%9}, {%0,%1,%2,%3};"
                 : "+f"(c0), "+f"(c1), "+f"(c2), "+f"(c3)
                 : "r"(a0), "r"(a1), "r"(a2), "r"(a3), "r"(b0), "r"(b1));
}

// ---------------- conversion kernels (unchanged) -----------------------------
__global__ void convert_x(const float* __restrict__ x,
                          const float* __restrict__ mask_f,
                          const float* __restrict__ mask_b)
{
    int idx = blockIdx.x * blockDim.x + threadIdx.x;
    if (idx >= Bn * Tn * (In / 4)) return;
    int bt = idx >> 7;
    int i4 = idx & 127;
    int b  = bt >> 8;
    float4 xv = *(const float4*)(x + (size_t)bt * In + i4 * 4);
#pragma unroll
    for (int dir = 0; dir < 2; dir++) {
        const float* mask = dir ? mask_b : mask_f;
#pragma unroll
        for (int g = 0; g < 4; g++) {
            float4 mv = *(const float4*)(mask + (size_t)b * (4 * In) + (size_t)g * In + i4 * 4);
            float v[4] = {xv.x * mv.x, xv.y * mv.y, xv.z * mv.z, xv.w * mv.w};
            __nv_bfloat16 h[4], l[4];
#pragma unroll
            for (int q = 0; q < 4; q++) {
                h[q] = __float2bfloat16(v[q]);
                l[q] = __float2bfloat16(v[q] - __bfloat162float(h[q]));
            }
            int z = dir * 4 + g;
            size_t o = (size_t)bt * In + i4 * 4;
            __nv_bfloat162 h0; h0.x = h[0]; h0.y = h[1];
            __nv_bfloat162 h1; h1.x = h[2]; h1.y = h[3];
            __nv_bfloat162 l0; l0.x = l[0]; l0.y = l[1];
            __nv_bfloat162 l1; l1.x = l[2]; l1.y = l[3];
            *(__nv_bfloat162*)&g_ahi[z][o]     = h0;
            *(__nv_bfloat162*)&g_ahi[z][o + 2] = h1;
            *(__nv_bfloat162*)&g_alo[z][o]     = l0;
            *(__nv_bfloat162*)&g_alo[z][o + 2] = l1;
        }
    }
}

__global__ void convert_w(const float* __restrict__ W_f,
                          const float* __restrict__ W_b)
{
    int idx = blockIdx.x * blockDim.x + threadIdx.x;
    if (idx >= 8 * In * Hn) return;
    int n    = idx % Hn;
    int rest = idx / Hn;
    int ks   = rest & 511;
    int z    = rest >> 9;
    int dir  = z >> 2, g = z & 3;
    const float* W = dir ? W_b : W_f;
    float v = W[(size_t)ks * FH + (size_t)g * Hn + n];
    __nv_bfloat16 h = __float2bfloat16(v);
    __nv_bfloat16 l = __float2bfloat16(v - __bfloat162float(h));
    g_wcat[z][(size_t)n * 1024 + ks]       = h;
    g_wcat[z][(size_t)n * 1024 + 512 + ks] = l;
}

// ---------------- proj GEMM via mma.sync (unchanged from R6) -----------------
#define PBK 32
#define PCHUNK 48
#define A_STRIDE 80
#define A_BYTES (128 * A_STRIDE)
#define B_BYTES (80  * A_STRIDE)

__global__ void __launch_bounds__(256)
proj_mma(const float* __restrict__ bias_f, const float* __restrict__ bias_b)
{
    __shared__ char sA[2][A_BYTES];
    __shared__ char sB[2][B_BYTES];

    const int z   = blockIdx.z;
    const int dir = z >> 2, g = z & 3;
    const int m0  = blockIdx.y * 128;
    const int n0  = blockIdx.x * 80;
    const __nv_bfloat16* __restrict__ ahi = g_ahi[z];
    const __nv_bfloat16* __restrict__ alo = g_alo[z];
    const __nv_bfloat16* __restrict__ wc  = g_wcat[z];
    const float* __restrict__ bias = dir ? bias_b : bias_f;

    const int tid  = threadIdx.x;
    const int wid  = tid >> 5;
    const int lane = tid & 31;
    const int wm   = wid & 3;
    const int wn   = wid >> 2;

    const uint32_t sAu = smem_u32(&sA[0][0]);
    const uint32_t sBu = smem_u32(&sB[0][0]);

    uint32_t aAddr[2], bAddr[5];
#pragma unroll
    for (int mt = 0; mt < 2; mt++) {
        int row = wm * 32 + mt * 16 + (lane & 15);
        aAddr[mt] = sAu + row * A_STRIDE + ((lane >> 4) << 3) * 2;
    }
#pragma unroll
    for (int nt = 0; nt < 5; nt++) {
        int row = wn * 40 + nt * 8 + (lane & 7);
        bAddr[nt] = sBu + row * A_STRIDE + (((lane >> 3) & 1) << 3) * 2;
    }

    float acc[2][5][4];
#pragma unroll
    for (int mt = 0; mt < 2; mt++)
#pragma unroll
        for (int nt = 0; nt < 5; nt++)
#pragma unroll
            for (int q = 0; q < 4; q++) acc[mt][nt][q] = 0.f;

    {
#pragma unroll
        for (int it = 0; it < 2; it++) {
            int idx = tid + it * 256;
            int r = idx >> 2, c = idx & 3;
            uint4 v = *(const uint4*)(ahi + (size_t)(m0 + r) * In + c * 8);
            *(uint4*)(&sA[0][r * A_STRIDE + c * 16]) = v;
        }
#pragma unroll
        for (int it = 0; it < 2; it++) {
            int idx = tid + it * 256;
            if (idx < 320) {
                int r = idx >> 2, c = idx & 3;
                uint4 v = *(const uint4*)(wc + (size_t)(n0 + r) * 1024 + c * 8);
                *(uint4*)(&sB[0][r * A_STRIDE + c * 16]) = v;
            }
        }
    }
    __syncthreads();

    for (int c = 0; c < PCHUNK; c++) {
        const int buf = c & 1;
        uint4 pa[2], pb[2];
        if (c + 1 < PCHUNK) {
            const int cn = c + 1;
            int ka, kb;
            const __nv_bfloat16* asrc;
            if (cn < 16)      { asrc = ahi; ka = cn * PBK;        kb = cn * PBK; }
            else if (cn < 32) { asrc = ahi; ka = (cn - 16) * PBK; kb = cn * PBK; }
            else              { asrc = alo; ka = (cn - 32) * PBK; kb = (cn - 32) * PBK; }
#pragma unroll
            for (int it = 0; it < 2; it++) {
                int idx = tid + it * 256;
                int r = idx >> 2, cc = idx & 3;
                pa[it] = *(const uint4*)(asrc + (size_t)(m0 + r) * In + ka + cc * 8);
            }
#pragma unroll
            for (int it = 0; it < 2; it++) {
                int idx = tid + it * 256;
                if (idx < 320) {
                    int r = idx >> 2, cc = idx & 3;
                    pb[it] = *(const uint4*)(wc + (size_t)(n0 + r) * 1024 + kb + cc * 8);
                }
            }
        }

        const uint32_t aOff = buf * A_BYTES;
        const uint32_t bOff = buf * B_BYTES;
#pragma unroll
        for (int kk = 0; kk < 2; kk++) {
            uint32_t a[2][4], b[5][2];
#pragma unroll
            for (int mt = 0; mt < 2; mt++)
                ldmatrix_x4(a[mt][0], a[mt][1], a[mt][2], a[mt][3],
                            aAddr[mt] + aOff + kk * 32);
#pragma unroll
            for (int nt = 0; nt < 5; nt++)
                ldmatrix_x2(b[nt][0], b[nt][1], bAddr[nt] + bOff + kk * 32);
#pragma unroll
            for (int mt = 0; mt < 2; mt++)
#pragma unroll
                for (int nt = 0; nt < 5; nt++)
                    mma_bf16(acc[mt][nt][0], acc[mt][nt][1], acc[mt][nt][2], acc[mt][nt][3],
                             a[mt][0], a[mt][1], a[mt][2], a[mt][3],
                             b[nt][0], b[nt][1]);
        }

        if (c + 1 < PCHUNK) {
            const int nb = buf ^ 1;
#pragma unroll
            for (int it = 0; it < 2; it++) {
                int idx = tid + it * 256;
                int r = idx >> 2, cc = idx & 3;
                *(uint4*)(&sA[nb][r * A_STRIDE + cc * 16]) = pa[it];
            }
#pragma unroll
            for (int it = 0; it < 2; it++) {
                int idx = tid + it * 256;
                if (idx < 320) {
                    int r = idx >> 2, cc = idx & 3;
                    *(uint4*)(&sB[nb][r * A_STRIDE + cc * 16]) = pb[it];
                }
            }
            __syncthreads();
        }
    }

    float* __restrict__ outp = g_proj[dir];
#pragma unroll
    for (int mt = 0; mt < 2; mt++) {
        int mrow0 = m0 + wm * 32 + mt * 16 + (lane >> 2);
#pragma unroll
        for (int nt = 0; nt < 5; nt++) {
            int n = n0 + wn * 40 + nt * 8 + ((lane & 3) << 1);
            float2 bv = *(const float2*)(bias + g * Hn + n);
            float2 v0 = make_float2(acc[mt][nt][0] + bv.x, acc[mt][nt][1] + bv.y);
            float2 v1 = make_float2(acc[mt][nt][2] + bv.x, acc[mt][nt][3] + bv.y);
            *(float2*)(outp + (size_t)mrow0 * FH + (size_t)g * Hn + n) = v0;
            *(float2*)(outp + (size_t)(mrow0 + 8) * FH + (size_t)g * Hn + n) = v1;
        }
    }
}

// ---------------- fast gate nonlinearities ----------------------------------
__device__ __forceinline__ float fast_sigmoid(float x) {
    return __fdividef(1.f, 1.f + __expf(-x));
}
__device__ __forceinline__ float fast_tanh(float x) {
    float e = __expf(2.f * x);
    return 1.f - __fdividef(2.f, e + 1.f);
}

// ---------------- persistent recurrence, HMMA split-bf16 ---------------------
// 134 CTAs (67/dir), 256 threads, 1 CTA/SM. U slice (96 rows x 800 k bf16,
// hi rows 0..47 / lo rows 48..95) resident in SMEM. Per step:
// z(64 x 48) = hhi@Uhi + hhi@Ulo + hlo@Uhi via mma.sync, 10 chunks of K=80.
__global__ void __launch_bounds__(256, 1)
lstm_persistent(const float* __restrict__ U_f,
                const float* __restrict__ U_b,
                float* __restrict__ out)
{
    extern __shared__ char dsm[];
    char*  sU = dsm;
    char*  sA = dsm + A_OFF;
    float* zs = (float*)(dsm + ZS_OFF);

    const int bid = blockIdx.x;
    const int dir = bid / NCTA_DIR;
    const int j   = bid - dir * NCTA_DIR;
    const int h0  = j * NH;
    const int tid = threadIdx.x;
    const int wid = tid >> 5;
    const int lane = tid & 31;
    const int wm  = wid & 3;            // 4 M tiles of 16
    const int wn  = wid >> 2;           // 2 N groups of 24
    const float* __restrict__ U = dir ? U_b : U_f;

    // ---- one-time: U slice -> SMEM bf16 hi/lo, k-major -----------------------
    for (int idx = tid; idx < 96 * Hn; idx += 256) {
        int k  = idx / 96;
        int w2 = idx - k * 96;
        int w  = (w2 < 48) ? w2 : w2 - 48;
        int g  = w / NH;
        int c  = w - g * NH;
        int hh = h0 + c;
        float v = (hh < Hn) ? U[(size_t)k * FH + (size_t)g * Hn + hh] : 0.f;
        __nv_bfloat16 hi = __float2bfloat16(v);
        __nv_bfloat16 res = (w2 < 48) ? hi : __float2bfloat16(v - __bfloat162float(hi));
        *(__nv_bfloat16*)(sU + (size_t)w2 * USTR_B + k * 2) = res;
    }

    // ---- precomputed decode tables ------------------------------------------
    // A chunk fill: 1280 uint4 (hi 0..639, lo 640..1279); per uint4: r=j/10, c=j%10
    int pr_goff[5], pr_soff[5];
    const __nv_bfloat16* hsel[5];   // set per-step below (depends on cur)
    int pr_part[5];
#pragma unroll
    for (int it = 0; it < 5; it++) {
        int idx = tid + it * 256;
        int part = (idx >= 640) ? 1 : 0;
        int jj = idx - part * 640;
        int r = jj / 10;
        int c = jj - r * 10;
        pr_part[it] = part;
        pr_goff[it] = r * Hn + c * 8;
        pr_soff[it] = r * ASTR_B + c * 16 + part * A_HALF;
    }
    // gate decode: idx -> (b, c)
    int gb[3], gc2[3];
#pragma unroll
    for (int it = 0; it < 3; it++) {
        int idx = it * 256 + tid;
        gb[it]  = idx / NH;
        gc2[it] = idx - gb[it] * NH;
    }

    // ldmatrix fragment addresses
    const uint32_t sAu = smem_u32(sA);
    const uint32_t sUu = smem_u32(sU);
    const uint32_t aBase = sAu + (wm * 16 + (lane & 15)) * ASTR_B + ((lane >> 4) << 4);
    uint32_t bHi[3];
#pragma unroll
    for (int nt = 0; nt < 3; nt++)
        bHi[nt] = sUu + (wn * 24 + nt * 8 + (lane & 7)) * USTR_B + (((lane >> 3) & 1) << 4);

    __syncthreads();

    unsigned sense = 0;
    const float* __restrict__ proj = g_proj[dir];

    for (int t = 0; t < Tn; t++) {
        const int cur = t & 1;
        const int nxt = cur ^ 1;
        const __nv_bfloat16* __restrict__ hhi = g_hbf[dir][cur][0];
        const __nv_bfloat16* __restrict__ hlo = g_hbf[dir][cur][1];

        // preload chunk 0 into buf 0
#pragma unroll
        for (int it = 0; it < 5; it++) {
            const __nv_bfloat16* src = pr_part[it] ? hlo : hhi;
            uint4 v = *(const uint4*)(src + pr_goff[it]);
            *(uint4*)(sA + pr_soff[it]) = v;
        }
        __syncthreads();

        float acc[3][4];
#pragma unroll
        for (int nt = 0; nt < 3; nt++)
#pragma unroll
            for (int q = 0; q < 4; q++) acc[nt][q] = 0.f;

        for (int chunk = 0; chunk < 10; chunk++) {
            const int buf = chunk & 1;
            uint4 pf[5];
            if (chunk < 9) {
                const int k0 = (chunk + 1) * 80;
#pragma unroll
                for (int it = 0; it < 5; it++) {
                    const __nv_bfloat16* src = pr_part[it] ? hlo : hhi;
                    pf[it] = *(const uint4*)(src + pr_goff[it] + k0);
                }
            }
            const uint32_t aOff = aBase + buf * A_BUF;
            const uint32_t kGlobByte = chunk * 160;   // chunk*80 k * 2B
#pragma unroll
            for (int kk = 0; kk < 5; kk++) {
                uint32_t ahi[4], alo[4], bh[3][2], bl[3][2];
                ldmatrix_x4(ahi[0], ahi[1], ahi[2], ahi[3], aOff + kk * 32);
                ldmatrix_x4(alo[0], alo[1], alo[2], alo[3], aOff + A_HALF + kk * 32);
#pragma unroll
                for (int nt = 0; nt < 3; nt++) {
                    uint32_t bb = bHi[nt] + kGlobByte + kk * 32;
                    ldmatrix_x2(bh[nt][0], bh[nt][1], bb);
                    ldmatrix_x2(bl[nt][0], bl[nt][1], bb + 48 * USTR_B);
                }
#pragma unroll
                for (int nt = 0; nt < 3; nt++) {
                    mma_bf16(acc[nt][0], acc[nt][1], acc[nt][2], acc[nt][3],
                             ahi[0], ahi[1], ahi[2], ahi[3], bh[nt][0], bh[nt][1]);
                    mma_bf16(acc[nt][0], acc[nt][1], acc[nt][2], acc[nt][3],
                             ahi[0], ahi[1], ahi[2], ahi[3], bl[nt][0], bl[nt][1]);
                    mma_bf16(acc[nt][0], acc[nt][1], acc[nt][2], acc[nt][3],
                             alo[0], alo[1], alo[2], alo[3], bh[nt][0], bh[nt][1]);
                }
            }
            if (chunk < 9) {
                const int nb = buf ^ 1;
#pragma unroll
                for (int it = 0; it < 5; it++)
                    *(uint4*)(sA + nb * A_BUF + pr_soff[it]) = pf[it];
                __syncthreads();
            }
        }

        // write z fragments to zs[64][ZSTR]
        {
            int row0 = wm * 16 + (lane >> 2);
            int colb = wn * 24 + ((lane & 3) << 1);
#pragma unroll
            for (int nt = 0; nt < 3; nt++) {
                int col = colb + nt * 8;
                *(float2*)&zs[row0 * ZSTR + col]       = make_float2(acc[nt][0], acc[nt][1]);
                *(float2*)&zs[(row0 + 8) * ZSTR + col] = make_float2(acc[nt][2], acc[nt][3]);
            }
        }
        __syncthreads();

        // gate update
        const int t_eff = dir ? (Tn - 1 - t) : t;
#pragma unroll
        for (int it = 0; it < 3; it++) {
            int b  = gb[it];
            int c  = gc2[it];
            int hh = h0 + c;
            if (hh < Hn) {
                size_t pbase = ((size_t)b * Tn + t_eff) * FH;
                float zi = zs[b * ZSTR + 0 * NH + c] + proj[pbase + 0 * Hn + hh];
                float zf = zs[b * ZSTR + 1 * NH + c] + proj[pbase + 1 * Hn + hh];
                float zg = zs[b * ZSTR + 2 * NH + c] + proj[pbase + 2 * Hn + hh];
                float zo = zs[b * ZSTR + 3 * NH + c] + proj[pbase + 3 * Hn + hh];

                float ig = fast_sigmoid(zi);
                float fg = fast_sigmoid(zf);
                float gg = fast_tanh(zg);
                float og = fast_sigmoid(zo);

                size_t ci = (size_t)b * Hn + hh;
                float cv = fg * g_c[dir][ci] + ig * gg;
                float hv = og * fast_tanh(cv);
                g_c[dir][ci] = cv;

                __nv_bfloat16 hvh = __float2bfloat16(hv);
                __nv_bfloat16 hvl = __float2bfloat16(hv - __bfloat162float(hvh));
                g_hbf[dir][nxt][0][ci] = hvh;
                g_hbf[dir][nxt][1][ci] = hvl;

                out[((size_t)b * Tn + t) * (2 * Hn) + (size_t)dir * Hn + hh] = hv;
                if (t == Tn - 1) {
                    size_t hcat0 = (size_t)Bn * Tn * (2 * Hn);
                    size_t ccat0 = hcat0 + (size_t)Bn * (2 * Hn);
                    out[hcat0 + (size_t)b * (2 * Hn) + (size_t)dir * Hn + hh] = hv;
                    out[ccat0 + (size_t)b * (2 * Hn) + (size_t)dir * Hn + hh] = cv;
                }
            }
        }

        // per-direction grid barrier
        __threadfence();
        __syncthreads();
        if (tid == 0) {
            unsigned ns = sense ^ 1u;
            unsigned arrived = atomicAdd((unsigned*)&g_bar_count[dir], 1u);
            if (arrived == NCTA_DIR - 1) {
                g_bar_count[dir] = 0u;
                __threadfence();
                g_bar_sense[dir] = ns;
            } else {
                while (g_bar_sense[dir] != ns) __nanosleep(64);
            }
            __threadfence();
        }
        __syncthreads();
        sense ^= 1u;
    }
}

// ---------------- launch ------------------------------------------------------
extern "C" void kernel_launch(void* const* d_in, const int* in_sizes, int n_in,
                              void* d_out, int out_size)
{
    const float* x      = (const float*)d_in[0];
    const float* mask_f = (const float*)d_in[1];
    const float* mask_b = (const float*)d_in[2];
    const float* W_f    = (const float*)d_in[3];
    const float* U_f    = (const float*)d_in[4];
    const float* b_f    = (const float*)d_in[5];
    const float* W_b    = (const float*)d_in[6];
    const float* U_b    = (const float*)d_in[7];
    const float* b_b    = (const float*)d_in[8];
    float* out = (float*)d_out;

    static int configured = 0;
    if (!configured) {
        cudaFuncSetAttribute(lstm_persistent,
                             cudaFuncAttributeMaxDynamicSharedMemorySize, LSTM_SMEM);
        configured = 1;
    }

    init_state<<<(Bn * Hn + 255) / 256, 256>>>();
    convert_x<<<(Bn * Tn * (In / 4) + 255) / 256, 256>>>(x, mask_f, mask_b);
    convert_w<<<(8 * In * Hn + 255) / 256, 256>>>(W_f, W_b);
    proj_mma<<<dim3(10, 128, 8), 256>>>(b_f, b_b);
    lstm_persistent<<<2 * NCTA_DIR, 256, LSTM_SMEM>>>(U_f, U_b, out);
}

// round 9
// speedup vs baseline: 3.5123x; 1.0778x over previous
#include <cuda_runtime.h>
#include <cuda_bf16.h>
#include <math.h>
#include <stdint.h>

#define Bn 64
#define Tn 256
#define In 512
#define Hn 800
#define FH 3200   // 4*H

#define NCTA_DIR 67
#define NH 12
#define WCOLS 48

// SMEM geometry for persistent kernel
#define USTR_B 1616            // bytes per U row (808 bf16), conflict-free
#define U_BYTES (96 * USTR_B)  // 155136
#define ASTR_B 176             // bytes per A row (88 bf16), conflict-free
#define A_HALF (64 * ASTR_B)   // 11264 (hi or lo)
#define A_BUF  (2 * A_HALF)    // 22528 per buffer
#define A_OFF  U_BYTES
#define ZS_OFF (U_BYTES + 2 * A_BUF)   // 200192
#define ZSTR 52
#define LSTM_SMEM (ZS_OFF + 64 * ZSTR * 4)  // 213504

// ---------------- device globals ------------------------------------------
__device__ float g_proj[2][Bn * Tn * FH];
__device__ __nv_bfloat16 g_ahi[8][Bn * Tn * In];
__device__ __nv_bfloat16 g_alo[8][Bn * Tn * In];
__device__ __nv_bfloat16 g_wcat[8][Hn * 1024];
__device__ __nv_bfloat16 g_hbf[2][2][2][Bn * Hn];   // [dir][buf][hi=0/lo=1]
__device__ volatile unsigned g_bar_count[2];
__device__ volatile unsigned g_bar_sense[2];

__global__ void init_state() {
    int i = blockIdx.x * blockDim.x + threadIdx.x;
    if (i < Bn * Hn) {
        __nv_bfloat16 z = __float2bfloat16(0.f);
#pragma unroll
        for (int d = 0; d < 2; d++)
#pragma unroll
            for (int bu = 0; bu < 2; bu++)
#pragma unroll
                for (int p = 0; p < 2; p++)
                    g_hbf[d][bu][p][i] = z;
    }
    if (i < 2) { g_bar_count[i] = 0u; g_bar_sense[i] = 0u; }
}

// ---------------- helpers ---------------------------------------------------
__device__ __forceinline__ uint32_t smem_u32(const void* p) {
    uint32_t a;
    asm("{ .reg .u64 t; cvta.to.shared.u64 t, %1; cvt.u32.u64 %0, t; }" : "=r"(a) : "l"(p));
    return a;
}
__device__ __forceinline__ void ldmatrix_x4(uint32_t& a0, uint32_t& a1, uint32_t& a2, uint32_t& a3,
                                            uint32_t addr) {
    asm volatile("ldmatrix.sync.aligned.m8n8.x4.shared.b16 {%0,%1,%2,%3}, [%4];"
                 : "=r"(a0), "=r"(a1), "=r"(a2), "=r"(a3) : "r"(addr));
}
__device__ __forceinline__ void ldmatrix_x2(uint32_t& b0, uint32_t& b1, uint32_t addr) {
    asm volatile("ldmatrix.sync.aligned.m8n8.x2.shared.b16 {%0,%1}, [%2];"
                 : "=r"(b0), "=r"(b1) : "r"(addr));
}
__device__ __forceinline__ void mma_bf16(float& c0, float& c1, float& c2, float& c3,
                                         uint32_t a0, uint32_t a1, uint32_t a2, uint32_t a3,
                                         uint32_t b0, uint32_t b1) {
    asm volatile("mma.sync.aligned.m16n8k16.row.col.f32.bf16.bf16.f32 "
                 "{%0,%1,%2,%3}, {%4,%5,%6,%7}, {%8,%9}, {%0,%1,%2,%3};"
                 : "+f"(c0), "+f"(c1), "+f"(c2), "+f"(c3)
                 : "r"(a0), "r"(a1), "r"(a2), "r"(a3), "r"(b0), "r"(b1));
}
__device__ __forceinline__ void cp_async16(uint32_t saddr, const void* gptr) {
    asm volatile("cp.async.cg.shared.global [%0], [%1], 16;" :: "r"(saddr), "l"(gptr));
}
#define CP_COMMIT() asm volatile("cp.async.commit_group;" ::: "memory")
#define CP_WAIT0()  asm volatile("cp.async.wait_group 0;" ::: "memory")

// ---------------- conversion kernels (unchanged) -----------------------------
__global__ void convert_x(const float* __restrict__ x,
                          const float* __restrict__ mask_f,
                          const float* __restrict__ mask_b)
{
    int idx = blockIdx.x * blockDim.x + threadIdx.x;
    if (idx >= Bn * Tn * (In / 4)) return;
    int bt = idx >> 7;
    int i4 = idx & 127;
    int b  = bt >> 8;
    float4 xv = *(const float4*)(x + (size_t)bt * In + i4 * 4);
#pragma unroll
    for (int dir = 0; dir < 2; dir++) {
        const float* mask = dir ? mask_b : mask_f;
#pragma unroll
        for (int g = 0; g < 4; g++) {
            float4 mv = *(const float4*)(mask + (size_t)b * (4 * In) + (size_t)g * In + i4 * 4);
            float v[4] = {xv.x * mv.x, xv.y * mv.y, xv.z * mv.z, xv.w * mv.w};
            __nv_bfloat16 h[4], l[4];
#pragma unroll
            for (int q = 0; q < 4; q++) {
                h[q] = __float2bfloat16(v[q]);
                l[q] = __float2bfloat16(v[q] - __bfloat162float(h[q]));
            }
            int z = dir * 4 + g;
            size_t o = (size_t)bt * In + i4 * 4;
            __nv_bfloat162 h0; h0.x = h[0]; h0.y = h[1];
            __nv_bfloat162 h1; h1.x = h[2]; h1.y = h[3];
            __nv_bfloat162 l0; l0.x = l[0]; l0.y = l[1];
            __nv_bfloat162 l1; l1.x = l[2]; l1.y = l[3];
            *(__nv_bfloat162*)&g_ahi[z][o]     = h0;
            *(__nv_bfloat162*)&g_ahi[z][o + 2] = h1;
            *(__nv_bfloat162*)&g_alo[z][o]     = l0;
            *(__nv_bfloat162*)&g_alo[z][o + 2] = l1;
        }
    }
}

__global__ void convert_w(const float* __restrict__ W_f,
                          const float* __restrict__ W_b)
{
    int idx = blockIdx.x * blockDim.x + threadIdx.x;
    if (idx >= 8 * In * Hn) return;
    int n    = idx % Hn;
    int rest = idx / Hn;
    int ks   = rest & 511;
    int z    = rest >> 9;
    int dir  = z >> 2, g = z & 3;
    const float* W = dir ? W_b : W_f;
    float v = W[(size_t)ks * FH + (size_t)g * Hn + n];
    __nv_bfloat16 h = __float2bfloat16(v);
    __nv_bfloat16 l = __float2bfloat16(v - __bfloat162float(h));
    g_wcat[z][(size_t)n * 1024 + ks]       = h;
    g_wcat[z][(size_t)n * 1024 + 512 + ks] = l;
}

// ---------------- proj GEMM via mma.sync (unchanged, known-good) -------------
#define PBK 32
#define PCHUNK 48
#define A_STRIDE 80
#define A_BYTES (128 * A_STRIDE)
#define B_BYTES (80  * A_STRIDE)

__global__ void __launch_bounds__(256)
proj_mma(const float* __restrict__ bias_f, const float* __restrict__ bias_b)
{
    __shared__ char sA[2][A_BYTES];
    __shared__ char sB[2][B_BYTES];

    const int z   = blockIdx.z;
    const int dir = z >> 2, g = z & 3;
    const int m0  = blockIdx.y * 128;
    const int n0  = blockIdx.x * 80;
    const __nv_bfloat16* __restrict__ ahi = g_ahi[z];
    const __nv_bfloat16* __restrict__ alo = g_alo[z];
    const __nv_bfloat16* __restrict__ wc  = g_wcat[z];
    const float* __restrict__ bias = dir ? bias_b : bias_f;

    const int tid  = threadIdx.x;
    const int wid  = tid >> 5;
    const int lane = tid & 31;
    const int wm   = wid & 3;
    const int wn   = wid >> 2;

    const uint32_t sAu = smem_u32(&sA[0][0]);
    const uint32_t sBu = smem_u32(&sB[0][0]);

    uint32_t aAddr[2], bAddr[5];
#pragma unroll
    for (int mt = 0; mt < 2; mt++) {
        int row = wm * 32 + mt * 16 + (lane & 15);
        aAddr[mt] = sAu + row * A_STRIDE + ((lane >> 4) << 3) * 2;
    }
#pragma unroll
    for (int nt = 0; nt < 5; nt++) {
        int row = wn * 40 + nt * 8 + (lane & 7);
        bAddr[nt] = sBu + row * A_STRIDE + (((lane >> 3) & 1) << 3) * 2;
    }

    float acc[2][5][4];
#pragma unroll
    for (int mt = 0; mt < 2; mt++)
#pragma unroll
        for (int nt = 0; nt < 5; nt++)
#pragma unroll
            for (int q = 0; q < 4; q++) acc[mt][nt][q] = 0.f;

    {
#pragma unroll
        for (int it = 0; it < 2; it++) {
            int idx = tid + it * 256;
            int r = idx >> 2, c = idx & 3;
            uint4 v = *(const uint4*)(ahi + (size_t)(m0 + r) * In + c * 8);
            *(uint4*)(&sA[0][r * A_STRIDE + c * 16]) = v;
        }
#pragma unroll
        for (int it = 0; it < 2; it++) {
            int idx = tid + it * 256;
            if (idx < 320) {
                int r = idx >> 2, c = idx & 3;
                uint4 v = *(const uint4*)(wc + (size_t)(n0 + r) * 1024 + c * 8);
                *(uint4*)(&sB[0][r * A_STRIDE + c * 16]) = v;
            }
        }
    }
    __syncthreads();

    for (int c = 0; c < PCHUNK; c++) {
        const int buf = c & 1;
        uint4 pa[2], pb[2];
        if (c + 1 < PCHUNK) {
            const int cn = c + 1;
            int ka, kb;
            const __nv_bfloat16* asrc;
            if (cn < 16)      { asrc = ahi; ka = cn * PBK;        kb = cn * PBK; }
            else if (cn < 32) { asrc = ahi; ka = (cn - 16) * PBK; kb = cn * PBK; }
            else              { asrc = alo; ka = (cn - 32) * PBK; kb = (cn - 32) * PBK; }
#pragma unroll
            for (int it = 0; it < 2; it++) {
                int idx = tid + it * 256;
                int r = idx >> 2, cc = idx & 3;
                pa[it] = *(const uint4*)(asrc + (size_t)(m0 + r) * In + ka + cc * 8);
            }
#pragma unroll
            for (int it = 0; it < 2; it++) {
                int idx = tid + it * 256;
                if (idx < 320) {
                    int r = idx >> 2, cc = idx & 3;
                    pb[it] = *(const uint4*)(wc + (size_t)(n0 + r) * 1024 + kb + cc * 8);
                }
            }
        }

        const uint32_t aOff = buf * A_BYTES;
        const uint32_t bOff = buf * B_BYTES;
#pragma unroll
        for (int kk = 0; kk < 2; kk++) {
            uint32_t a[2][4], b[5][2];
#pragma unroll
            for (int mt = 0; mt < 2; mt++)
                ldmatrix_x4(a[mt][0], a[mt][1], a[mt][2], a[mt][3],
                            aAddr[mt] + aOff + kk * 32);
#pragma unroll
            for (int nt = 0; nt < 5; nt++)
                ldmatrix_x2(b[nt][0], b[nt][1], bAddr[nt] + bOff + kk * 32);
#pragma unroll
            for (int mt = 0; mt < 2; mt++)
#pragma unroll
                for (int nt = 0; nt < 5; nt++)
                    mma_bf16(acc[mt][nt][0], acc[mt][nt][1], acc[mt][nt][2], acc[mt][nt][3],
                             a[mt][0], a[mt][1], a[mt][2], a[mt][3],
                             b[nt][0], b[nt][1]);
        }

        if (c + 1 < PCHUNK) {
            const int nb = buf ^ 1;
#pragma unroll
            for (int it = 0; it < 2; it++) {
                int idx = tid + it * 256;
                int r = idx >> 2, cc = idx & 3;
                *(uint4*)(&sA[nb][r * A_STRIDE + cc * 16]) = pa[it];
            }
#pragma unroll
            for (int it = 0; it < 2; it++) {
                int idx = tid + it * 256;
                if (idx < 320) {
                    int r = idx >> 2, cc = idx & 3;
                    *(uint4*)(&sB[nb][r * A_STRIDE + cc * 16]) = pb[it];
                }
            }
            __syncthreads();
        }
    }

    float* __restrict__ outp = g_proj[dir];
#pragma unroll
    for (int mt = 0; mt < 2; mt++) {
        int mrow0 = m0 + wm * 32 + mt * 16 + (lane >> 2);
#pragma unroll
        for (int nt = 0; nt < 5; nt++) {
            int n = n0 + wn * 40 + nt * 8 + ((lane & 3) << 1);
            float2 bv = *(const float2*)(bias + g * Hn + n);
            float2 v0 = make_float2(acc[mt][nt][0] + bv.x, acc[mt][nt][1] + bv.y);
            float2 v1 = make_float2(acc[mt][nt][2] + bv.x, acc[mt][nt][3] + bv.y);
            *(float2*)(outp + (size_t)mrow0 * FH + (size_t)g * Hn + n) = v0;
            *(float2*)(outp + (size_t)(mrow0 + 8) * FH + (size_t)g * Hn + n) = v1;
        }
    }
}

// ---------------- fast gate nonlinearities ----------------------------------
__device__ __forceinline__ float fast_sigmoid(float x) {
    return __fdividef(1.f, 1.f + __expf(-x));
}
__device__ __forceinline__ float fast_tanh(float x) {
    float e = __expf(2.f * x);
    return 1.f - __fdividef(2.f, e + 1.f);
}

// ---------------- persistent recurrence, HMMA split-bf16 ---------------------
__global__ void __launch_bounds__(256, 1)
lstm_persistent(const float* __restrict__ U_f,
                const float* __restrict__ U_b,
                float* __restrict__ out)
{
    extern __shared__ char dsm[];
    char*  sU = dsm;
    char*  sA = dsm + A_OFF;
    float* zs = (float*)(dsm + ZS_OFF);

    const int bid = blockIdx.x;
    const int dir = bid / NCTA_DIR;
    const int j   = bid - dir * NCTA_DIR;
    const int h0  = j * NH;
    const int tid = threadIdx.x;
    const int lane = tid & 31;
    const int wid = tid >> 5;
    const int wm  = wid & 3;            // 4 M tiles of 16
    const int wn  = wid >> 2;           // 2 N groups of 24
    const float* __restrict__ U = dir ? U_b : U_f;

    // ---- one-time: U slice -> SMEM bf16 hi/lo, k-major -----------------------
    for (int idx = tid; idx < 96 * Hn; idx += 256) {
        int k  = idx / 96;
        int w2 = idx - k * 96;
        int w  = (w2 < 48) ? w2 : w2 - 48;
        int g  = w / NH;
        int c  = w - g * NH;
        int hh = h0 + c;
        float v = (hh < Hn) ? U[(size_t)k * FH + (size_t)g * Hn + hh] : 0.f;
        __nv_bfloat16 hi = __float2bfloat16(v);
        __nv_bfloat16 res = (w2 < 48) ? hi : __float2bfloat16(v - __bfloat162float(hi));
        *(__nv_bfloat16*)(sU + (size_t)w2 * USTR_B + k * 2) = res;
    }

    // ---- precomputed decode tables ------------------------------------------
    int pr_goff[5], pr_soff[5], pr_part[5];
#pragma unroll
    for (int it = 0; it < 5; it++) {
        int idx = tid + it * 256;
        int part = (idx >= 640) ? 1 : 0;
        int jj = idx - part * 640;
        int r = jj / 10;
        int c = jj - r * 10;
        pr_part[it] = part;
        pr_goff[it] = r * Hn + c * 8;
        pr_soff[it] = r * ASTR_B + c * 16 + part * A_HALF;
    }
    // gate decode (+ validity for the padded tail CTA)
    int gb[3], gc2[3], gvalid[3];
#pragma unroll
    for (int it = 0; it < 3; it++) {
        int idx = it * 256 + tid;
        gb[it]  = idx / NH;
        gc2[it] = idx - gb[it] * NH;
        gvalid[it] = (h0 + gc2[it] < Hn) ? 1 : 0;
    }

    // ldmatrix fragment addresses
    const uint32_t sAu = smem_u32(sA);
    const uint32_t sUu = smem_u32(sU);
    const uint32_t aBase = sAu + (wm * 16 + (lane & 15)) * ASTR_B + ((lane >> 4) << 4);
    // B x4: lanes 0-15 -> Uhi rows, lanes 16-31 -> Ulo rows (+48)
    uint32_t bAddr[3];
    {
        int l8 = lane & 7;
        int kh = (lane >> 3) & 1;
        int pt = lane >> 4;              // 0 = hi, 1 = lo
#pragma unroll
        for (int nt = 0; nt < 3; nt++)
            bAddr[nt] = sUu + (wn * 24 + nt * 8 + l8 + pt * 48) * USTR_B + (kh << 4);
    }

    __syncthreads();

    unsigned sense = 0;
    const float* __restrict__ proj = g_proj[dir];

    // persistent per-thread state
    float c_reg[3] = {0.f, 0.f, 0.f};
    float pp[3][4];
    // prefetch proj for t = 0 (guarded: padded h columns read nothing)
    {
        const int te = dir ? (Tn - 1) : 0;
#pragma unroll
        for (int it = 0; it < 3; it++) {
            pp[it][0] = pp[it][1] = pp[it][2] = pp[it][3] = 0.f;
            if (gvalid[it]) {
                size_t pbase = ((size_t)gb[it] * Tn + te) * FH + (h0 + gc2[it]);
                pp[it][0] = proj[pbase];
                pp[it][1] = proj[pbase + Hn];
                pp[it][2] = proj[pbase + 2 * Hn];
                pp[it][3] = proj[pbase + 3 * Hn];
            }
        }
    }

    for (int t = 0; t < Tn; t++) {
        const int cur = t & 1;
        const int nxt = cur ^ 1;
        const __nv_bfloat16* __restrict__ hhi = g_hbf[dir][cur][0];
        const __nv_bfloat16* __restrict__ hlo = g_hbf[dir][cur][1];

        // preload chunk 0 into buf 0 (cp.async, L1-bypass)
#pragma unroll
        for (int it = 0; it < 5; it++) {
            const __nv_bfloat16* src = pr_part[it] ? hlo : hhi;
            cp_async16(sAu + pr_soff[it], src + pr_goff[it]);
        }
        CP_COMMIT();
        CP_WAIT0();
        __syncthreads();

        float acc[3][4];
#pragma unroll
        for (int nt = 0; nt < 3; nt++)
#pragma unroll
            for (int q = 0; q < 4; q++) acc[nt][q] = 0.f;

        for (int chunk = 0; chunk < 10; chunk++) {
            const int buf = chunk & 1;
            if (chunk < 9) {
                const int k0 = (chunk + 1) * 80;
                const uint32_t dst = sAu + (buf ^ 1) * A_BUF;
#pragma unroll
                for (int it = 0; it < 5; it++) {
                    const __nv_bfloat16* src = pr_part[it] ? hlo : hhi;
                    cp_async16(dst + pr_soff[it], src + pr_goff[it] + k0);
                }
                CP_COMMIT();
            }
            const uint32_t aOff = aBase + buf * A_BUF;
            const uint32_t kGlobByte = chunk * 160;   // chunk*80 k * 2B
#pragma unroll
            for (int kk = 0; kk < 5; kk++) {
                uint32_t ahi[4], alo[4], b4[3][4];
                ldmatrix_x4(ahi[0], ahi[1], ahi[2], ahi[3], aOff + kk * 32);
                ldmatrix_x4(alo[0], alo[1], alo[2], alo[3], aOff + A_HALF + kk * 32);
#pragma unroll
                for (int nt = 0; nt < 3; nt++)
                    ldmatrix_x4(b4[nt][0], b4[nt][1], b4[nt][2], b4[nt][3],
                                bAddr[nt] + kGlobByte + kk * 32);
#pragma unroll
                for (int nt = 0; nt < 3; nt++) {
                    mma_bf16(acc[nt][0], acc[nt][1], acc[nt][2], acc[nt][3],
                             ahi[0], ahi[1], ahi[2], ahi[3], b4[nt][0], b4[nt][1]);
                    mma_bf16(acc[nt][0], acc[nt][1], acc[nt][2], acc[nt][3],
                             ahi[0], ahi[1], ahi[2], ahi[3], b4[nt][2], b4[nt][3]);
                    mma_bf16(acc[nt][0], acc[nt][1], acc[nt][2], acc[nt][3],
                             alo[0], alo[1], alo[2], alo[3], b4[nt][0], b4[nt][1]);
                }
            }
            if (chunk < 9) {
                CP_WAIT0();
                __syncthreads();
            }
        }

        // write z fragments to zs[64][ZSTR]
        {
            int row0 = wm * 16 + (lane >> 2);
            int colb = wn * 24 + ((lane & 3) << 1);
#pragma unroll
            for (int nt = 0; nt < 3; nt++) {
                int col = colb + nt * 8;
                *(float2*)&zs[row0 * ZSTR + col]       = make_float2(acc[nt][0], acc[nt][1]);
                *(float2*)&zs[(row0 + 8) * ZSTR + col] = make_float2(acc[nt][2], acc[nt][3]);
            }
        }
        __syncthreads();

        // gate update (proj from registers, c from registers)
#pragma unroll
        for (int it = 0; it < 3; it++) {
            if (gvalid[it]) {
                int b  = gb[it];
                int c  = gc2[it];
                int hh = h0 + c;
                float zi = zs[b * ZSTR + 0 * NH + c] + pp[it][0];
                float zf = zs[b * ZSTR + 1 * NH + c] + pp[it][1];
                float zg = zs[b * ZSTR + 2 * NH + c] + pp[it][2];
                float zo = zs[b * ZSTR + 3 * NH + c] + pp[it][3];

                float ig = fast_sigmoid(zi);
                float fg = fast_sigmoid(zf);
                float gg = fast_tanh(zg);
                float og = fast_sigmoid(zo);

                float cv = fg * c_reg[it] + ig * gg;
                float hv = og * fast_tanh(cv);
                c_reg[it] = cv;

                size_t ci = (size_t)b * Hn + hh;
                __nv_bfloat16 hvh = __float2bfloat16(hv);
                __nv_bfloat16 hvl = __float2bfloat16(hv - __bfloat162float(hvh));
                g_hbf[dir][nxt][0][ci] = hvh;
                g_hbf[dir][nxt][1][ci] = hvl;

                out[((size_t)b * Tn + t) * (2 * Hn) + (size_t)dir * Hn + hh] = hv;
                if (t == Tn - 1) {
                    size_t hcat0 = (size_t)Bn * Tn * (2 * Hn);
                    size_t ccat0 = hcat0 + (size_t)Bn * (2 * Hn);
                    out[hcat0 + (size_t)b * (2 * Hn) + (size_t)dir * Hn + hh] = hv;
                    out[ccat0 + (size_t)b * (2 * Hn) + (size_t)dir * Hn + hh] = cv;
                }
            }
        }

        // release h writes, then hide next-step proj loads behind the barrier
        __threadfence();
        __syncthreads();
        if (t + 1 < Tn) {
            const int te = dir ? (Tn - 2 - t) : (t + 1);
#pragma unroll
            for (int it = 0; it < 3; it++) {
                if (gvalid[it]) {
                    size_t pbase = ((size_t)gb[it] * Tn + te) * FH + (h0 + gc2[it]);
                    pp[it][0] = proj[pbase];
                    pp[it][1] = proj[pbase + Hn];
                    pp[it][2] = proj[pbase + 2 * Hn];
                    pp[it][3] = proj[pbase + 3 * Hn];
                }
            }
        }
        if (tid == 0) {
            unsigned ns = sense ^ 1u;
            unsigned arrived = atomicAdd((unsigned*)&g_bar_count[dir], 1u);
            if (arrived == NCTA_DIR - 1) {
                g_bar_count[dir] = 0u;
                __threadfence();
                g_bar_sense[dir] = ns;
            } else {
                while (g_bar_sense[dir] != ns) __nanosleep(32);
            }
            __threadfence();
        }
        __syncthreads();
        sense ^= 1u;
    }
}

// ---------------- launch ------------------------------------------------------
extern "C" void kernel_launch(void* const* d_in, const int* in_sizes, int n_in,
                              void* d_out, int out_size)
{
    const float* x      = (const float*)d_in[0];
    const float* mask_f = (const float*)d_in[1];
    const float* mask_b = (const float*)d_in[2];
    const float* W_f    = (const float*)d_in[3];
    const float* U_f    = (const float*)d_in[4];
    const float* b_f    = (const float*)d_in[5];
    const float* W_b    = (const float*)d_in[6];
    const float* U_b    = (const float*)d_in[7];
    const float* b_b    = (const float*)d_in[8];
    float* out = (float*)d_out;

    static int configured = 0;
    if (!configured) {
        cudaFuncSetAttribute(lstm_persistent,
                             cudaFuncAttributeMaxDynamicSharedMemorySize, LSTM_SMEM);
        configured = 1;
    }

    init_state<<<(Bn * Hn + 255) / 256, 256>>>();
    convert_x<<<(Bn * Tn * (In / 4) + 255) / 256, 256>>>(x, mask_f, mask_b);
    convert_w<<<(8 * In * Hn + 255) / 256, 256>>>(W_f, W_b);
    proj_mma<<<dim3(10, 128, 8), 256>>>(b_f, b_b);
    lstm_persistent<<<2 * NCTA_DIR, 256, LSTM_SMEM>>>(U_f, U_b, out);
}

// round 10
// speedup vs baseline: 4.2778x; 1.2179x over previous
#include <cuda_runtime.h>
#include <cuda_bf16.h>
#include <math.h>
#include <stdint.h>

#define Bn 64
#define Tn 256
#define In 512
#define Hn 800
#define FH 3200   // 4*H

#define NCTA_DIR 67
#define NH 12
#define WCOLS 48

// SMEM geometry for persistent kernel (U slice + z exchange only)
#define USTR_B 1616            // bytes per U row (808 bf16), conflict-free
#define U_BYTES (96 * USTR_B)  // 155136
#define ZS_OFF U_BYTES
#define ZSTR 52
#define LSTM_SMEM (ZS_OFF + 64 * ZSTR * 4)  // 168448

// ---------------- device globals ------------------------------------------
__device__ float g_proj[2][Bn * Tn * FH];
__device__ __nv_bfloat16 g_ahi[8][Bn * Tn * In];
__device__ __nv_bfloat16 g_alo[8][Bn * Tn * In];
__device__ __nv_bfloat16 g_wcat[8][Hn * 1024];
// h in MMA-fragment layout: [dir][buf][hi/lo][k16(50)][bg(4)][r(8)][m(4)][8 bf16]
// unit(k16,bg,r,m) = 16B = the exact ldmatrix.x4 A fragment for lane (r*4+m)
__device__ __nv_bfloat16 g_hfrag[2][2][2][51200];
__device__ volatile unsigned g_bar_count[2];
__device__ volatile unsigned g_bar_sense[2];

__global__ void init_state() {
    int i = blockIdx.x * blockDim.x + threadIdx.x;
    if (i < Bn * Hn) {
        __nv_bfloat16 z = __float2bfloat16(0.f);
#pragma unroll
        for (int d = 0; d < 2; d++)
#pragma unroll
            for (int bu = 0; bu < 2; bu++)
#pragma unroll
                for (int p = 0; p < 2; p++)
                    g_hfrag[d][bu][p][i] = z;
    }
    if (i < 2) { g_bar_count[i] = 0u; g_bar_sense[i] = 0u; }
}

// ---------------- helpers ---------------------------------------------------
__device__ __forceinline__ uint32_t smem_u32(const void* p) {
    uint32_t a;
    asm("{ .reg .u64 t; cvta.to.shared.u64 t, %1; cvt.u32.u64 %0, t; }" : "=r"(a) : "l"(p));
    return a;
}
__device__ __forceinline__ void ldmatrix_x4(uint32_t& a0, uint32_t& a1, uint32_t& a2, uint32_t& a3,
                                            uint32_t addr) {
    asm volatile("ldmatrix.sync.aligned.m8n8.x4.shared.b16 {%0,%1,%2,%3}, [%4];"
                 : "=r"(a0), "=r"(a1), "=r"(a2), "=r"(a3) : "r"(addr));
}
__device__ __forceinline__ void ldmatrix_x2(uint32_t& b0, uint32_t& b1, uint32_t addr) {
    asm volatile("ldmatrix.sync.aligned.m8n8.x2.shared.b16 {%0,%1}, [%2];"
                 : "=r"(b0), "=r"(b1) : "r"(addr));
}
__device__ __forceinline__ void mma_bf16(float& c0, float& c1, float& c2, float& c3,
                                         uint32_t a0, uint32_t a1, uint32_t a2, uint32_t a3,
                                         uint32_t b0, uint32_t b1) {
    asm volatile("mma.sync.aligned.m16n8k16.row.col.f32.bf16.bf16.f32 "
                 "{%0,%1,%2,%3}, {%4,%5,%6,%7}, {%8,%9}, {%0,%1,%2,%3};"
                 : "+f"(c0), "+f"(c1), "+f"(c2), "+f"(c3)
                 : "r"(a0), "r"(a1), "r"(a2), "r"(a3), "r"(b0), "r"(b1));
}
__device__ __forceinline__ uint4 ldcg_u4(const void* p) {
    uint4 v;
    asm volatile("ld.global.cg.v4.u32 {%0,%1,%2,%3}, [%4];"
                 : "=r"(v.x), "=r"(v.y), "=r"(v.z), "=r"(v.w) : "l"(p));
    return v;
}

// ---------------- conversion kernels (unchanged) -----------------------------
__global__ void convert_x(const float* __restrict__ x,
                          const float* __restrict__ mask_f,
                          const float* __restrict__ mask_b)
{
    int idx = blockIdx.x * blockDim.x + threadIdx.x;
    if (idx >= Bn * Tn * (In / 4)) return;
    int bt = idx >> 7;
    int i4 = idx & 127;
    int b  = bt >> 8;
    float4 xv = *(const float4*)(x + (size_t)bt * In + i4 * 4);
#pragma unroll
    for (int dir = 0; dir < 2; dir++) {
        const float* mask = dir ? mask_b : mask_f;
#pragma unroll
        for (int g = 0; g < 4; g++) {
            float4 mv = *(const float4*)(mask + (size_t)b * (4 * In) + (size_t)g * In + i4 * 4);
            float v[4] = {xv.x * mv.x, xv.y * mv.y, xv.z * mv.z, xv.w * mv.w};
            __nv_bfloat16 h[4], l[4];
#pragma unroll
            for (int q = 0; q < 4; q++) {
                h[q] = __float2bfloat16(v[q]);
                l[q] = __float2bfloat16(v[q] - __bfloat162float(h[q]));
            }
            int z = dir * 4 + g;
            size_t o = (size_t)bt * In + i4 * 4;
            __nv_bfloat162 h0; h0.x = h[0]; h0.y = h[1];
            __nv_bfloat162 h1; h1.x = h[2]; h1.y = h[3];
            __nv_bfloat162 l0; l0.x = l[0]; l0.y = l[1];
            __nv_bfloat162 l1; l1.x = l[2]; l1.y = l[3];
            *(__nv_bfloat162*)&g_ahi[z][o]     = h0;
            *(__nv_bfloat162*)&g_ahi[z][o + 2] = h1;
            *(__nv_bfloat162*)&g_alo[z][o]     = l0;
            *(__nv_bfloat162*)&g_alo[z][o + 2] = l1;
        }
    }
}

__global__ void convert_w(const float* __restrict__ W_f,
                          const float* __restrict__ W_b)
{
    int idx = blockIdx.x * blockDim.x + threadIdx.x;
    if (idx >= 8 * In * Hn) return;
    int n    = idx % Hn;
    int rest = idx / Hn;
    int ks   = rest & 511;
    int z    = rest >> 9;
    int dir  = z >> 2, g = z & 3;
    const float* W = dir ? W_b : W_f;
    float v = W[(size_t)ks * FH + (size_t)g * Hn + n];
    __nv_bfloat16 h = __float2bfloat16(v);
    __nv_bfloat16 l = __float2bfloat16(v - __bfloat162float(h));
    g_wcat[z][(size_t)n * 1024 + ks]       = h;
    g_wcat[z][(size_t)n * 1024 + 512 + ks] = l;
}

// ---------------- proj GEMM via mma.sync (unchanged, known-good) -------------
#define PBK 32
#define PCHUNK 48
#define A_STRIDE 80
#define A_BYTES (128 * A_STRIDE)
#define B_BYTES (80  * A_STRIDE)

__global__ void __launch_bounds__(256)
proj_mma(const float* __restrict__ bias_f, const float* __restrict__ bias_b)
{
    __shared__ char sA[2][A_BYTES];
    __shared__ char sB[2][B_BYTES];

    const int z   = blockIdx.z;
    const int dir = z >> 2, g = z & 3;
    const int m0  = blockIdx.y * 128;
    const int n0  = blockIdx.x * 80;
    const __nv_bfloat16* __restrict__ ahi = g_ahi[z];
    const __nv_bfloat16* __restrict__ alo = g_alo[z];
    const __nv_bfloat16* __restrict__ wc  = g_wcat[z];
    const float* __restrict__ bias = dir ? bias_b : bias_f;

    const int tid  = threadIdx.x;
    const int wid  = tid >> 5;
    const int lane = tid & 31;
    const int wm   = wid & 3;
    const int wn   = wid >> 2;

    const uint32_t sAu = smem_u32(&sA[0][0]);
    const uint32_t sBu = smem_u32(&sB[0][0]);

    uint32_t aAddr[2], bAddr[5];
#pragma unroll
    for (int mt = 0; mt < 2; mt++) {
        int row = wm * 32 + mt * 16 + (lane & 15);
        aAddr[mt] = sAu + row * A_STRIDE + ((lane >> 4) << 3) * 2;
    }
#pragma unroll
    for (int nt = 0; nt < 5; nt++) {
        int row = wn * 40 + nt * 8 + (lane & 7);
        bAddr[nt] = sBu + row * A_STRIDE + (((lane >> 3) & 1) << 3) * 2;
    }

    float acc[2][5][4];
#pragma unroll
    for (int mt = 0; mt < 2; mt++)
#pragma unroll
        for (int nt = 0; nt < 5; nt++)
#pragma unroll
            for (int q = 0; q < 4; q++) acc[mt][nt][q] = 0.f;

    {
#pragma unroll
        for (int it = 0; it < 2; it++) {
            int idx = tid + it * 256;
            int r = idx >> 2, c = idx & 3;
            uint4 v = *(const uint4*)(ahi + (size_t)(m0 + r) * In + c * 8);
            *(uint4*)(&sA[0][r * A_STRIDE + c * 16]) = v;
        }
#pragma unroll
        for (int it = 0; it < 2; it++) {
            int idx = tid + it * 256;
            if (idx < 320) {
                int r = idx >> 2, c = idx & 3;
                uint4 v = *(const uint4*)(wc + (size_t)(n0 + r) * 1024 + c * 8);
                *(uint4*)(&sB[0][r * A_STRIDE + c * 16]) = v;
            }
        }
    }
    __syncthreads();

    for (int c = 0; c < PCHUNK; c++) {
        const int buf = c & 1;
        uint4 pa[2], pb[2];
        if (c + 1 < PCHUNK) {
            const int cn = c + 1;
            int ka, kb;
            const __nv_bfloat16* asrc;
            if (cn < 16)      { asrc = ahi; ka = cn * PBK;        kb = cn * PBK; }
            else if (cn < 32) { asrc = ahi; ka = (cn - 16) * PBK; kb = cn * PBK; }
            else              { asrc = alo; ka = (cn - 32) * PBK; kb = (cn - 32) * PBK; }
#pragma unroll
            for (int it = 0; it < 2; it++) {
                int idx = tid + it * 256;
                int r = idx >> 2, cc = idx & 3;
                pa[it] = *(const uint4*)(asrc + (size_t)(m0 + r) * In + ka + cc * 8);
            }
#pragma unroll
            for (int it = 0; it < 2; it++) {
                int idx = tid + it * 256;
                if (idx < 320) {
                    int r = idx >> 2, cc = idx & 3;
                    pb[it] = *(const uint4*)(wc + (size_t)(n0 + r) * 1024 + kb + cc * 8);
                }
            }
        }

        const uint32_t aOff = buf * A_BYTES;
        const uint32_t bOff = buf * B_BYTES;
#pragma unroll
        for (int kk = 0; kk < 2; kk++) {
            uint32_t a[2][4], b[5][2];
#pragma unroll
            for (int mt = 0; mt < 2; mt++)
                ldmatrix_x4(a[mt][0], a[mt][1], a[mt][2], a[mt][3],
                            aAddr[mt] + aOff + kk * 32);
#pragma unroll
            for (int nt = 0; nt < 5; nt++)
                ldmatrix_x2(b[nt][0], b[nt][1], bAddr[nt] + bOff + kk * 32);
#pragma unroll
            for (int mt = 0; mt < 2; mt++)
#pragma unroll
                for (int nt = 0; nt < 5; nt++)
                    mma_bf16(acc[mt][nt][0], acc[mt][nt][1], acc[mt][nt][2], acc[mt][nt][3],
                             a[mt][0], a[mt][1], a[mt][2], a[mt][3],
                             b[nt][0], b[nt][1]);
        }

        if (c + 1 < PCHUNK) {
            const int nb = buf ^ 1;
#pragma unroll
            for (int it = 0; it < 2; it++) {
                int idx = tid + it * 256;
                int r = idx >> 2, cc = idx & 3;
                *(uint4*)(&sA[nb][r * A_STRIDE + cc * 16]) = pa[it];
            }
#pragma unroll
            for (int it = 0; it < 2; it++) {
                int idx = tid + it * 256;
                if (idx < 320) {
                    int r = idx >> 2, cc = idx & 3;
                    *(uint4*)(&sB[nb][r * A_STRIDE + cc * 16]) = pb[it];
                }
            }
            __syncthreads();
        }
    }

    float* __restrict__ outp = g_proj[dir];
#pragma unroll
    for (int mt = 0; mt < 2; mt++) {
        int mrow0 = m0 + wm * 32 + mt * 16 + (lane >> 2);
#pragma unroll
        for (int nt = 0; nt < 5; nt++) {
            int n = n0 + wn * 40 + nt * 8 + ((lane & 3) << 1);
            float2 bv = *(const float2*)(bias + g * Hn + n);
            float2 v0 = make_float2(acc[mt][nt][0] + bv.x, acc[mt][nt][1] + bv.y);
            float2 v1 = make_float2(acc[mt][nt][2] + bv.x, acc[mt][nt][3] + bv.y);
            *(float2*)(outp + (size_t)mrow0 * FH + (size_t)g * Hn + n) = v0;
            *(float2*)(outp + (size_t)(mrow0 + 8) * FH + (size_t)g * Hn + n) = v1;
        }
    }
}

// ---------------- fast gate nonlinearities ----------------------------------
__device__ __forceinline__ float fast_sigmoid(float x) {
    return __fdividef(1.f, 1.f + __expf(-x));
}
__device__ __forceinline__ float fast_tanh(float x) {
    float e = __expf(2.f * x);
    return 1.f - __fdividef(2.f, e + 1.f);
}

// ---------------- persistent recurrence: fragment-direct HMMA ---------------
// 134 CTAs (67/dir), 256 threads, 1 CTA/SM. U slice in SMEM (unchanged).
// h lives in GMEM in MMA-fragment layout: each lane's A operand is one
// ld.global.cg.v4 — no SMEM staging, no ldmatrix for A, no syncs in GEMM.
__global__ void __launch_bounds__(256, 1)
lstm_persistent(const float* __restrict__ U_f,
                const float* __restrict__ U_b,
                float* __restrict__ out)
{
    extern __shared__ char dsm[];
    char*  sU = dsm;
    float* zs = (float*)(dsm + ZS_OFF);

    const int bid = blockIdx.x;
    const int dir = bid / NCTA_DIR;
    const int j   = bid - dir * NCTA_DIR;
    const int h0  = j * NH;
    const int tid = threadIdx.x;
    const int lane = tid & 31;
    const int wid = tid >> 5;
    const int wm  = wid & 3;            // 4 M tiles of 16 batches
    const int wn  = wid >> 2;           // 2 N groups of 24 cols
    const float* __restrict__ U = dir ? U_b : U_f;

    // ---- one-time: U slice -> SMEM bf16 hi/lo, k-major -----------------------
    for (int idx = tid; idx < 96 * Hn; idx += 256) {
        int k  = idx / 96;
        int w2 = idx - k * 96;
        int w  = (w2 < 48) ? w2 : w2 - 48;
        int g  = w / NH;
        int c  = w - g * NH;
        int hh = h0 + c;
        float v = (hh < Hn) ? U[(size_t)k * FH + (size_t)g * Hn + hh] : 0.f;
        __nv_bfloat16 hi = __float2bfloat16(v);
        __nv_bfloat16 res = (w2 < 48) ? hi : __float2bfloat16(v - __bfloat162float(hi));
        *(__nv_bfloat16*)(sU + (size_t)w2 * USTR_B + k * 2) = res;
    }

    // ---- gate decode + fragment-layout scatter offsets -----------------------
    int gb[3], gc2[3], gvalid[3], hoff[3];
#pragma unroll
    for (int it = 0; it < 3; it++) {
        int idx = it * 256 + tid;
        gb[it]  = idx / NH;
        gc2[it] = idx - gb[it] * NH;
        int hh  = h0 + gc2[it];
        gvalid[it] = (hh < Hn) ? 1 : 0;
        int b = gb[it];
        int k16 = hh >> 4, kin = hh & 15;
        int bg = b >> 4, rr = b & 15;
        hoff[it] = k16 * 1024 + bg * 256 + (rr & 7) * 32 + ((kin & 7) >> 1) * 8
                 + (kin >> 3) * 4 + ((rr >> 3) & 1) * 2 + (kin & 1);
        if (!gvalid[it]) hoff[it] = 0;
    }

    // per-lane A fragment offset within a k16 block (bf16 elems)
    const int aoff = wm * 256 + (lane >> 2) * 32 + (lane & 3) * 8;

    // B ldmatrix addresses: x4, lanes 0-15 -> Uhi rows, 16-31 -> Ulo (+48)
    const uint32_t sUu = smem_u32(sU);
    uint32_t bAddr[3];
    {
        int l8 = lane & 7;
        int kh = (lane >> 3) & 1;
        int pt = lane >> 4;
#pragma unroll
        for (int nt = 0; nt < 3; nt++)
            bAddr[nt] = sUu + (wn * 24 + nt * 8 + l8 + pt * 48) * USTR_B + (kh << 4);
    }

    __syncthreads();

    unsigned sense = 0;
    const float* __restrict__ proj = g_proj[dir];

    // persistent per-thread state
    float c_reg[3] = {0.f, 0.f, 0.f};
    float pp[3][4];
    {
        const int te = dir ? (Tn - 1) : 0;
#pragma unroll
        for (int it = 0; it < 3; it++) {
            pp[it][0] = pp[it][1] = pp[it][2] = pp[it][3] = 0.f;
            if (gvalid[it]) {
                size_t pbase = ((size_t)gb[it] * Tn + te) * FH + (h0 + gc2[it]);
                pp[it][0] = proj[pbase];
                pp[it][1] = proj[pbase + Hn];
                pp[it][2] = proj[pbase + 2 * Hn];
                pp[it][3] = proj[pbase + 3 * Hn];
            }
        }
    }

    for (int t = 0; t < Tn; t++) {
        const int cur = t & 1;
        const int nxt = cur ^ 1;
        const __nv_bfloat16* __restrict__ fhi = g_hfrag[dir][cur][0];
        const __nv_bfloat16* __restrict__ flo = g_hfrag[dir][cur][1];

        float acc[3][4];
#pragma unroll
        for (int nt = 0; nt < 3; nt++)
#pragma unroll
            for (int q = 0; q < 4; q++) acc[nt][q] = 0.f;

        // register-double-buffered fragment GEMM over 50 k16 blocks
        uint4 Ah[2][5], Al[2][5];
#pragma unroll
        for (int j2 = 0; j2 < 5; j2++) {
            Ah[0][j2] = ldcg_u4(fhi + j2 * 1024 + aoff);
            Al[0][j2] = ldcg_u4(flo + j2 * 1024 + aoff);
        }
#pragma unroll
        for (int c = 0; c < 10; c++) {
            const int cb = c & 1, nb = cb ^ 1;
            if (c < 9) {
#pragma unroll
                for (int j2 = 0; j2 < 5; j2++) {
                    int kb = (c + 1) * 5 + j2;
                    Ah[nb][j2] = ldcg_u4(fhi + kb * 1024 + aoff);
                    Al[nb][j2] = ldcg_u4(flo + kb * 1024 + aoff);
                }
            }
#pragma unroll
            for (int j2 = 0; j2 < 5; j2++) {
                const int kglob = c * 5 + j2;
                uint32_t b4[3][4];
#pragma unroll
                for (int nt = 0; nt < 3; nt++)
                    ldmatrix_x4(b4[nt][0], b4[nt][1], b4[nt][2], b4[nt][3],
                                bAddr[nt] + kglob * 32);
#pragma unroll
                for (int nt = 0; nt < 3; nt++) {
                    mma_bf16(acc[nt][0], acc[nt][1], acc[nt][2], acc[nt][3],
                             Ah[cb][j2].x, Ah[cb][j2].y, Ah[cb][j2].z, Ah[cb][j2].w,
                             b4[nt][0], b4[nt][1]);
                    mma_bf16(acc[nt][0], acc[nt][1], acc[nt][2], acc[nt][3],
                             Ah[cb][j2].x, Ah[cb][j2].y, Ah[cb][j2].z, Ah[cb][j2].w,
                             b4[nt][2], b4[nt][3]);
                    mma_bf16(acc[nt][0], acc[nt][1], acc[nt][2], acc[nt][3],
                             Al[cb][j2].x, Al[cb][j2].y, Al[cb][j2].z, Al[cb][j2].w,
                             b4[nt][0], b4[nt][1]);
                }
            }
        }

        // write z fragments to zs[64][ZSTR]
        {
            int row0 = wm * 16 + (lane >> 2);
            int colb = wn * 24 + ((lane & 3) << 1);
#pragma unroll
            for (int nt = 0; nt < 3; nt++) {
                int col = colb + nt * 8;
                *(float2*)&zs[row0 * ZSTR + col]       = make_float2(acc[nt][0], acc[nt][1]);
                *(float2*)&zs[(row0 + 8) * ZSTR + col] = make_float2(acc[nt][2], acc[nt][3]);
            }
        }
        __syncthreads();

        // gate update (proj and c from registers; h scattered to fragment layout)
        __nv_bfloat16* __restrict__ whi = g_hfrag[dir][nxt][0];
        __nv_bfloat16* __restrict__ wlo = g_hfrag[dir][nxt][1];
#pragma unroll
        for (int it = 0; it < 3; it++) {
            if (gvalid[it]) {
                int b  = gb[it];
                int c  = gc2[it];
                int hh = h0 + c;
                float zi = zs[b * ZSTR + 0 * NH + c] + pp[it][0];
                float zf = zs[b * ZSTR + 1 * NH + c] + pp[it][1];
                float zg = zs[b * ZSTR + 2 * NH + c] + pp[it][2];
                float zo = zs[b * ZSTR + 3 * NH + c] + pp[it][3];

                float ig = fast_sigmoid(zi);
                float fg = fast_sigmoid(zf);
                float gg = fast_tanh(zg);
                float og = fast_sigmoid(zo);

                float cv = fg * c_reg[it] + ig * gg;
                float hv = og * fast_tanh(cv);
                c_reg[it] = cv;

                __nv_bfloat16 hvh = __float2bfloat16(hv);
                __nv_bfloat16 hvl = __float2bfloat16(hv - __bfloat162float(hvh));
                whi[hoff[it]] = hvh;
                wlo[hoff[it]] = hvl;

                out[((size_t)b * Tn + t) * (2 * Hn) + (size_t)dir * Hn + hh] = hv;
                if (t == Tn - 1) {
                    size_t hcat0 = (size_t)Bn * Tn * (2 * Hn);
                    size_t ccat0 = hcat0 + (size_t)Bn * (2 * Hn);
                    out[hcat0 + (size_t)b * (2 * Hn) + (size_t)dir * Hn + hh] = hv;
                    out[ccat0 + (size_t)b * (2 * Hn) + (size_t)dir * Hn + hh] = cv;
                }
            }
        }

        // release h writes; prefetch next-step proj behind the barrier wait
        __threadfence();
        __syncthreads();
        if (t + 1 < Tn) {
            const int te = dir ? (Tn - 2 - t) : (t + 1);
#pragma unroll
            for (int it = 0; it < 3; it++) {
                if (gvalid[it]) {
                    size_t pbase = ((size_t)gb[it] * Tn + te) * FH + (h0 + gc2[it]);
                    pp[it][0] = proj[pbase];
                    pp[it][1] = proj[pbase + Hn];
                    pp[it][2] = proj[pbase + 2 * Hn];
                    pp[it][3] = proj[pbase + 3 * Hn];
                }
            }
        }
        if (tid == 0) {
            unsigned ns = sense ^ 1u;
            unsigned arrived = atomicAdd((unsigned*)&g_bar_count[dir], 1u);
            if (arrived == NCTA_DIR - 1) {
                g_bar_count[dir] = 0u;
                __threadfence();
                g_bar_sense[dir] = ns;
            } else {
                while (g_bar_sense[dir] != ns) __nanosleep(32);
            }
            __threadfence();   // reader-side: CCTL.IVALL invalidates this SM's L1
        }
        __syncthreads();
        sense ^= 1u;
    }
}

// ---------------- launch ------------------------------------------------------
extern "C" void kernel_launch(void* const* d_in, const int* in_sizes, int n_in,
                              void* d_out, int out_size)
{
    const float* x      = (const float*)d_in[0];
    const float* mask_f = (const float*)d_in[1];
    const float* mask_b = (const float*)d_in[2];
    const float* W_f    = (const float*)d_in[3];
    const float* U_f    = (const float*)d_in[4];
    const float* b_f    = (const float*)d_in[5];
    const float* W_b    = (const float*)d_in[6];
    const float* U_b    = (const float*)d_in[7];
    const float* b_b    = (const float*)d_in[8];
    float* out = (float*)d_out;

    static int configured = 0;
    if (!configured) {
        cudaFuncSetAttribute(lstm_persistent,
                             cudaFuncAttributeMaxDynamicSharedMemorySize, LSTM_SMEM);
        configured = 1;
    }

    init_state<<<(Bn * Hn + 255) / 256, 256>>>();
    convert_x<<<(Bn * Tn * (In / 4) + 255) / 256, 256>>>(x, mask_f, mask_b);
    convert_w<<<(8 * In * Hn + 255) / 256, 256>>>(W_f, W_b);
    proj_mma<<<dim3(10, 128, 8), 256>>>(b_f, b_b);
    lstm_persistent<<<2 * NCTA_DIR, 256, LSTM_SMEM>>>(U_f, U_b, out);
}

// round 11
// speedup vs baseline: 4.8112x; 1.1247x over previous
#include <cuda_runtime.h>
#include <cuda_bf16.h>
#include <math.h>
#include <stdint.h>

#define Bn 64
#define Tn 256
#define In 512
#define Hn 800
#define FH 3200   // 4*H

#define NCTA_DIR 67
#define NH 12
#define WCOLS 48

// SMEM geometry for persistent kernel (U slice + z exchange only)
#define USTR_B 1616            // bytes per U row (808 bf16), conflict-free
#define U_BYTES (96 * USTR_B)  // 155136
#define ZS_OFF U_BYTES
#define ZSTR 52
#define LSTM_SMEM (ZS_OFF + 64 * ZSTR * 4)  // 168448

// ---------------- device globals ------------------------------------------
__device__ float g_proj[2][Bn * Tn * FH];
__device__ __nv_bfloat16 g_ahi[8][Bn * Tn * In];
__device__ __nv_bfloat16 g_alo[8][Bn * Tn * In];
__device__ __nv_bfloat16 g_wcat[8][Hn * 1024];
// h in MMA-fragment layout: [dir][buf][hi/lo][k16(50)][bg(4)][r(8)][m(4)][8 bf16]
__device__ __nv_bfloat16 g_hfrag[2][2][2][51200];
__device__ volatile unsigned g_bar_count[2];
__device__ volatile unsigned g_bar_sense[2];

__global__ void init_state() {
    int i = blockIdx.x * blockDim.x + threadIdx.x;
    if (i < Bn * Hn) {
        __nv_bfloat16 z = __float2bfloat16(0.f);
#pragma unroll
        for (int d = 0; d < 2; d++)
#pragma unroll
            for (int bu = 0; bu < 2; bu++)
#pragma unroll
                for (int p = 0; p < 2; p++)
                    g_hfrag[d][bu][p][i] = z;
    }
    if (i < 2) { g_bar_count[i] = 0u; g_bar_sense[i] = 0u; }
}

// ---------------- helpers ---------------------------------------------------
__device__ __forceinline__ uint32_t smem_u32(const void* p) {
    uint32_t a;
    asm("{ .reg .u64 t; cvta.to.shared.u64 t, %1; cvt.u32.u64 %0, t; }" : "=r"(a) : "l"(p));
    return a;
}
__device__ __forceinline__ void ldmatrix_x4(uint32_t& a0, uint32_t& a1, uint32_t& a2, uint32_t& a3,
                                            uint32_t addr) {
    asm volatile("ldmatrix.sync.aligned.m8n8.x4.shared.b16 {%0,%1,%2,%3}, [%4];"
                 : "=r"(a0), "=r"(a1), "=r"(a2), "=r"(a3) : "r"(addr));
}
__device__ __forceinline__ void ldmatrix_x2(uint32_t& b0, uint32_t& b1, uint32_t addr) {
    asm volatile("ldmatrix.sync.aligned.m8n8.x2.shared.b16 {%0,%1}, [%2];"
                 : "=r"(b0), "=r"(b1) : "r"(addr));
}
__device__ __forceinline__ void mma_bf16(float& c0, float& c1, float& c2, float& c3,
                                         uint32_t a0, uint32_t a1, uint32_t a2, uint32_t a3,
                                         uint32_t b0, uint32_t b1) {
    asm volatile("mma.sync.aligned.m16n8k16.row.col.f32.bf16.bf16.f32 "
                 "{%0,%1,%2,%3}, {%4,%5,%6,%7}, {%8,%9}, {%0,%1,%2,%3};"
                 : "+f"(c0), "+f"(c1), "+f"(c2), "+f"(c3)
                 : "r"(a0), "r"(a1), "r"(a2), "r"(a3), "r"(b0), "r"(b1));
}
__device__ __forceinline__ uint4 ldca_u4(const void* p) {
    uint4 v;
    asm volatile("ld.global.ca.v4.u32 {%0,%1,%2,%3}, [%4];"
                 : "=r"(v.x), "=r"(v.y), "=r"(v.z), "=r"(v.w) : "l"(p));
    return v;
}
__device__ __forceinline__ void cp_async16(uint32_t saddr, const void* gptr) {
    asm volatile("cp.async.cg.shared.global [%0], [%1], 16;" :: "r"(saddr), "l"(gptr));
}
#define CP_COMMIT() asm volatile("cp.async.commit_group;" ::: "memory")
#define CP_WAIT0()  asm volatile("cp.async.wait_group 0;" ::: "memory")

// ---------------- conversion kernels (unchanged) -----------------------------
__global__ void convert_x(const float* __restrict__ x,
                          const float* __restrict__ mask_f,
                          const float* __restrict__ mask_b)
{
    int idx = blockIdx.x * blockDim.x + threadIdx.x;
    if (idx >= Bn * Tn * (In / 4)) return;
    int bt = idx >> 7;
    int i4 = idx & 127;
    int b  = bt >> 8;
    float4 xv = *(const float4*)(x + (size_t)bt * In + i4 * 4);
#pragma unroll
    for (int dir = 0; dir < 2; dir++) {
        const float* mask = dir ? mask_b : mask_f;
#pragma unroll
        for (int g = 0; g < 4; g++) {
            float4 mv = *(const float4*)(mask + (size_t)b * (4 * In) + (size_t)g * In + i4 * 4);
            float v[4] = {xv.x * mv.x, xv.y * mv.y, xv.z * mv.z, xv.w * mv.w};
            __nv_bfloat16 h[4], l[4];
#pragma unroll
            for (int q = 0; q < 4; q++) {
                h[q] = __float2bfloat16(v[q]);
                l[q] = __float2bfloat16(v[q] - __bfloat162float(h[q]));
            }
            int z = dir * 4 + g;
            size_t o = (size_t)bt * In + i4 * 4;
            __nv_bfloat162 h0; h0.x = h[0]; h0.y = h[1];
            __nv_bfloat162 h1; h1.x = h[2]; h1.y = h[3];
            __nv_bfloat162 l0; l0.x = l[0]; l0.y = l[1];
            __nv_bfloat162 l1; l1.x = l[2]; l1.y = l[3];
            *(__nv_bfloat162*)&g_ahi[z][o]     = h0;
            *(__nv_bfloat162*)&g_ahi[z][o + 2] = h1;
            *(__nv_bfloat162*)&g_alo[z][o]     = l0;
            *(__nv_bfloat162*)&g_alo[z][o + 2] = l1;
        }
    }
}

__global__ void convert_w(const float* __restrict__ W_f,
                          const float* __restrict__ W_b)
{
    int idx = blockIdx.x * blockDim.x + threadIdx.x;
    if (idx >= 8 * In * Hn) return;
    int n    = idx % Hn;
    int rest = idx / Hn;
    int ks   = rest & 511;
    int z    = rest >> 9;
    int dir  = z >> 2, g = z & 3;
    const float* W = dir ? W_b : W_f;
    float v = W[(size_t)ks * FH + (size_t)g * Hn + n];
    __nv_bfloat16 h = __float2bfloat16(v);
    __nv_bfloat16 l = __float2bfloat16(v - __bfloat162float(h));
    g_wcat[z][(size_t)n * 1024 + ks]       = h;
    g_wcat[z][(size_t)n * 1024 + 512 + ks] = l;
}

// ---------------- proj GEMM via mma.sync + cp.async staging ------------------
#define PBK 32
#define PCHUNK 48
#define A_STRIDE 80
#define A_BYTES (128 * A_STRIDE)
#define B_BYTES (80  * A_STRIDE)

__global__ void __launch_bounds__(256)
proj_mma(const float* __restrict__ bias_f, const float* __restrict__ bias_b)
{
    __shared__ char sA[2][A_BYTES];
    __shared__ char sB[2][B_BYTES];

    const int z   = blockIdx.z;
    const int dir = z >> 2, g = z & 3;
    const int m0  = blockIdx.y * 128;
    const int n0  = blockIdx.x * 80;
    const __nv_bfloat16* __restrict__ ahi = g_ahi[z];
    const __nv_bfloat16* __restrict__ alo = g_alo[z];
    const __nv_bfloat16* __restrict__ wc  = g_wcat[z];
    const float* __restrict__ bias = dir ? bias_b : bias_f;

    const int tid  = threadIdx.x;
    const int wid  = tid >> 5;
    const int lane = tid & 31;
    const int wm   = wid & 3;
    const int wn   = wid >> 2;

    const uint32_t sAu = smem_u32(&sA[0][0]);
    const uint32_t sBu = smem_u32(&sB[0][0]);

    // staging decode (constant per thread)
    const int ar0 = (tid) >> 2,        ac0 = (tid) & 3;          // A elem 0
    const int ar1 = (tid + 256) >> 2,  ac1 = (tid + 256) & 3;    // A elem 1
    const int br0 = (tid) >> 2,        bc0 = (tid) & 3;          // B elem 0 (tid<320 always true)
    const int br1 = (tid + 256) >> 2,  bc1 = (tid + 256) & 3;    // B elem 1 (guard idx<320)
    const int bvalid1 = (tid + 256 < 320);

    uint32_t aAddr[2], bAddr[5];
#pragma unroll
    for (int mt = 0; mt < 2; mt++) {
        int row = wm * 32 + mt * 16 + (lane & 15);
        aAddr[mt] = sAu + row * A_STRIDE + ((lane >> 4) << 3) * 2;
    }
#pragma unroll
    for (int nt = 0; nt < 5; nt++) {
        int row = wn * 40 + nt * 8 + (lane & 7);
        bAddr[nt] = sBu + row * A_STRIDE + (((lane >> 3) & 1) << 3) * 2;
    }

    float acc[2][5][4];
#pragma unroll
    for (int mt = 0; mt < 2; mt++)
#pragma unroll
        for (int nt = 0; nt < 5; nt++)
#pragma unroll
            for (int q = 0; q < 4; q++) acc[mt][nt][q] = 0.f;

    // chunk 0 via cp.async
    cp_async16(sAu + ar0 * A_STRIDE + ac0 * 16, ahi + (size_t)(m0 + ar0) * In + ac0 * 8);
    cp_async16(sAu + ar1 * A_STRIDE + ac1 * 16, ahi + (size_t)(m0 + ar1) * In + ac1 * 8);
    cp_async16(sBu + br0 * A_STRIDE + bc0 * 16, wc + (size_t)(n0 + br0) * 1024 + bc0 * 8);
    if (bvalid1)
        cp_async16(sBu + br1 * A_STRIDE + bc1 * 16, wc + (size_t)(n0 + br1) * 1024 + bc1 * 8);
    CP_COMMIT();
    CP_WAIT0();
    __syncthreads();

    for (int c = 0; c < PCHUNK; c++) {
        const int buf = c & 1;
        if (c + 1 < PCHUNK) {
            const int cn = c + 1;
            int ka, kb;
            const __nv_bfloat16* asrc;
            if (cn < 16)      { asrc = ahi; ka = cn * PBK;        kb = cn * PBK; }
            else if (cn < 32) { asrc = ahi; ka = (cn - 16) * PBK; kb = cn * PBK; }
            else              { asrc = alo; ka = (cn - 32) * PBK; kb = (cn - 32) * PBK; }
            const uint32_t dA = sAu + (buf ^ 1) * A_BYTES;
            const uint32_t dB = sBu + (buf ^ 1) * B_BYTES;
            cp_async16(dA + ar0 * A_STRIDE + ac0 * 16, asrc + (size_t)(m0 + ar0) * In + ka + ac0 * 8);
            cp_async16(dA + ar1 * A_STRIDE + ac1 * 16, asrc + (size_t)(m0 + ar1) * In + ka + ac1 * 8);
            cp_async16(dB + br0 * A_STRIDE + bc0 * 16, wc + (size_t)(n0 + br0) * 1024 + kb + bc0 * 8);
            if (bvalid1)
                cp_async16(dB + br1 * A_STRIDE + bc1 * 16, wc + (size_t)(n0 + br1) * 1024 + kb + bc1 * 8);
            CP_COMMIT();
        }

        const uint32_t aOff = buf * A_BYTES;
        const uint32_t bOff = buf * B_BYTES;
#pragma unroll
        for (int kk = 0; kk < 2; kk++) {
            uint32_t a[2][4], b[5][2];
#pragma unroll
            for (int mt = 0; mt < 2; mt++)
                ldmatrix_x4(a[mt][0], a[mt][1], a[mt][2], a[mt][3],
                            aAddr[mt] + aOff + kk * 32);
#pragma unroll
            for (int nt = 0; nt < 5; nt++)
                ldmatrix_x2(b[nt][0], b[nt][1], bAddr[nt] + bOff + kk * 32);
#pragma unroll
            for (int mt = 0; mt < 2; mt++)
#pragma unroll
                for (int nt = 0; nt < 5; nt++)
                    mma_bf16(acc[mt][nt][0], acc[mt][nt][1], acc[mt][nt][2], acc[mt][nt][3],
                             a[mt][0], a[mt][1], a[mt][2], a[mt][3],
                             b[nt][0], b[nt][1]);
        }

        if (c + 1 < PCHUNK) {
            CP_WAIT0();
            __syncthreads();
        }
    }

    float* __restrict__ outp = g_proj[dir];
#pragma unroll
    for (int mt = 0; mt < 2; mt++) {
        int mrow0 = m0 + wm * 32 + mt * 16 + (lane >> 2);
#pragma unroll
        for (int nt = 0; nt < 5; nt++) {
            int n = n0 + wn * 40 + nt * 8 + ((lane & 3) << 1);
            float2 bv = *(const float2*)(bias + g * Hn + n);
            float2 v0 = make_float2(acc[mt][nt][0] + bv.x, acc[mt][nt][1] + bv.y);
            float2 v1 = make_float2(acc[mt][nt][2] + bv.x, acc[mt][nt][3] + bv.y);
            *(float2*)(outp + (size_t)mrow0 * FH + (size_t)g * Hn + n) = v0;
            *(float2*)(outp + (size_t)(mrow0 + 8) * FH + (size_t)g * Hn + n) = v1;
        }
    }
}

// ---------------- fast gate nonlinearities ----------------------------------
__device__ __forceinline__ float fast_sigmoid(float x) {
    return __fdividef(1.f, 1.f + __expf(-x));
}
__device__ __forceinline__ float fast_tanh(float x) {
    float e = __expf(2.f * x);
    return 1.f - __fdividef(2.f, e + 1.f);
}

// ---------------- persistent recurrence: fragment-direct HMMA ---------------
__global__ void __launch_bounds__(256, 1)
lstm_persistent(const float* __restrict__ U_f,
                const float* __restrict__ U_b,
                float* __restrict__ out)
{
    extern __shared__ char dsm[];
    char*  sU = dsm;
    float* zs = (float*)(dsm + ZS_OFF);

    const int bid = blockIdx.x;
    const int dir = bid / NCTA_DIR;
    const int j   = bid - dir * NCTA_DIR;
    const int h0  = j * NH;
    const int tid = threadIdx.x;
    const int lane = tid & 31;
    const int wid = tid >> 5;
    const int wm  = wid & 3;
    const int wn  = wid >> 2;
    const float* __restrict__ U = dir ? U_b : U_f;

    for (int idx = tid; idx < 96 * Hn; idx += 256) {
        int k  = idx / 96;
        int w2 = idx - k * 96;
        int w  = (w2 < 48) ? w2 : w2 - 48;
        int g  = w / NH;
        int c  = w - g * NH;
        int hh = h0 + c;
        float v = (hh < Hn) ? U[(size_t)k * FH + (size_t)g * Hn + hh] : 0.f;
        __nv_bfloat16 hi = __float2bfloat16(v);
        __nv_bfloat16 res = (w2 < 48) ? hi : __float2bfloat16(v - __bfloat162float(hi));
        *(__nv_bfloat16*)(sU + (size_t)w2 * USTR_B + k * 2) = res;
    }

    int gb[3], gc2[3], gvalid[3], hoff[3];
#pragma unroll
    for (int it = 0; it < 3; it++) {
        int idx = it * 256 + tid;
        gb[it]  = idx / NH;
        gc2[it] = idx - gb[it] * NH;
        int hh  = h0 + gc2[it];
        gvalid[it] = (hh < Hn) ? 1 : 0;
        int b = gb[it];
        int k16 = hh >> 4, kin = hh & 15;
        int bg = b >> 4, rr = b & 15;
        hoff[it] = k16 * 1024 + bg * 256 + (rr & 7) * 32 + ((kin & 7) >> 1) * 8
                 + (kin >> 3) * 4 + ((rr >> 3) & 1) * 2 + (kin & 1);
        if (!gvalid[it]) hoff[it] = 0;
    }

    const int aoff = wm * 256 + (lane >> 2) * 32 + (lane & 3) * 8;

    const uint32_t sUu = smem_u32(sU);
    uint32_t bAddr[3];
    {
        int l8 = lane & 7;
        int kh = (lane >> 3) & 1;
        int pt = lane >> 4;
#pragma unroll
        for (int nt = 0; nt < 3; nt++)
            bAddr[nt] = sUu + (wn * 24 + nt * 8 + l8 + pt * 48) * USTR_B + (kh << 4);
    }

    __syncthreads();

    unsigned sense = 0;
    const float* __restrict__ proj = g_proj[dir];

    float c_reg[3] = {0.f, 0.f, 0.f};
    float pp[3][4];
    {
        const int te = dir ? (Tn - 1) : 0;
#pragma unroll
        for (int it = 0; it < 3; it++) {
            pp[it][0] = pp[it][1] = pp[it][2] = pp[it][3] = 0.f;
            if (gvalid[it]) {
                size_t pbase = ((size_t)gb[it] * Tn + te) * FH + (h0 + gc2[it]);
                pp[it][0] = proj[pbase];
                pp[it][1] = proj[pbase + Hn];
                pp[it][2] = proj[pbase + 2 * Hn];
                pp[it][3] = proj[pbase + 3 * Hn];
            }
        }
    }

    for (int t = 0; t < Tn; t++) {
        const int cur = t & 1;
        const int nxt = cur ^ 1;
        const __nv_bfloat16* __restrict__ fhi = g_hfrag[dir][cur][0];
        const __nv_bfloat16* __restrict__ flo = g_hfrag[dir][cur][1];

        float acc[3][4];
#pragma unroll
        for (int nt = 0; nt < 3; nt++)
#pragma unroll
            for (int q = 0; q < 4; q++) acc[nt][q] = 0.f;

        // register-double-buffered fragment GEMM (L1-cached loads: wn pair hits)
        uint4 Ah[2][5], Al[2][5];
#pragma unroll
        for (int j2 = 0; j2 < 5; j2++) {
            Ah[0][j2] = ldca_u4(fhi + j2 * 1024 + aoff);
            Al[0][j2] = ldca_u4(flo + j2 * 1024 + aoff);
        }
#pragma unroll
        for (int c = 0; c < 10; c++) {
            const int cb = c & 1, nb = cb ^ 1;
            if (c < 9) {
#pragma unroll
                for (int j2 = 0; j2 < 5; j2++) {
                    int kb = (c + 1) * 5 + j2;
                    Ah[nb][j2] = ldca_u4(fhi + kb * 1024 + aoff);
                    Al[nb][j2] = ldca_u4(flo + kb * 1024 + aoff);
                }
            }
#pragma unroll
            for (int j2 = 0; j2 < 5; j2++) {
                const int kglob = c * 5 + j2;
                uint32_t b4[3][4];
#pragma unroll
                for (int nt = 0; nt < 3; nt++)
                    ldmatrix_x4(b4[nt][0], b4[nt][1], b4[nt][2], b4[nt][3],
                                bAddr[nt] + kglob * 32);
#pragma unroll
                for (int nt = 0; nt < 3; nt++) {
                    mma_bf16(acc[nt][0], acc[nt][1], acc[nt][2], acc[nt][3],
                             Ah[cb][j2].x, Ah[cb][j2].y, Ah[cb][j2].z, Ah[cb][j2].w,
                             b4[nt][0], b4[nt][1]);
                    mma_bf16(acc[nt][0], acc[nt][1], acc[nt][2], acc[nt][3],
                             Ah[cb][j2].x, Ah[cb][j2].y, Ah[cb][j2].z, Ah[cb][j2].w,
                             b4[nt][2], b4[nt][3]);
                    mma_bf16(acc[nt][0], acc[nt][1], acc[nt][2], acc[nt][3],
                             Al[cb][j2].x, Al[cb][j2].y, Al[cb][j2].z, Al[cb][j2].w,
                             b4[nt][0], b4[nt][1]);
                }
            }
        }

        {
            int row0 = wm * 16 + (lane >> 2);
            int colb = wn * 24 + ((lane & 3) << 1);
#pragma unroll
            for (int nt = 0; nt < 3; nt++) {
                int col = colb + nt * 8;
                *(float2*)&zs[row0 * ZSTR + col]       = make_float2(acc[nt][0], acc[nt][1]);
                *(float2*)&zs[(row0 + 8) * ZSTR + col] = make_float2(acc[nt][2], acc[nt][3]);
            }
        }
        __syncthreads();

        __nv_bfloat16* __restrict__ whi = g_hfrag[dir][nxt][0];
        __nv_bfloat16* __restrict__ wlo = g_hfrag[dir][nxt][1];
#pragma unroll
        for (int it = 0; it < 3; it++) {
            if (gvalid[it]) {
                int b  = gb[it];
                int c  = gc2[it];
                int hh = h0 + c;
                float zi = zs[b * ZSTR + 0 * NH + c] + pp[it][0];
                float zf = zs[b * ZSTR + 1 * NH + c] + pp[it][1];
                float zg = zs[b * ZSTR + 2 * NH + c] + pp[it][2];
                float zo = zs[b * ZSTR + 3 * NH + c] + pp[it][3];

                float ig = fast_sigmoid(zi);
                float fg = fast_sigmoid(zf);
                float gg = fast_tanh(zg);
                float og = fast_sigmoid(zo);

                float cv = fg * c_reg[it] + ig * gg;
                float hv = og * fast_tanh(cv);
                c_reg[it] = cv;

                __nv_bfloat16 hvh = __float2bfloat16(hv);
                __nv_bfloat16 hvl = __float2bfloat16(hv - __bfloat162float(hvh));
                whi[hoff[it]] = hvh;
                wlo[hoff[it]] = hvl;

                out[((size_t)b * Tn + t) * (2 * Hn) + (size_t)dir * Hn + hh] = hv;
                if (t == Tn - 1) {
                    size_t hcat0 = (size_t)Bn * Tn * (2 * Hn);
                    size_t ccat0 = hcat0 + (size_t)Bn * (2 * Hn);
                    out[hcat0 + (size_t)b * (2 * Hn) + (size_t)dir * Hn + hh] = hv;
                    out[ccat0 + (size_t)b * (2 * Hn) + (size_t)dir * Hn + hh] = cv;
                }
            }
        }

        // release h writes + flush L1 (coherence for next step's ld.ca),
        // prefetch next-step proj behind the barrier wait
        __threadfence();
        __syncthreads();
        if (t + 1 < Tn) {
            const int te = dir ? (Tn - 2 - t) : (t + 1);
#pragma unroll
            for (int it = 0; it < 3; it++) {
                if (gvalid[it]) {
                    size_t pbase = ((size_t)gb[it] * Tn + te) * FH + (h0 + gc2[it]);
                    pp[it][0] = proj[pbase];
                    pp[it][1] = proj[pbase + Hn];
                    pp[it][2] = proj[pbase + 2 * Hn];
                    pp[it][3] = proj[pbase + 3 * Hn];
                }
            }
        }
        if (tid == 0) {
            unsigned ns = sense ^ 1u;
            unsigned arrived = atomicAdd((unsigned*)&g_bar_count[dir], 1u);
            if (arrived == NCTA_DIR - 1) {
                g_bar_count[dir] = 0u;
                __threadfence();
                g_bar_sense[dir] = ns;
            } else {
                while (g_bar_sense[dir] != ns) __nanosleep(32);
            }
            __threadfence();
        }
        __syncthreads();
        sense ^= 1u;
    }
}

// ---------------- launch ------------------------------------------------------
extern "C" void kernel_launch(void* const* d_in, const int* in_sizes, int n_in,
                              void* d_out, int out_size)
{
    const float* x      = (const float*)d_in[0];
    const float* mask_f = (const float*)d_in[1];
    const float* mask_b = (const float*)d_in[2];
    const float* W_f    = (const float*)d_in[3];
    const float* U_f    = (const float*)d_in[4];
    const float* b_f    = (const float*)d_in[5];
    const float* W_b    = (const float*)d_in[6];
    const float* U_b    = (const float*)d_in[7];
    const float* b_b    = (const float*)d_in[8];
    float* out = (float*)d_out;

    static int configured = 0;
    if (!configured) {
        cudaFuncSetAttribute(lstm_persistent,
                             cudaFuncAttributeMaxDynamicSharedMemorySize, LSTM_SMEM);
        configured = 1;
    }

    init_state<<<(Bn * Hn + 255) / 256, 256>>>();
    convert_x<<<(Bn * Tn * (In / 4) + 255) / 256, 256>>>(x, mask_f, mask_b);
    convert_w<<<(8 * In * Hn + 255) / 256, 256>>>(W_f, W_b);
    proj_mma<<<dim3(10, 128, 8), 256>>>(b_f, b_b);
    lstm_persistent<<<2 * NCTA_DIR, 256, LSTM_SMEM>>>(U_f, U_b, out);
}

// round 12
// speedup vs baseline: 5.0418x; 1.0479x over previous
#include <cuda_runtime.h>
#include <cuda_bf16.h>
#include <math.h>
#include <stdint.h>

#define Bn 64
#define Tn 256
#define In 512
#define Hn 800
#define FH 3200   // 4*H

#define NCTA_DIR 67
#define NH 12
#define WCOLS 48

// SMEM geometry for persistent kernel (U slice + 2x z-partials)
#define USTR_B 1616            // bytes per U row (808 bf16), conflict-free
#define U_BYTES (96 * USTR_B)  // 155136
#define ZS_OFF U_BYTES
#define ZSTR 52
#define ZBUF (64 * ZSTR)       // floats per partial buffer
#define LSTM_SMEM (ZS_OFF + 2 * ZBUF * 4)  // 181760

// ---------------- device globals ------------------------------------------
__device__ float g_proj[2][Bn * Tn * FH];
__device__ __nv_bfloat16 g_ahi[8][Bn * Tn * In];
__device__ __nv_bfloat16 g_alo[8][Bn * Tn * In];
__device__ __nv_bfloat16 g_wcat[8][Hn * 1024];
// h in MMA-fragment layout: [dir][buf][hi/lo][k16(50)][bg(4)][r(8)][m(4)][8 bf16]
__device__ __nv_bfloat16 g_hfrag[2][2][2][51200];
__device__ volatile unsigned g_bar_count[2];
__device__ volatile unsigned g_bar_sense[2];

__global__ void init_state() {
    int i = blockIdx.x * blockDim.x + threadIdx.x;
    if (i < Bn * Hn) {
        __nv_bfloat16 z = __float2bfloat16(0.f);
#pragma unroll
        for (int d = 0; d < 2; d++)
#pragma unroll
            for (int bu = 0; bu < 2; bu++)
#pragma unroll
                for (int p = 0; p < 2; p++)
                    g_hfrag[d][bu][p][i] = z;
    }
    if (i < 2) { g_bar_count[i] = 0u; g_bar_sense[i] = 0u; }
}

// ---------------- helpers ---------------------------------------------------
__device__ __forceinline__ uint32_t smem_u32(const void* p) {
    uint32_t a;
    asm("{ .reg .u64 t; cvta.to.shared.u64 t, %1; cvt.u32.u64 %0, t; }" : "=r"(a) : "l"(p));
    return a;
}
__device__ __forceinline__ void ldmatrix_x4(uint32_t& a0, uint32_t& a1, uint32_t& a2, uint32_t& a3,
                                            uint32_t addr) {
    asm volatile("ldmatrix.sync.aligned.m8n8.x4.shared.b16 {%0,%1,%2,%3}, [%4];"
                 : "=r"(a0), "=r"(a1), "=r"(a2), "=r"(a3) : "r"(addr));
}
__device__ __forceinline__ void ldmatrix_x2(uint32_t& b0, uint32_t& b1, uint32_t addr) {
    asm volatile("ldmatrix.sync.aligned.m8n8.x2.shared.b16 {%0,%1}, [%2];"
                 : "=r"(b0), "=r"(b1) : "r"(addr));
}
__device__ __forceinline__ void mma_bf16(float& c0, float& c1, float& c2, float& c3,
                                         uint32_t a0, uint32_t a1, uint32_t a2, uint32_t a3,
                                         uint32_t b0, uint32_t b1) {
    asm volatile("mma.sync.aligned.m16n8k16.row.col.f32.bf16.bf16.f32 "
                 "{%0,%1,%2,%3}, {%4,%5,%6,%7}, {%8,%9}, {%0,%1,%2,%3};"
                 : "+f"(c0), "+f"(c1), "+f"(c2), "+f"(c3)
                 : "r"(a0), "r"(a1), "r"(a2), "r"(a3), "r"(b0), "r"(b1));
}
__device__ __forceinline__ uint4 ldca_u4(const void* p) {
    uint4 v;
    asm volatile("ld.global.ca.v4.u32 {%0,%1,%2,%3}, [%4];"
                 : "=r"(v.x), "=r"(v.y), "=r"(v.z), "=r"(v.w) : "l"(p));
    return v;
}
__device__ __forceinline__ void cp_async16(uint32_t saddr, const void* gptr) {
    asm volatile("cp.async.cg.shared.global [%0], [%1], 16;" :: "r"(saddr), "l"(gptr));
}
#define CP_COMMIT() asm volatile("cp.async.commit_group;" ::: "memory")
#define CP_WAIT0()  asm volatile("cp.async.wait_group 0;" ::: "memory")

// ---------------- conversion kernels (unchanged) -----------------------------
__global__ void convert_x(const float* __restrict__ x,
                          const float* __restrict__ mask_f,
                          const float* __restrict__ mask_b)
{
    int idx = blockIdx.x * blockDim.x + threadIdx.x;
    if (idx >= Bn * Tn * (In / 4)) return;
    int bt = idx >> 7;
    int i4 = idx & 127;
    int b  = bt >> 8;
    float4 xv = *(const float4*)(x + (size_t)bt * In + i4 * 4);
#pragma unroll
    for (int dir = 0; dir < 2; dir++) {
        const float* mask = dir ? mask_b : mask_f;
#pragma unroll
        for (int g = 0; g < 4; g++) {
            float4 mv = *(const float4*)(mask + (size_t)b * (4 * In) + (size_t)g * In + i4 * 4);
            float v[4] = {xv.x * mv.x, xv.y * mv.y, xv.z * mv.z, xv.w * mv.w};
            __nv_bfloat16 h[4], l[4];
#pragma unroll
            for (int q = 0; q < 4; q++) {
                h[q] = __float2bfloat16(v[q]);
                l[q] = __float2bfloat16(v[q] - __bfloat162float(h[q]));
            }
            int z = dir * 4 + g;
            size_t o = (size_t)bt * In + i4 * 4;
            __nv_bfloat162 h0; h0.x = h[0]; h0.y = h[1];
            __nv_bfloat162 h1; h1.x = h[2]; h1.y = h[3];
            __nv_bfloat162 l0; l0.x = l[0]; l0.y = l[1];
            __nv_bfloat162 l1; l1.x = l[2]; l1.y = l[3];
            *(__nv_bfloat162*)&g_ahi[z][o]     = h0;
            *(__nv_bfloat162*)&g_ahi[z][o + 2] = h1;
            *(__nv_bfloat162*)&g_alo[z][o]     = l0;
            *(__nv_bfloat162*)&g_alo[z][o + 2] = l1;
        }
    }
}

__global__ void convert_w(const float* __restrict__ W_f,
                          const float* __restrict__ W_b)
{
    int idx = blockIdx.x * blockDim.x + threadIdx.x;
    if (idx >= 8 * In * Hn) return;
    int n    = idx % Hn;
    int rest = idx / Hn;
    int ks   = rest & 511;
    int z    = rest >> 9;
    int dir  = z >> 2, g = z & 3;
    const float* W = dir ? W_b : W_f;
    float v = W[(size_t)ks * FH + (size_t)g * Hn + n];
    __nv_bfloat16 h = __float2bfloat16(v);
    __nv_bfloat16 l = __float2bfloat16(v - __bfloat162float(h));
    g_wcat[z][(size_t)n * 1024 + ks]       = h;
    g_wcat[z][(size_t)n * 1024 + 512 + ks] = l;
}

// ---------------- proj GEMM via mma.sync + cp.async (unchanged) --------------
#define PBK 32
#define PCHUNK 48
#define A_STRIDE 80
#define A_BYTES (128 * A_STRIDE)
#define B_BYTES (80  * A_STRIDE)

__global__ void __launch_bounds__(256)
proj_mma(const float* __restrict__ bias_f, const float* __restrict__ bias_b)
{
    __shared__ char sA[2][A_BYTES];
    __shared__ char sB[2][B_BYTES];

    const int z   = blockIdx.z;
    const int dir = z >> 2, g = z & 3;
    const int m0  = blockIdx.y * 128;
    const int n0  = blockIdx.x * 80;
    const __nv_bfloat16* __restrict__ ahi = g_ahi[z];
    const __nv_bfloat16* __restrict__ alo = g_alo[z];
    const __nv_bfloat16* __restrict__ wc  = g_wcat[z];
    const float* __restrict__ bias = dir ? bias_b : bias_f;

    const int tid  = threadIdx.x;
    const int wid  = tid >> 5;
    const int lane = tid & 31;
    const int wm   = wid & 3;
    const int wn   = wid >> 2;

    const uint32_t sAu = smem_u32(&sA[0][0]);
    const uint32_t sBu = smem_u32(&sB[0][0]);

    const int ar0 = (tid) >> 2,        ac0 = (tid) & 3;
    const int ar1 = (tid + 256) >> 2,  ac1 = (tid + 256) & 3;
    const int br0 = (tid) >> 2,        bc0 = (tid) & 3;
    const int br1 = (tid + 256) >> 2,  bc1 = (tid + 256) & 3;
    const int bvalid1 = (tid + 256 < 320);

    uint32_t aAddr[2], bAddr[5];
#pragma unroll
    for (int mt = 0; mt < 2; mt++) {
        int row = wm * 32 + mt * 16 + (lane & 15);
        aAddr[mt] = sAu + row * A_STRIDE + ((lane >> 4) << 3) * 2;
    }
#pragma unroll
    for (int nt = 0; nt < 5; nt++) {
        int row = wn * 40 + nt * 8 + (lane & 7);
        bAddr[nt] = sBu + row * A_STRIDE + (((lane >> 3) & 1) << 3) * 2;
    }

    float acc[2][5][4];
#pragma unroll
    for (int mt = 0; mt < 2; mt++)
#pragma unroll
        for (int nt = 0; nt < 5; nt++)
#pragma unroll
            for (int q = 0; q < 4; q++) acc[mt][nt][q] = 0.f;

    cp_async16(sAu + ar0 * A_STRIDE + ac0 * 16, ahi + (size_t)(m0 + ar0) * In + ac0 * 8);
    cp_async16(sAu + ar1 * A_STRIDE + ac1 * 16, ahi + (size_t)(m0 + ar1) * In + ac1 * 8);
    cp_async16(sBu + br0 * A_STRIDE + bc0 * 16, wc + (size_t)(n0 + br0) * 1024 + bc0 * 8);
    if (bvalid1)
        cp_async16(sBu + br1 * A_STRIDE + bc1 * 16, wc + (size_t)(n0 + br1) * 1024 + bc1 * 8);
    CP_COMMIT();
    CP_WAIT0();
    __syncthreads();

    for (int c = 0; c < PCHUNK; c++) {
        const int buf = c & 1;
        if (c + 1 < PCHUNK) {
            const int cn = c + 1;
            int ka, kb;
            const __nv_bfloat16* asrc;
            if (cn < 16)      { asrc = ahi; ka = cn * PBK;        kb = cn * PBK; }
            else if (cn < 32) { asrc = ahi; ka = (cn - 16) * PBK; kb = cn * PBK; }
            else              { asrc = alo; ka = (cn - 32) * PBK; kb = (cn - 32) * PBK; }
            const uint32_t dA = sAu + (buf ^ 1) * A_BYTES;
            const uint32_t dB = sBu + (buf ^ 1) * B_BYTES;
            cp_async16(dA + ar0 * A_STRIDE + ac0 * 16, asrc + (size_t)(m0 + ar0) * In + ka + ac0 * 8);
            cp_async16(dA + ar1 * A_STRIDE + ac1 * 16, asrc + (size_t)(m0 + ar1) * In + ka + ac1 * 8);
            cp_async16(dB + br0 * A_STRIDE + bc0 * 16, wc + (size_t)(n0 + br0) * 1024 + kb + bc0 * 8);
            if (bvalid1)
                cp_async16(dB + br1 * A_STRIDE + bc1 * 16, wc + (size_t)(n0 + br1) * 1024 + kb + bc1 * 8);
            CP_COMMIT();
        }

        const uint32_t aOff = buf * A_BYTES;
        const uint32_t bOff = buf * B_BYTES;
#pragma unroll
        for (int kk = 0; kk < 2; kk++) {
            uint32_t a[2][4], b[5][2];
#pragma unroll
            for (int mt = 0; mt < 2; mt++)
                ldmatrix_x4(a[mt][0], a[mt][1], a[mt][2], a[mt][3],
                            aAddr[mt] + aOff + kk * 32);
#pragma unroll
            for (int nt = 0; nt < 5; nt++)
                ldmatrix_x2(b[nt][0], b[nt][1], bAddr[nt] + bOff + kk * 32);
#pragma unroll
            for (int mt = 0; mt < 2; mt++)
#pragma unroll
                for (int nt = 0; nt < 5; nt++)
                    mma_bf16(acc[mt][nt][0], acc[mt][nt][1], acc[mt][nt][2], acc[mt][nt][3],
                             a[mt][0], a[mt][1], a[mt][2], a[mt][3],
                             b[nt][0], b[nt][1]);
        }

        if (c + 1 < PCHUNK) {
            CP_WAIT0();
            __syncthreads();
        }
    }

    float* __restrict__ outp = g_proj[dir];
#pragma unroll
    for (int mt = 0; mt < 2; mt++) {
        int mrow0 = m0 + wm * 32 + mt * 16 + (lane >> 2);
#pragma unroll
        for (int nt = 0; nt < 5; nt++) {
            int n = n0 + wn * 40 + nt * 8 + ((lane & 3) << 1);
            float2 bv = *(const float2*)(bias + g * Hn + n);
            float2 v0 = make_float2(acc[mt][nt][0] + bv.x, acc[mt][nt][1] + bv.y);
            float2 v1 = make_float2(acc[mt][nt][2] + bv.x, acc[mt][nt][3] + bv.y);
            *(float2*)(outp + (size_t)mrow0 * FH + (size_t)g * Hn + n) = v0;
            *(float2*)(outp + (size_t)(mrow0 + 8) * FH + (size_t)g * Hn + n) = v1;
        }
    }
}

// ---------------- fast gate nonlinearities ----------------------------------
__device__ __forceinline__ float fast_sigmoid(float x) {
    return __fdividef(1.f, 1.f + __expf(-x));
}
__device__ __forceinline__ float fast_tanh(float x) {
    float e = __expf(2.f * x);
    return 1.f - __fdividef(2.f, e + 1.f);
}

// ---------------- persistent recurrence: fragment-direct HMMA, K-split -------
// wn=0 computes k16 blocks 0-24, wn=1 computes 25-49, each over ALL 48 z cols;
// partials reduced through two SMEM z buffers. Halves per-CTA A traffic.
__global__ void __launch_bounds__(256, 1)
lstm_persistent(const float* __restrict__ U_f,
                const float* __restrict__ U_b,
                float* __restrict__ out)
{
    extern __shared__ char dsm[];
    char*  sU = dsm;
    float* zs = (float*)(dsm + ZS_OFF);   // [2][64][ZSTR]

    const int bid = blockIdx.x;
    const int dir = bid / NCTA_DIR;
    const int j   = bid - dir * NCTA_DIR;
    const int h0  = j * NH;
    const int tid = threadIdx.x;
    const int lane = tid & 31;
    const int wid = tid >> 5;
    const int wm  = wid & 3;            // 4 M tiles of 16 batches
    const int wn  = wid >> 2;           // K-split half (0: k 0-24, 1: k 25-49)
    const float* __restrict__ U = dir ? U_b : U_f;

    for (int idx = tid; idx < 96 * Hn; idx += 256) {
        int k  = idx / 96;
        int w2 = idx - k * 96;
        int w  = (w2 < 48) ? w2 : w2 - 48;
        int g  = w / NH;
        int c  = w - g * NH;
        int hh = h0 + c;
        float v = (hh < Hn) ? U[(size_t)k * FH + (size_t)g * Hn + hh] : 0.f;
        __nv_bfloat16 hi = __float2bfloat16(v);
        __nv_bfloat16 res = (w2 < 48) ? hi : __float2bfloat16(v - __bfloat162float(hi));
        *(__nv_bfloat16*)(sU + (size_t)w2 * USTR_B + k * 2) = res;
    }

    int gb[3], gc2[3], gvalid[3], hoff[3];
#pragma unroll
    for (int it = 0; it < 3; it++) {
        int idx = it * 256 + tid;
        gb[it]  = idx / NH;
        gc2[it] = idx - gb[it] * NH;
        int hh  = h0 + gc2[it];
        gvalid[it] = (hh < Hn) ? 1 : 0;
        int b = gb[it];
        int k16 = hh >> 4, kin = hh & 15;
        int bg = b >> 4, rr = b & 15;
        hoff[it] = k16 * 1024 + bg * 256 + (rr & 7) * 32 + ((kin & 7) >> 1) * 8
                 + (kin >> 3) * 4 + ((rr >> 3) & 1) * 2 + (kin & 1);
        if (!gvalid[it]) hoff[it] = 0;
    }

    // per-lane A fragment offset; k origin for this warp's half
    const int aoff = wm * 256 + (lane >> 2) * 32 + (lane & 3) * 8;
    const int kbase16 = wn * 25;                     // first k16 block
    const int abase = kbase16 * 1024 + aoff;

    // B ldmatrix addresses: all 6 n-tiles (48 cols); x4 folds hi/lo via pt
    const uint32_t sUu = smem_u32(sU);
    uint32_t bAddr[6];
    {
        int l8 = lane & 7;
        int kh = (lane >> 3) & 1;
        int pt = lane >> 4;
#pragma unroll
        for (int nt = 0; nt < 6; nt++)
            bAddr[nt] = sUu + (nt * 8 + l8 + pt * 48) * USTR_B + (kh << 4) + kbase16 * 32;
    }

    __syncthreads();

    unsigned sense = 0;
    const float* __restrict__ proj = g_proj[dir];

    float c_reg[3] = {0.f, 0.f, 0.f};
    float pp[3][4];
    {
        const int te = dir ? (Tn - 1) : 0;
#pragma unroll
        for (int it = 0; it < 3; it++) {
            pp[it][0] = pp[it][1] = pp[it][2] = pp[it][3] = 0.f;
            if (gvalid[it]) {
                size_t pbase = ((size_t)gb[it] * Tn + te) * FH + (h0 + gc2[it]);
                pp[it][0] = proj[pbase];
                pp[it][1] = proj[pbase + Hn];
                pp[it][2] = proj[pbase + 2 * Hn];
                pp[it][3] = proj[pbase + 3 * Hn];
            }
        }
    }

    for (int t = 0; t < Tn; t++) {
        const int cur = t & 1;
        const int nxt = cur ^ 1;
        const __nv_bfloat16* __restrict__ fhi = g_hfrag[dir][cur][0];
        const __nv_bfloat16* __restrict__ flo = g_hfrag[dir][cur][1];

        float acc[6][4];
#pragma unroll
        for (int nt = 0; nt < 6; nt++)
#pragma unroll
            for (int q = 0; q < 4; q++) acc[nt][q] = 0.f;

        // 25 k16 blocks = 5 chunks of 5, register double-buffered
        uint4 Ah[2][5], Al[2][5];
#pragma unroll
        for (int j2 = 0; j2 < 5; j2++) {
            Ah[0][j2] = ldca_u4(fhi + abase + j2 * 1024);
            Al[0][j2] = ldca_u4(flo + abase + j2 * 1024);
        }
#pragma unroll
        for (int c = 0; c < 5; c++) {
            const int cb = c & 1, nb = cb ^ 1;
            if (c < 4) {
#pragma unroll
                for (int j2 = 0; j2 < 5; j2++) {
                    int kb = (c + 1) * 5 + j2;
                    Ah[nb][j2] = ldca_u4(fhi + abase + kb * 1024);
                    Al[nb][j2] = ldca_u4(flo + abase + kb * 1024);
                }
            }
#pragma unroll
            for (int j2 = 0; j2 < 5; j2++) {
                const int klocal = c * 5 + j2;
                uint32_t b4[6][4];
#pragma unroll
                for (int nt = 0; nt < 6; nt++)
                    ldmatrix_x4(b4[nt][0], b4[nt][1], b4[nt][2], b4[nt][3],
                                bAddr[nt] + klocal * 32);
#pragma unroll
                for (int nt = 0; nt < 6; nt++) {
                    mma_bf16(acc[nt][0], acc[nt][1], acc[nt][2], acc[nt][3],
                             Ah[cb][j2].x, Ah[cb][j2].y, Ah[cb][j2].z, Ah[cb][j2].w,
                             b4[nt][0], b4[nt][1]);
                    mma_bf16(acc[nt][0], acc[nt][1], acc[nt][2], acc[nt][3],
                             Ah[cb][j2].x, Ah[cb][j2].y, Ah[cb][j2].z, Ah[cb][j2].w,
                             b4[nt][2], b4[nt][3]);
                    mma_bf16(acc[nt][0], acc[nt][1], acc[nt][2], acc[nt][3],
                             Al[cb][j2].x, Al[cb][j2].y, Al[cb][j2].z, Al[cb][j2].w,
                             b4[nt][0], b4[nt][1]);
                }
            }
        }

        // write z partials: wn half -> its own buffer
        {
            float* zw = zs + wn * ZBUF;
            int row0 = wm * 16 + (lane >> 2);
            int colb = (lane & 3) << 1;
#pragma unroll
            for (int nt = 0; nt < 6; nt++) {
                int col = colb + nt * 8;
                *(float2*)&zw[row0 * ZSTR + col]       = make_float2(acc[nt][0], acc[nt][1]);
                *(float2*)&zw[(row0 + 8) * ZSTR + col] = make_float2(acc[nt][2], acc[nt][3]);
            }
        }
        __syncthreads();

        __nv_bfloat16* __restrict__ whi = g_hfrag[dir][nxt][0];
        __nv_bfloat16* __restrict__ wlo = g_hfrag[dir][nxt][1];
#pragma unroll
        for (int it = 0; it < 3; it++) {
            if (gvalid[it]) {
                int b  = gb[it];
                int c  = gc2[it];
                int hh = h0 + c;
                float zi = zs[b * ZSTR + 0 * NH + c] + zs[ZBUF + b * ZSTR + 0 * NH + c] + pp[it][0];
                float zf = zs[b * ZSTR + 1 * NH + c] + zs[ZBUF + b * ZSTR + 1 * NH + c] + pp[it][1];
                float zg = zs[b * ZSTR + 2 * NH + c] + zs[ZBUF + b * ZSTR + 2 * NH + c] + pp[it][2];
                float zo = zs[b * ZSTR + 3 * NH + c] + zs[ZBUF + b * ZSTR + 3 * NH + c] + pp[it][3];

                float ig = fast_sigmoid(zi);
                float fg = fast_sigmoid(zf);
                float gg = fast_tanh(zg);
                float og = fast_sigmoid(zo);

                float cv = fg * c_reg[it] + ig * gg;
                float hv = og * fast_tanh(cv);
                c_reg[it] = cv;

                __nv_bfloat16 hvh = __float2bfloat16(hv);
                __nv_bfloat16 hvl = __float2bfloat16(hv - __bfloat162float(hvh));
                whi[hoff[it]] = hvh;
                wlo[hoff[it]] = hvl;

                out[((size_t)b * Tn + t) * (2 * Hn) + (size_t)dir * Hn + hh] = hv;
                if (t == Tn - 1) {
                    size_t hcat0 = (size_t)Bn * Tn * (2 * Hn);
                    size_t ccat0 = hcat0 + (size_t)Bn * (2 * Hn);
                    out[hcat0 + (size_t)b * (2 * Hn) + (size_t)dir * Hn + hh] = hv;
                    out[ccat0 + (size_t)b * (2 * Hn) + (size_t)dir * Hn + hh] = cv;
                }
            }
        }

        // release h writes + L1 flush; prefetch next-step proj behind barrier
        __threadfence();
        __syncthreads();
        if (t + 1 < Tn) {
            const int te = dir ? (Tn - 2 - t) : (t + 1);
#pragma unroll
            for (int it = 0; it < 3; it++) {
                if (gvalid[it]) {
                    size_t pbase = ((size_t)gb[it] * Tn + te) * FH + (h0 + gc2[it]);
                    pp[it][0] = proj[pbase];
                    pp[it][1] = proj[pbase + Hn];
                    pp[it][2] = proj[pbase + 2 * Hn];
                    pp[it][3] = proj[pbase + 3 * Hn];
                }
            }
        }
        if (tid == 0) {
            unsigned ns = sense ^ 1u;
            unsigned arrived = atomicAdd((unsigned*)&g_bar_count[dir], 1u);
            if (arrived == NCTA_DIR - 1) {
                g_bar_count[dir] = 0u;
                __threadfence();
                g_bar_sense[dir] = ns;
            } else {
                while (g_bar_sense[dir] != ns) __nanosleep(32);
            }
            __threadfence();
        }
        __syncthreads();
        sense ^= 1u;
    }
}

// ---------------- launch ------------------------------------------------------
extern "C" void kernel_launch(void* const* d_in, const int* in_sizes, int n_in,
                              void* d_out, int out_size)
{
    const float* x      = (const float*)d_in[0];
    const float* mask_f = (const float*)d_in[1];
    const float* mask_b = (const float*)d_in[2];
    const float* W_f    = (const float*)d_in[3];
    const float* U_f    = (const float*)d_in[4];
    const float* b_f    = (const float*)d_in[5];
    const float* W_b    = (const float*)d_in[6];
    const float* U_b    = (const float*)d_in[7];
    const float* b_b    = (const float*)d_in[8];
    float* out = (float*)d_out;

    static int configured = 0;
    if (!configured) {
        cudaFuncSetAttribute(lstm_persistent,
                             cudaFuncAttributeMaxDynamicSharedMemorySize, LSTM_SMEM);
        configured = 1;
    }

    init_state<<<(Bn * Hn + 255) / 256, 256>>>();
    convert_x<<<(Bn * Tn * (In / 4) + 255) / 256, 256>>>(x, mask_f, mask_b);
    convert_w<<<(8 * In * Hn + 255) / 256, 256>>>(W_f, W_b);
    proj_mma<<<dim3(10, 128, 8), 256>>>(b_f, b_b);
    lstm_persistent<<<2 * NCTA_DIR, 256, LSTM_SMEM>>>(U_f, U_b, out);
}

// round 13
// speedup vs baseline: 5.5314x; 1.0971x over previous
#include <cuda_runtime.h>
#include <cuda_bf16.h>
#include <math.h>
#include <stdint.h>

#define Bn 64
#define Tn 256
#define In 512
#define Hn 800
#define FH 3200   // 4*H

#define NCTA_DIR 67
#define NH 12
#define WCOLS 48

// SMEM geometry for persistent kernel (U slice + 2x z-partials)
#define USTR_B 1616            // bytes per U row (808 bf16), conflict-free
#define U_BYTES (96 * USTR_B)  // 155136
#define ZS_OFF U_BYTES
#define ZSTR 52
#define ZBUF (64 * ZSTR)       // floats per partial buffer
#define LSTM_SMEM (ZS_OFF + 2 * ZBUF * 4)  // 181760

// ---------------- device globals ------------------------------------------
__device__ float g_proj[2][Bn * Tn * FH];
__device__ __nv_bfloat16 g_ahi[8][Bn * Tn * In];
__device__ __nv_bfloat16 g_alo[8][Bn * Tn * In];
__device__ __nv_bfloat16 g_wcat[8][Hn * 1024];
// h in MMA-fragment layout: [dir][buf][hi/lo][k16(50)][bg(4)][r(8)][m(4)][8 bf16]
__device__ __nv_bfloat16 g_hfrag[2][2][2][51200];
__device__ unsigned g_bar_count[2];
__device__ unsigned g_bar_sense[2];

__global__ void init_state() {
    int i = blockIdx.x * blockDim.x + threadIdx.x;
    if (i < Bn * Hn) {
        __nv_bfloat16 z = __float2bfloat16(0.f);
#pragma unroll
        for (int d = 0; d < 2; d++)
#pragma unroll
            for (int bu = 0; bu < 2; bu++)
#pragma unroll
                for (int p = 0; p < 2; p++)
                    g_hfrag[d][bu][p][i] = z;
    }
    if (i < 2) { g_bar_count[i] = 0u; g_bar_sense[i] = 0u; }
}

// ---------------- helpers ---------------------------------------------------
__device__ __forceinline__ uint32_t smem_u32(const void* p) {
    uint32_t a;
    asm("{ .reg .u64 t; cvta.to.shared.u64 t, %1; cvt.u32.u64 %0, t; }" : "=r"(a) : "l"(p));
    return a;
}
__device__ __forceinline__ void ldmatrix_x4(uint32_t& a0, uint32_t& a1, uint32_t& a2, uint32_t& a3,
                                            uint32_t addr) {
    asm volatile("ldmatrix.sync.aligned.m8n8.x4.shared.b16 {%0,%1,%2,%3}, [%4];"
                 : "=r"(a0), "=r"(a1), "=r"(a2), "=r"(a3) : "r"(addr));
}
__device__ __forceinline__ void ldmatrix_x2(uint32_t& b0, uint32_t& b1, uint32_t addr) {
    asm volatile("ldmatrix.sync.aligned.m8n8.x2.shared.b16 {%0,%1}, [%2];"
                 : "=r"(b0), "=r"(b1) : "r"(addr));
}
__device__ __forceinline__ void mma_bf16(float& c0, float& c1, float& c2, float& c3,
                                         uint32_t a0, uint32_t a1, uint32_t a2, uint32_t a3,
                                         uint32_t b0, uint32_t b1) {
    asm volatile("mma.sync.aligned.m16n8k16.row.col.f32.bf16.bf16.f32 "
                 "{%0,%1,%2,%3}, {%4,%5,%6,%7}, {%8,%9}, {%0,%1,%2,%3};"
                 : "+f"(c0), "+f"(c1), "+f"(c2), "+f"(c3)
                 : "r"(a0), "r"(a1), "r"(a2), "r"(a3), "r"(b0), "r"(b1));
}
__device__ __forceinline__ uint4 ldcg_u4(const void* p) {
    uint4 v;
    asm volatile("ld.global.cg.v4.u32 {%0,%1,%2,%3}, [%4];"
                 : "=r"(v.x), "=r"(v.y), "=r"(v.z), "=r"(v.w) : "l"(p));
    return v;
}
__device__ __forceinline__ void cp_async16(uint32_t saddr, const void* gptr) {
    asm volatile("cp.async.cg.shared.global [%0], [%1], 16;" :: "r"(saddr), "l"(gptr));
}
#define CP_COMMIT() asm volatile("cp.async.commit_group;" ::: "memory")
#define CP_WAIT0()  asm volatile("cp.async.wait_group 0;" ::: "memory")

// scoped-atomic grid barrier primitives
__device__ __forceinline__ unsigned atom_add_release_gpu(unsigned* p, unsigned v) {
    unsigned old;
    asm volatile("atom.global.add.release.gpu.u32 %0, [%1], %2;"
                 : "=r"(old) : "l"(p), "r"(v) : "memory");
    return old;
}
__device__ __forceinline__ void st_release_gpu(unsigned* p, unsigned v) {
    asm volatile("st.global.release.gpu.u32 [%0], %1;" :: "l"(p), "r"(v) : "memory");
}
__device__ __forceinline__ unsigned ld_acquire_gpu(const unsigned* p) {
    unsigned v;
    asm volatile("ld.global.acquire.gpu.u32 %0, [%1];" : "=r"(v) : "l"(p) : "memory");
    return v;
}

// ---------------- conversion kernels (unchanged) -----------------------------
__global__ void convert_x(const float* __restrict__ x,
                          const float* __restrict__ mask_f,
                          const float* __restrict__ mask_b)
{
    int idx = blockIdx.x * blockDim.x + threadIdx.x;
    if (idx >= Bn * Tn * (In / 4)) return;
    int bt = idx >> 7;
    int i4 = idx & 127;
    int b  = bt >> 8;
    float4 xv = *(const float4*)(x + (size_t)bt * In + i4 * 4);
#pragma unroll
    for (int dir = 0; dir < 2; dir++) {
        const float* mask = dir ? mask_b : mask_f;
#pragma unroll
        for (int g = 0; g < 4; g++) {
            float4 mv = *(const float4*)(mask + (size_t)b * (4 * In) + (size_t)g * In + i4 * 4);
            float v[4] = {xv.x * mv.x, xv.y * mv.y, xv.z * mv.z, xv.w * mv.w};
            __nv_bfloat16 h[4], l[4];
#pragma unroll
            for (int q = 0; q < 4; q++) {
                h[q] = __float2bfloat16(v[q]);
                l[q] = __float2bfloat16(v[q] - __bfloat162float(h[q]));
            }
            int z = dir * 4 + g;
            size_t o = (size_t)bt * In + i4 * 4;
            __nv_bfloat162 h0; h0.x = h[0]; h0.y = h[1];
            __nv_bfloat162 h1; h1.x = h[2]; h1.y = h[3];
            __nv_bfloat162 l0; l0.x = l[0]; l0.y = l[1];
            __nv_bfloat162 l1; l1.x = l[2]; l1.y = l[3];
            *(__nv_bfloat162*)&g_ahi[z][o]     = h0;
            *(__nv_bfloat162*)&g_ahi[z][o + 2] = h1;
            *(__nv_bfloat162*)&g_alo[z][o]     = l0;
            *(__nv_bfloat162*)&g_alo[z][o + 2] = l1;
        }
    }
}

__global__ void convert_w(const float* __restrict__ W_f,
                          const float* __restrict__ W_b)
{
    int idx = blockIdx.x * blockDim.x + threadIdx.x;
    if (idx >= 8 * In * Hn) return;
    int n    = idx % Hn;
    int rest = idx / Hn;
    int ks   = rest & 511;
    int z    = rest >> 9;
    int dir  = z >> 2, g = z & 3;
    const float* W = dir ? W_b : W_f;
    float v = W[(size_t)ks * FH + (size_t)g * Hn + n];
    __nv_bfloat16 h = __float2bfloat16(v);
    __nv_bfloat16 l = __float2bfloat16(v - __bfloat162float(h));
    g_wcat[z][(size_t)n * 1024 + ks]       = h;
    g_wcat[z][(size_t)n * 1024 + 512 + ks] = l;
}

// ---------------- proj GEMM via mma.sync + cp.async (unchanged) --------------
#define PBK 32
#define PCHUNK 48
#define A_STRIDE 80
#define A_BYTES (128 * A_STRIDE)
#define B_BYTES (80  * A_STRIDE)

__global__ void __launch_bounds__(256)
proj_mma(const float* __restrict__ bias_f, const float* __restrict__ bias_b)
{
    __shared__ char sA[2][A_BYTES];
    __shared__ char sB[2][B_BYTES];

    const int z   = blockIdx.z;
    const int dir = z >> 2, g = z & 3;
    const int m0  = blockIdx.y * 128;
    const int n0  = blockIdx.x * 80;
    const __nv_bfloat16* __restrict__ ahi = g_ahi[z];
    const __nv_bfloat16* __restrict__ alo = g_alo[z];
    const __nv_bfloat16* __restrict__ wc  = g_wcat[z];
    const float* __restrict__ bias = dir ? bias_b : bias_f;

    const int tid  = threadIdx.x;
    const int wid  = tid >> 5;
    const int lane = tid & 31;
    const int wm   = wid & 3;
    const int wn   = wid >> 2;

    const uint32_t sAu = smem_u32(&sA[0][0]);
    const uint32_t sBu = smem_u32(&sB[0][0]);

    const int ar0 = (tid) >> 2,        ac0 = (tid) & 3;
    const int ar1 = (tid + 256) >> 2,  ac1 = (tid + 256) & 3;
    const int br0 = (tid) >> 2,        bc0 = (tid) & 3;
    const int br1 = (tid + 256) >> 2,  bc1 = (tid + 256) & 3;
    const int bvalid1 = (tid + 256 < 320);

    uint32_t aAddr[2], bAddr[5];
#pragma unroll
    for (int mt = 0; mt < 2; mt++) {
        int row = wm * 32 + mt * 16 + (lane & 15);
        aAddr[mt] = sAu + row * A_STRIDE + ((lane >> 4) << 3) * 2;
    }
#pragma unroll
    for (int nt = 0; nt < 5; nt++) {
        int row = wn * 40 + nt * 8 + (lane & 7);
        bAddr[nt] = sBu + row * A_STRIDE + (((lane >> 3) & 1) << 3) * 2;
    }

    float acc[2][5][4];
#pragma unroll
    for (int mt = 0; mt < 2; mt++)
#pragma unroll
        for (int nt = 0; nt < 5; nt++)
#pragma unroll
            for (int q = 0; q < 4; q++) acc[mt][nt][q] = 0.f;

    cp_async16(sAu + ar0 * A_STRIDE + ac0 * 16, ahi + (size_t)(m0 + ar0) * In + ac0 * 8);
    cp_async16(sAu + ar1 * A_STRIDE + ac1 * 16, ahi + (size_t)(m0 + ar1) * In + ac1 * 8);
    cp_async16(sBu + br0 * A_STRIDE + bc0 * 16, wc + (size_t)(n0 + br0) * 1024 + bc0 * 8);
    if (bvalid1)
        cp_async16(sBu + br1 * A_STRIDE + bc1 * 16, wc + (size_t)(n0 + br1) * 1024 + bc1 * 8);
    CP_COMMIT();
    CP_WAIT0();
    __syncthreads();

    for (int c = 0; c < PCHUNK; c++) {
        const int buf = c & 1;
        if (c + 1 < PCHUNK) {
            const int cn = c + 1;
            int ka, kb;
            const __nv_bfloat16* asrc;
            if (cn < 16)      { asrc = ahi; ka = cn * PBK;        kb = cn * PBK; }
            else if (cn < 32) { asrc = ahi; ka = (cn - 16) * PBK; kb = cn * PBK; }
            else              { asrc = alo; ka = (cn - 32) * PBK; kb = (cn - 32) * PBK; }
            const uint32_t dA = sAu + (buf ^ 1) * A_BYTES;
            const uint32_t dB = sBu + (buf ^ 1) * B_BYTES;
            cp_async16(dA + ar0 * A_STRIDE + ac0 * 16, asrc + (size_t)(m0 + ar0) * In + ka + ac0 * 8);
            cp_async16(dA + ar1 * A_STRIDE + ac1 * 16, asrc + (size_t)(m0 + ar1) * In + ka + ac1 * 8);
            cp_async16(dB + br0 * A_STRIDE + bc0 * 16, wc + (size_t)(n0 + br0) * 1024 + kb + bc0 * 8);
            if (bvalid1)
                cp_async16(dB + br1 * A_STRIDE + bc1 * 16, wc + (size_t)(n0 + br1) * 1024 + kb + bc1 * 8);
            CP_COMMIT();
        }

        const uint32_t aOff = buf * A_BYTES;
        const uint32_t bOff = buf * B_BYTES;
#pragma unroll
        for (int kk = 0; kk < 2; kk++) {
            uint32_t a[2][4], b[5][2];
#pragma unroll
            for (int mt = 0; mt < 2; mt++)
                ldmatrix_x4(a[mt][0], a[mt][1], a[mt][2], a[mt][3],
                            aAddr[mt] + aOff + kk * 32);
#pragma unroll
            for (int nt = 0; nt < 5; nt++)
                ldmatrix_x2(b[nt][0], b[nt][1], bAddr[nt] + bOff + kk * 32);
#pragma unroll
            for (int mt = 0; mt < 2; mt++)
#pragma unroll
                for (int nt = 0; nt < 5; nt++)
                    mma_bf16(acc[mt][nt][0], acc[mt][nt][1], acc[mt][nt][2], acc[mt][nt][3],
                             a[mt][0], a[mt][1], a[mt][2], a[mt][3],
                             b[nt][0], b[nt][1]);
        }

        if (c + 1 < PCHUNK) {
            CP_WAIT0();
            __syncthreads();
        }
    }

    float* __restrict__ outp = g_proj[dir];
#pragma unroll
    for (int mt = 0; mt < 2; mt++) {
        int mrow0 = m0 + wm * 32 + mt * 16 + (lane >> 2);
#pragma unroll
        for (int nt = 0; nt < 5; nt++) {
            int n = n0 + wn * 40 + nt * 8 + ((lane & 3) << 1);
            float2 bv = *(const float2*)(bias + g * Hn + n);
            float2 v0 = make_float2(acc[mt][nt][0] + bv.x, acc[mt][nt][1] + bv.y);
            float2 v1 = make_float2(acc[mt][nt][2] + bv.x, acc[mt][nt][3] + bv.y);
            *(float2*)(outp + (size_t)mrow0 * FH + (size_t)g * Hn + n) = v0;
            *(float2*)(outp + (size_t)(mrow0 + 8) * FH + (size_t)g * Hn + n) = v1;
        }
    }
}

// ---------------- fast gate nonlinearities ----------------------------------
__device__ __forceinline__ float fast_sigmoid(float x) {
    return __fdividef(1.f, 1.f + __expf(-x));
}
__device__ __forceinline__ float fast_tanh(float x) {
    float e = __expf(2.f * x);
    return 1.f - __fdividef(2.f, e + 1.f);
}

// ---------------- persistent recurrence: fragment-direct HMMA, K-split,
//                  release/acquire grid barrier (no threadfence/IVALL) --------
__global__ void __launch_bounds__(256, 1)
lstm_persistent(const float* __restrict__ U_f,
                const float* __restrict__ U_b,
                float* __restrict__ out)
{
    extern __shared__ char dsm[];
    char*  sU = dsm;
    float* zs = (float*)(dsm + ZS_OFF);   // [2][64][ZSTR]

    const int bid = blockIdx.x;
    const int dir = bid / NCTA_DIR;
    const int j   = bid - dir * NCTA_DIR;
    const int h0  = j * NH;
    const int tid = threadIdx.x;
    const int lane = tid & 31;
    const int wid = tid >> 5;
    const int wm  = wid & 3;            // 4 M tiles of 16 batches
    const int wn  = wid >> 2;           // K-split half (0: k 0-24, 1: k 25-49)
    const float* __restrict__ U = dir ? U_b : U_f;

    for (int idx = tid; idx < 96 * Hn; idx += 256) {
        int k  = idx / 96;
        int w2 = idx - k * 96;
        int w  = (w2 < 48) ? w2 : w2 - 48;
        int g  = w / NH;
        int c  = w - g * NH;
        int hh = h0 + c;
        float v = (hh < Hn) ? U[(size_t)k * FH + (size_t)g * Hn + hh] : 0.f;
        __nv_bfloat16 hi = __float2bfloat16(v);
        __nv_bfloat16 res = (w2 < 48) ? hi : __float2bfloat16(v - __bfloat162float(hi));
        *(__nv_bfloat16*)(sU + (size_t)w2 * USTR_B + k * 2) = res;
    }

    int gb[3], gc2[3], gvalid[3], hoff[3];
#pragma unroll
    for (int it = 0; it < 3; it++) {
        int idx = it * 256 + tid;
        gb[it]  = idx / NH;
        gc2[it] = idx - gb[it] * NH;
        int hh  = h0 + gc2[it];
        gvalid[it] = (hh < Hn) ? 1 : 0;
        int b = gb[it];
        int k16 = hh >> 4, kin = hh & 15;
        int bg = b >> 4, rr = b & 15;
        hoff[it] = k16 * 1024 + bg * 256 + (rr & 7) * 32 + ((kin & 7) >> 1) * 8
                 + (kin >> 3) * 4 + ((rr >> 3) & 1) * 2 + (kin & 1);
        if (!gvalid[it]) hoff[it] = 0;
    }

    const int aoff = wm * 256 + (lane >> 2) * 32 + (lane & 3) * 8;
    const int kbase16 = wn * 25;
    const int abase = kbase16 * 1024 + aoff;

    const uint32_t sUu = smem_u32(sU);
    uint32_t bAddr[6];
    {
        int l8 = lane & 7;
        int kh = (lane >> 3) & 1;
        int pt = lane >> 4;
#pragma unroll
        for (int nt = 0; nt < 6; nt++)
            bAddr[nt] = sUu + (nt * 8 + l8 + pt * 48) * USTR_B + (kh << 4) + kbase16 * 32;
    }

    __syncthreads();

    unsigned sense = 0;
    const float* __restrict__ proj = g_proj[dir];

    float c_reg[3] = {0.f, 0.f, 0.f};
    float pp[3][4];
    {
        const int te = dir ? (Tn - 1) : 0;
#pragma unroll
        for (int it = 0; it < 3; it++) {
            pp[it][0] = pp[it][1] = pp[it][2] = pp[it][3] = 0.f;
            if (gvalid[it]) {
                size_t pbase = ((size_t)gb[it] * Tn + te) * FH + (h0 + gc2[it]);
                pp[it][0] = proj[pbase];
                pp[it][1] = proj[pbase + Hn];
                pp[it][2] = proj[pbase + 2 * Hn];
                pp[it][3] = proj[pbase + 3 * Hn];
            }
        }
    }

    for (int t = 0; t < Tn; t++) {
        const int cur = t & 1;
        const int nxt = cur ^ 1;
        const __nv_bfloat16* __restrict__ fhi = g_hfrag[dir][cur][0];
        const __nv_bfloat16* __restrict__ flo = g_hfrag[dir][cur][1];

        float acc[6][4];
#pragma unroll
        for (int nt = 0; nt < 6; nt++)
#pragma unroll
            for (int q = 0; q < 4; q++) acc[nt][q] = 0.f;

        // 25 k16 blocks = 5 chunks of 5, register double-buffered, L2-direct
        uint4 Ah[2][5], Al[2][5];
#pragma unroll
        for (int j2 = 0; j2 < 5; j2++) {
            Ah[0][j2] = ldcg_u4(fhi + abase + j2 * 1024);
            Al[0][j2] = ldcg_u4(flo + abase + j2 * 1024);
        }
#pragma unroll
        for (int c = 0; c < 5; c++) {
            const int cb = c & 1, nb = cb ^ 1;
            if (c < 4) {
#pragma unroll
                for (int j2 = 0; j2 < 5; j2++) {
                    int kb = (c + 1) * 5 + j2;
                    Ah[nb][j2] = ldcg_u4(fhi + abase + kb * 1024);
                    Al[nb][j2] = ldcg_u4(flo + abase + kb * 1024);
                }
            }
#pragma unroll
            for (int j2 = 0; j2 < 5; j2++) {
                const int klocal = c * 5 + j2;
                uint32_t b4[6][4];
#pragma unroll
                for (int nt = 0; nt < 6; nt++)
                    ldmatrix_x4(b4[nt][0], b4[nt][1], b4[nt][2], b4[nt][3],
                                bAddr[nt] + klocal * 32);
#pragma unroll
                for (int nt = 0; nt < 6; nt++) {
                    mma_bf16(acc[nt][0], acc[nt][1], acc[nt][2], acc[nt][3],
                             Ah[cb][j2].x, Ah[cb][j2].y, Ah[cb][j2].z, Ah[cb][j2].w,
                             b4[nt][0], b4[nt][1]);
                    mma_bf16(acc[nt][0], acc[nt][1], acc[nt][2], acc[nt][3],
                             Ah[cb][j2].x, Ah[cb][j2].y, Ah[cb][j2].z, Ah[cb][j2].w,
                             b4[nt][2], b4[nt][3]);
                    mma_bf16(acc[nt][0], acc[nt][1], acc[nt][2], acc[nt][3],
                             Al[cb][j2].x, Al[cb][j2].y, Al[cb][j2].z, Al[cb][j2].w,
                             b4[nt][0], b4[nt][1]);
                }
            }
        }

        // write z partials: wn half -> its own buffer
        {
            float* zw = zs + wn * ZBUF;
            int row0 = wm * 16 + (lane >> 2);
            int colb = (lane & 3) << 1;
#pragma unroll
            for (int nt = 0; nt < 6; nt++) {
                int col = colb + nt * 8;
                *(float2*)&zw[row0 * ZSTR + col]       = make_float2(acc[nt][0], acc[nt][1]);
                *(float2*)&zw[(row0 + 8) * ZSTR + col] = make_float2(acc[nt][2], acc[nt][3]);
            }
        }
        __syncthreads();

        __nv_bfloat16* __restrict__ whi = g_hfrag[dir][nxt][0];
        __nv_bfloat16* __restrict__ wlo = g_hfrag[dir][nxt][1];
#pragma unroll
        for (int it = 0; it < 3; it++) {
            if (gvalid[it]) {
                int b  = gb[it];
                int c  = gc2[it];
                int hh = h0 + c;
                float zi = zs[b * ZSTR + 0 * NH + c] + zs[ZBUF + b * ZSTR + 0 * NH + c] + pp[it][0];
                float zf = zs[b * ZSTR + 1 * NH + c] + zs[ZBUF + b * ZSTR + 1 * NH + c] + pp[it][1];
                float zg = zs[b * ZSTR + 2 * NH + c] + zs[ZBUF + b * ZSTR + 2 * NH + c] + pp[it][2];
                float zo = zs[b * ZSTR + 3 * NH + c] + zs[ZBUF + b * ZSTR + 3 * NH + c] + pp[it][3];

                float ig = fast_sigmoid(zi);
                float fg = fast_sigmoid(zf);
                float gg = fast_tanh(zg);
                float og = fast_sigmoid(zo);

                float cv = fg * c_reg[it] + ig * gg;
                float hv = og * fast_tanh(cv);
                c_reg[it] = cv;

                __nv_bfloat16 hvh = __float2bfloat16(hv);
                __nv_bfloat16 hvl = __float2bfloat16(hv - __bfloat162float(hvh));
                whi[hoff[it]] = hvh;
                wlo[hoff[it]] = hvl;

                out[((size_t)b * Tn + t) * (2 * Hn) + (size_t)dir * Hn + hh] = hv;
                if (t == Tn - 1) {
                    size_t hcat0 = (size_t)Bn * Tn * (2 * Hn);
                    size_t ccat0 = hcat0 + (size_t)Bn * (2 * Hn);
                    out[hcat0 + (size_t)b * (2 * Hn) + (size_t)dir * Hn + hh] = hv;
                    out[ccat0 + (size_t)b * (2 * Hn) + (size_t)dir * Hn + hh] = cv;
                }
            }
        }

        // --- release/acquire grid barrier (per direction) ---------------------
        __syncthreads();                     // all h stores program-ordered before arrival
        const unsigned ns = sense ^ 1u;
        if (tid == 0) {
            unsigned arrived = atom_add_release_gpu(&g_bar_count[dir], 1u);
            if (arrived == NCTA_DIR - 1) {
                g_bar_count[dir] = 0u;       // ordered before release store below
                st_release_gpu(&g_bar_sense[dir], ns);
            }
        }
        // prefetch next-step proj while waiting (immutable data, barrier-independent)
        if (t + 1 < Tn) {
            const int te = dir ? (Tn - 2 - t) : (t + 1);
#pragma unroll
            for (int it = 0; it < 3; it++) {
                if (gvalid[it]) {
                    size_t pbase = ((size_t)gb[it] * Tn + te) * FH + (h0 + gc2[it]);
                    pp[it][0] = proj[pbase];
                    pp[it][1] = proj[pbase + Hn];
                    pp[it][2] = proj[pbase + 2 * Hn];
                    pp[it][3] = proj[pbase + 3 * Hn];
                }
            }
        }
        // every warp polls independently; acquire orders subsequent h loads
        if (lane == 0) {
            while (ld_acquire_gpu(&g_bar_sense[dir]) != ns) __nanosleep(20);
        }
        __syncwarp();
        sense = ns;
    }
}

// ---------------- launch ------------------------------------------------------
extern "C" void kernel_launch(void* const* d_in, const int* in_sizes, int n_in,
                              void* d_out, int out_size)
{
    const float* x      = (const float*)d_in[0];
    const float* mask_f = (const float*)d_in[1];
    const float* mask_b = (const float*)d_in[2];
    const float* W_f    = (const float*)d_in[3];
    const float* U_f    = (const float*)d_in[4];
    const float* b_f    = (const float*)d_in[5];
    const float* W_b    = (const float*)d_in[6];
    const float* U_b    = (const float*)d_in[7];
    const float* b_b    = (const float*)d_in[8];
    float* out = (float*)d_out;

    static int configured = 0;
    if (!configured) {
        cudaFuncSetAttribute(lstm_persistent,
                             cudaFuncAttributeMaxDynamicSharedMemorySize, LSTM_SMEM);
        configured = 1;
    }

    init_state<<<(Bn * Hn + 255) / 256, 256>>>();
    convert_x<<<(Bn * Tn * (In / 4) + 255) / 256, 256>>>(x, mask_f, mask_b);
    convert_w<<<(8 * In * Hn + 255) / 256, 256>>>(W_f, W_b);
    proj_mma<<<dim3(10, 128, 8), 256>>>(b_f, b_b);
    lstm_persistent<<<2 * NCTA_DIR, 256, LSTM_SMEM>>>(U_f, U_b, out);
}